// round 11
// baseline (speedup 1.0000x reference)
#include <cuda_runtime.h>
#include <math.h>
#include <stdint.h>

#define B_ 2
#define S_ 1024
#define D_ 2048
#define H_ 16
#define HKV_ 8
#define HD_ 128
#define F_ 5632
#define E_ 8
#define R_ 16
#define T_ (B_*S_)
#define EPS_ 1e-5f
#define SCALE_ 2.0f
#define NQKV_ 4096

// ---------------- device scratch (static, allocation-free) ----------------
__device__ float g_xn[T_*D_];
__device__ float g_wqkv[NQKV_*D_];
__device__ float g_qkv[(size_t)T_*NQKV_];
__device__ float g_attn[T_*D_];
__device__ float g_sn[T_*D_];
__device__ float g_c1[T_*F_];
__device__ float g_c3[T_*F_];
__device__ float g_h1[2*T_*F_];
__device__ float g_h3[2*T_*F_];
__device__ float g_expout[2*T_*D_];
__device__ float g_u1[2*T_*R_];
__device__ float g_u3[2*T_*R_];
__device__ float g_u2[2*T_*R_];
__device__ float g_logits[T_*E_];
__device__ float g_zmax[B_*E_];
__device__ float g_zsum[B_*E_];
__device__ int   g_cnt[E_];
__device__ int   g_off[E_];
__device__ int   g_tok[E_*T_];
__device__ int   g_sel[2*T_];
__device__ int   g_pos[2*T_];
__device__ float g_wgt[2*T_];

// ---------------- helpers ----------------
__device__ __forceinline__ float tf32r(float x) {
    uint32_t y;
    asm("cvt.rna.tf32.f32 %0, %1;" : "=r"(y) : "f"(x));
    return __uint_as_float(y);
}
__device__ __forceinline__ void mma_tf32(float& d0, float& d1, float& d2, float& d3,
                                         float a0, float a1, float a2, float a3,
                                         float b0, float b1) {
    asm volatile(
        "mma.sync.aligned.m16n8k8.row.col.f32.tf32.tf32.f32 "
        "{%0,%1,%2,%3}, {%4,%5,%6,%7}, {%8,%9}, {%0,%1,%2,%3};"
        : "+f"(d0), "+f"(d1), "+f"(d2), "+f"(d3)
        : "r"(__float_as_uint(a0)), "r"(__float_as_uint(a1)),
          "r"(__float_as_uint(a2)), "r"(__float_as_uint(a3)),
          "r"(__float_as_uint(b0)), "r"(__float_as_uint(b1)));
}

// ---------------- tf32 mma.sync GEMM (v1 tiling): 128x128 CTA, 64x32 warp ----------------
// C[(base+m), n] = A[(base+m)] @ Bw[n]^T (+Res[m,n]); rope on cols < ropeN.
// N multiple of 128, K multiple of 16.
__global__ __launch_bounds__(256, 2)
void gemm_mma(const float* __restrict__ A, const float* __restrict__ Bw,
              float* __restrict__ C, int M, int N, int K,
              const float* __restrict__ Res,
              const int* __restrict__ Mcnt, const int* __restrict__ Moff,
              const float* __restrict__ ropec, const float* __restrict__ ropes,
              int ropeN) {
    __shared__ float As[2][128][20];
    __shared__ float Bs[2][128][20];

    int z = blockIdx.z;
    if (Mcnt) M = Mcnt[z];
    int bm = blockIdx.y * 128;
    if (bm >= M) return;
    int bn = blockIdx.x * 128;
    int base = Moff ? Moff[z] : 0;

    int tid = threadIdx.x, wid = tid >> 5, lid = tid & 31;
    int wm = wid >> 2, wn = wid & 3;           // 2 x 4 warp grid
    int m0 = wm * 64, n0 = wn * 32;
    int lr = lid >> 2, lc = lid & 3;

    float acc[4][4][4];
#pragma unroll
    for (int i = 0; i < 4; i++)
#pragma unroll
        for (int j = 0; j < 4; j++)
#pragma unroll
            for (int q = 0; q < 4; q++) acc[i][j][q] = 0.f;

    int grA = tid >> 2;                        // 0..63 (+64 on second it)
    int gc  = (tid & 3) * 4;

    float4 pa[2], pb[2];
    const float4 z4 = make_float4(0.f, 0.f, 0.f, 0.f);

#define PREF(k0) do {                                                           \
        _Pragma("unroll")                                                       \
        for (int it = 0; it < 2; it++) {                                        \
            int gr = it * 64 + grA;                                             \
            pa[it] = z4;                                                        \
            if (bm + gr < M)                                                    \
                pa[it] = *reinterpret_cast<const float4*>(                      \
                    A + (size_t)(base + bm + gr) * K + (k0) + gc);              \
            pb[it] = *reinterpret_cast<const float4*>(                          \
                    Bw + (size_t)(bn + gr) * K + (k0) + gc);                    \
        }                                                                       \
    } while (0)

#define STOREM(buf) do {                                                        \
        _Pragma("unroll")                                                       \
        for (int it = 0; it < 2; it++) {                                        \
            int gr = it * 64 + grA;                                             \
            As[buf][gr][gc + 0] = tf32r(pa[it].x);                              \
            As[buf][gr][gc + 1] = tf32r(pa[it].y);                              \
            As[buf][gr][gc + 2] = tf32r(pa[it].z);                              \
            As[buf][gr][gc + 3] = tf32r(pa[it].w);                              \
            Bs[buf][gr][gc + 0] = tf32r(pb[it].x);                              \
            Bs[buf][gr][gc + 1] = tf32r(pb[it].y);                              \
            Bs[buf][gr][gc + 2] = tf32r(pb[it].z);                              \
            Bs[buf][gr][gc + 3] = tf32r(pb[it].w);                              \
        }                                                                       \
    } while (0)

#define COMPUTE(buf) do {                                                       \
        _Pragma("unroll")                                                       \
        for (int ks = 0; ks < 2; ks++) {                                        \
            int kk = ks * 8;                                                    \
            float a[4][4], b[4][2];                                             \
            _Pragma("unroll")                                                   \
            for (int mt = 0; mt < 4; mt++) {                                    \
                a[mt][0] = As[buf][m0 + mt*16 + lr][kk + lc];                   \
                a[mt][1] = As[buf][m0 + mt*16 + lr + 8][kk + lc];               \
                a[mt][2] = As[buf][m0 + mt*16 + lr][kk + lc + 4];               \
                a[mt][3] = As[buf][m0 + mt*16 + lr + 8][kk + lc + 4];           \
            }                                                                   \
            _Pragma("unroll")                                                   \
            for (int nt = 0; nt < 4; nt++) {                                    \
                b[nt][0] = Bs[buf][n0 + nt*8 + lr][kk + lc];                    \
                b[nt][1] = Bs[buf][n0 + nt*8 + lr][kk + lc + 4];                \
            }                                                                   \
            _Pragma("unroll")                                                   \
            for (int mt = 0; mt < 4; mt++)                                      \
                _Pragma("unroll")                                               \
                for (int nt = 0; nt < 4; nt++)                                  \
                    mma_tf32(acc[mt][nt][0], acc[mt][nt][1],                    \
                             acc[mt][nt][2], acc[mt][nt][3],                    \
                             a[mt][0], a[mt][1], a[mt][2], a[mt][3],            \
                             b[nt][0], b[nt][1]);                               \
        }                                                                       \
    } while (0)

    PREF(0);
    STOREM(0);
    __syncthreads();

    int nk = K / 16;
    for (int t = 0; t < nk; t++) {
        if (t + 1 < nk) PREF((t + 1) * 16);
        COMPUTE(t & 1);
        if (t + 1 < nk) STOREM((t + 1) & 1);
        __syncthreads();
    }
#undef PREF
#undef STOREM
#undef COMPUTE

    // epilogue: per (mt, nt): rows (row, row+8), cols (col, col+1)
#pragma unroll
    for (int mt = 0; mt < 4; mt++) {
#pragma unroll
        for (int nt = 0; nt < 4; nt++) {
            int row = bm + m0 + mt * 16 + lr;
            int col = bn + n0 + nt * 8 + lc * 2;
#pragma unroll
            for (int hh = 0; hh < 2; hh++) {
                int r = row + hh * 8;
                if (r >= M) continue;
                float2 v = make_float2(acc[mt][nt][hh * 2], acc[mt][nt][hh * 2 + 1]);
                if (Res) {
                    const float2 rv = *reinterpret_cast<const float2*>(
                        Res + (size_t)(base + r) * N + col);
                    v.x += rv.x; v.y += rv.y;
                }
                if (ropec && col < ropeN) {
                    int p = (col & 127) >> 1;
                    int sp = (base + r) & (S_ - 1);
                    float cc = ropec[sp * 64 + p];
                    float ss = ropes[sp * 64 + p];
                    float o1 = v.x * cc - v.y * ss;
                    float o2 = v.x * ss + v.y * cc;
                    v.x = o1; v.y = o2;
                }
                *reinterpret_cast<float2*>(C + (size_t)(base + r) * N + col) = v;
            }
        }
    }
}

// ---------------- small kernels ----------------
__global__ void reset_kernel(int* cnt) {
    if (threadIdx.x < E_) cnt[threadIdx.x] = 0;
}

// concat wq (2048 rows) | wk (1024) | wv (1024), each row K=2048 floats
__global__ void concat_w_kernel(const float* __restrict__ wq, const float* __restrict__ wk,
                                const float* __restrict__ wv, float* __restrict__ wqkv) {
    size_t i = ((size_t)blockIdx.x * blockDim.x + threadIdx.x) * 4;
    size_t tot = (size_t)NQKV_ * D_;
    if (i >= tot) return;
    size_t row = i / D_;
    const float* src;
    size_t srow;
    if (row < 2048)      { src = wq; srow = row; }
    else if (row < 3072) { src = wk; srow = row - 2048; }
    else                 { src = wv; srow = row - 3072; }
    float4 v = *reinterpret_cast<const float4*>(src + srow * D_ + (i % D_));
    *reinterpret_cast<float4*>(wqkv + i) = v;
}

__global__ void rmsnorm_kernel(const float* __restrict__ x, const float* __restrict__ w,
                               float* __restrict__ out) {
    int row = blockIdx.x;
    const float* xr = x + (size_t)row * D_;
    float ss = 0.f;
    for (int i = threadIdx.x; i < D_; i += 256) { float v = xr[i]; ss += v * v; }
    __shared__ float red[256];
    red[threadIdx.x] = ss; __syncthreads();
    for (int s = 128; s > 0; s >>= 1) {
        if (threadIdx.x < s) red[threadIdx.x] += red[threadIdx.x + s];
        __syncthreads();
    }
    float inv = rsqrtf(red[0] / (float)D_ + EPS_);
    float* orow = out + (size_t)row * D_;
    for (int i = threadIdx.x; i < D_; i += 256) orow[i] = xr[i] * inv * w[i];
}

// ---------------- small SGEMM: 64x64 tile, expert-batched (LoRA path) ----------------
__global__ void gemm_small(const float* __restrict__ A, const float* __restrict__ Bw,
                           float* __restrict__ C, int N, int K,
                           const int* __restrict__ tokIdx, int gatherA,
                           const float* __restrict__ Res,
                           float alpha, int accumulate,
                           const int* __restrict__ Mcnt, const int* __restrict__ Moff,
                           size_t strideB, const float* __restrict__ siluMul) {
    int z = blockIdx.z;
    int M = Mcnt[z];
    int bm = blockIdx.y * 64;
    if (bm >= M) return;
    int bn = blockIdx.x * 64;
    int base = Moff[z];
    const int* tok = tokIdx + z * T_;
    const float* Bz = Bw + (size_t)z * strideB;

    __shared__ float As[16][64];
    __shared__ float Bs[16][64];
    int tid = threadIdx.x;
    int tx = tid & 15, ty = tid >> 4;
    float acc[4][4];
#pragma unroll
    for (int i = 0; i < 4; i++)
#pragma unroll
        for (int j = 0; j < 4; j++) acc[i][j] = 0.f;

    for (int k0 = 0; k0 < K; k0 += 16) {
#pragma unroll
        for (int l = 0; l < 4; l++) {
            int ii = l * 256 + tid;
            int m = ii >> 4, kk = ii & 15;
            int row = bm + m;
            float a = 0.f;
            if (row < M) {
                int ar = gatherA ? tok[row] : base + row;
                a = A[(size_t)ar * K + k0 + kk];
            }
            As[kk][m] = a;
            float bv = 0.f;
            if (bn + m < N) bv = Bz[(size_t)(bn + m) * K + k0 + kk];
            Bs[kk][m] = bv;
        }
        __syncthreads();
#pragma unroll
        for (int kk = 0; kk < 16; kk++) {
            float4 av = *reinterpret_cast<const float4*>(&As[kk][ty * 4]);
            float4 bv = *reinterpret_cast<const float4*>(&Bs[kk][tx * 4]);
            float a0 = av.x, a1 = av.y, a2 = av.z, a3 = av.w;
            float b0 = bv.x, b1 = bv.y, b2 = bv.z, b3 = bv.w;
            acc[0][0] += a0*b0; acc[0][1] += a0*b1; acc[0][2] += a0*b2; acc[0][3] += a0*b3;
            acc[1][0] += a1*b0; acc[1][1] += a1*b1; acc[1][2] += a1*b2; acc[1][3] += a1*b3;
            acc[2][0] += a2*b0; acc[2][1] += a2*b1; acc[2][2] += a2*b2; acc[2][3] += a2*b3;
            acc[3][0] += a3*b0; acc[3][1] += a3*b1; acc[3][2] += a3*b2; acc[3][3] += a3*b3;
        }
        __syncthreads();
    }
#pragma unroll
    for (int i = 0; i < 4; i++) {
        int row = bm + ty * 4 + i;
        if (row >= M) continue;
        size_t crow = (size_t)(base + row) * N;
#pragma unroll
        for (int j = 0; j < 4; j++) {
            int col = bn + tx * 4 + j;
            if (col >= N) continue;
            float val = alpha * acc[i][j];
            if (Res) val += Res[(size_t)tok[row] * N + col];
            if (siluMul) {
                float s = val / (1.f + expf(-val));
                val = s * siluMul[crow + col];
            }
            if (accumulate) C[crow + col] += val;
            else            C[crow + col] = val;
        }
    }
}

// ---------------- flash attention, fp32, 64-query tiles; reads packed qkv ----------------
#define ATTN_SMEM (20928 * 4)
__global__ void attn_kernel(const float* __restrict__ qkv, const float* __restrict__ mask,
                            float* __restrict__ o) {
    extern __shared__ float smf[];
    float* Qt   = smf;
    float* KV   = smf + 8320;
    float* Sc   = smf + 16640;
    float* mrow = smf + 20800;
    float* lrow = smf + 20864;

    int qt = blockIdx.x, h = blockIdx.y, b = blockIdx.z;
    int hkv = h >> 1;
    int tid = threadIdx.x;
    int q0 = qt * 64;

    for (int i = tid; i < 64 * 128; i += 256) {
        int r = i >> 7, d = i & 127;
        Qt[d * 65 + r] = qkv[(size_t)(b * S_ + q0 + r) * NQKV_ + h * HD_ + d];
    }
    if (tid < 64) { mrow[tid] = -3e38f; lrow[tid] = 0.f; }
    float acc[32];
#pragma unroll
    for (int i = 0; i < 32; i++) acc[i] = 0.f;
    int tx = tid & 15, ty = tid >> 4;
    int rg = tid >> 2, cg = tid & 3;
    __syncthreads();

    const float sca = 0.08838834764831845f;
    for (int kt = 0; kt < S_; kt += 64) {
        for (int i = tid; i < 64 * 128; i += 256) {
            int r = i >> 7, d = i & 127;
            KV[d * 65 + r] = qkv[(size_t)(b * S_ + kt + r) * NQKV_ + 2048 + hkv * HD_ + d];
        }
        __syncthreads();
        float sc[4][4];
#pragma unroll
        for (int i = 0; i < 4; i++)
#pragma unroll
            for (int j = 0; j < 4; j++) sc[i][j] = 0.f;
        for (int d = 0; d < 128; d++) {
            float a0 = Qt[d * 65 + ty * 4 + 0];
            float a1 = Qt[d * 65 + ty * 4 + 1];
            float a2 = Qt[d * 65 + ty * 4 + 2];
            float a3 = Qt[d * 65 + ty * 4 + 3];
            float b0 = KV[d * 65 + tx * 4 + 0];
            float b1 = KV[d * 65 + tx * 4 + 1];
            float b2 = KV[d * 65 + tx * 4 + 2];
            float b3 = KV[d * 65 + tx * 4 + 3];
            sc[0][0] += a0*b0; sc[0][1] += a0*b1; sc[0][2] += a0*b2; sc[0][3] += a0*b3;
            sc[1][0] += a1*b0; sc[1][1] += a1*b1; sc[1][2] += a1*b2; sc[1][3] += a1*b3;
            sc[2][0] += a2*b0; sc[2][1] += a2*b1; sc[2][2] += a2*b2; sc[2][3] += a2*b3;
            sc[3][0] += a3*b0; sc[3][1] += a3*b1; sc[3][2] += a3*b2; sc[3][3] += a3*b3;
        }
#pragma unroll
        for (int i = 0; i < 4; i++)
#pragma unroll
            for (int j = 0; j < 4; j++) {
                int rr = ty * 4 + i, cc = tx * 4 + j;
                Sc[rr * 65 + cc] = sc[i][j] * sca + mask[(q0 + rr) * S_ + kt + cc];
            }
        __syncthreads();
        for (int i = tid; i < 64 * 128; i += 256) {
            int r = i >> 7, d = i & 127;
            KV[r * 128 + d] = qkv[(size_t)(b * S_ + kt + r) * NQKV_ + 3072 + hkv * HD_ + d];
        }
        float tm = -3e38f;
#pragma unroll
        for (int ii = 0; ii < 16; ii++) tm = fmaxf(tm, Sc[rg * 65 + cg + 4 * ii]);
        tm = fmaxf(tm, __shfl_xor_sync(0xffffffffu, tm, 1));
        tm = fmaxf(tm, __shfl_xor_sync(0xffffffffu, tm, 2));
        float mprev = mrow[rg];
        float mnew = fmaxf(mprev, tm);
        float fac = expf(mprev - mnew);
        float ls = 0.f;
#pragma unroll
        for (int ii = 0; ii < 16; ii++) {
            float p = expf(Sc[rg * 65 + cg + 4 * ii] - mnew);
            Sc[rg * 65 + cg + 4 * ii] = p;
            ls += p;
        }
        ls += __shfl_xor_sync(0xffffffffu, ls, 1);
        ls += __shfl_xor_sync(0xffffffffu, ls, 2);
        if (cg == 0) { mrow[rg] = mnew; lrow[rg] = lrow[rg] * fac + ls; }
#pragma unroll
        for (int ii = 0; ii < 32; ii++) acc[ii] *= fac;
        __syncthreads();
        for (int j = 0; j < 64; j++) {
            float p = Sc[rg * 65 + j];
#pragma unroll
            for (int ii = 0; ii < 32; ii++) acc[ii] += p * KV[j * 128 + cg + 4 * ii];
        }
        __syncthreads();
    }
    float invl = 1.f / lrow[rg];
#pragma unroll
    for (int ii = 0; ii < 32; ii++)
        o[(((size_t)b * S_ + q0 + rg) * H_ + h) * HD_ + cg + 4 * ii] = acc[ii] * invl;
}

// ---------------- router ----------------
__global__ void router_logits_kernel(const float* __restrict__ sn, const float* __restrict__ gw,
                                     float* __restrict__ logits) {
    int t = blockIdx.x;
    int wid = threadIdx.x >> 5, lid = threadIdx.x & 31;
    const float* x = sn + (size_t)t * D_;
    const float* g = gw + (size_t)wid * D_;
    float s = 0.f;
    for (int i = lid * 4; i < D_; i += 128) {
        float4 xv = *reinterpret_cast<const float4*>(x + i);
        float4 gv = *reinterpret_cast<const float4*>(g + i);
        s += xv.x * gv.x + xv.y * gv.y + xv.z * gv.z + xv.w * gv.w;
    }
#pragma unroll
    for (int o = 16; o > 0; o >>= 1) s += __shfl_xor_sync(0xffffffffu, s, o);
    if (lid == 0) logits[(size_t)t * E_ + wid] = s;
}

__global__ void col_softmax_stats(const float* __restrict__ logits, float* __restrict__ zmax,
                                  float* __restrict__ zsum) {
    int be = blockIdx.x;
    int b = be / E_, e = be % E_;
    __shared__ float red[256];
    float mx = -3e38f;
    for (int s = threadIdx.x; s < S_; s += 256)
        mx = fmaxf(mx, logits[((size_t)b * S_ + s) * E_ + e]);
    red[threadIdx.x] = mx; __syncthreads();
    for (int s = 128; s > 0; s >>= 1) {
        if (threadIdx.x < s) red[threadIdx.x] = fmaxf(red[threadIdx.x], red[threadIdx.x + s]);
        __syncthreads();
    }
    mx = red[0]; __syncthreads();
    float sum = 0.f;
    for (int s = threadIdx.x; s < S_; s += 256)
        sum += expf(logits[((size_t)b * S_ + s) * E_ + e] - mx);
    red[threadIdx.x] = sum; __syncthreads();
    for (int s = 128; s > 0; s >>= 1) {
        if (threadIdx.x < s) red[threadIdx.x] += red[threadIdx.x + s];
        __syncthreads();
    }
    if (threadIdx.x == 0) { zmax[be] = mx; zsum[be] = red[0]; }
}

__global__ void top2_kernel(const float* __restrict__ logits, const float* __restrict__ zmax,
                            const float* __restrict__ zsum, int* __restrict__ cnt,
                            int* __restrict__ tok, int* __restrict__ sel,
                            int* __restrict__ pos, float* __restrict__ wgt) {
    int t = blockIdx.x * blockDim.x + threadIdx.x;
    if (t >= T_) return;
    int b = t / S_;
    float rw[E_];
#pragma unroll
    for (int e = 0; e < E_; e++)
        rw[e] = expf(logits[(size_t)t * E_ + e] - zmax[b * E_ + e]) / zsum[b * E_ + e];
    int e0 = 0; float v0 = rw[0];
#pragma unroll
    for (int e = 1; e < E_; e++) if (rw[e] > v0) { v0 = rw[e]; e0 = e; }
    int e1 = -1; float v1 = -3e38f;
#pragma unroll
    for (int e = 0; e < E_; e++) if (e != e0 && rw[e] > v1) { v1 = rw[e]; e1 = e; }
    float inv = 1.f / (v0 + v1);
    int p0 = atomicAdd(&cnt[e0], 1);
    tok[e0 * T_ + p0] = t;
    int p1 = atomicAdd(&cnt[e1], 1);
    tok[e1 * T_ + p1] = t;
    sel[2*t] = e0; pos[2*t] = p0; wgt[2*t] = v0 * inv;
    sel[2*t+1] = e1; pos[2*t+1] = p1; wgt[2*t+1] = v1 * inv;
}

__global__ void offsets_kernel(const int* __restrict__ cnt, int* __restrict__ off) {
    if (threadIdx.x == 0) {
        int s = 0;
        for (int e = 0; e < E_; e++) { off[e] = s; s += cnt[e]; }
    }
}

__global__ void gather_kernel(const float* __restrict__ expout, const int* __restrict__ off,
                              const int* __restrict__ sel, const int* __restrict__ pos,
                              const float* __restrict__ wgt, float* __restrict__ out) {
    int t = blockIdx.x;
    int e0 = sel[2*t], e1 = sel[2*t+1];
    size_t r0 = (size_t)(off[e0] + pos[2*t]) * D_;
    size_t r1 = (size_t)(off[e1] + pos[2*t+1]) * D_;
    float w0 = wgt[2*t], w1 = wgt[2*t+1];
    for (int i = threadIdx.x; i < D_; i += 256)
        out[(size_t)t * D_ + i] += w0 * expout[r0 + i] + w1 * expout[r1 + i];
}

// ---------------- host launch ----------------
extern "C" void kernel_launch(void* const* d_in, const int* in_sizes, int n_in,
                              void* d_out, int out_size) {
    const float* data   = (const float*)d_in[0];
    const float* mask   = (const float*)d_in[1];
    const float* ropec  = (const float*)d_in[2];
    const float* ropes  = (const float*)d_in[3];
    const float* anw    = (const float*)d_in[4];
    const float* fnw    = (const float*)d_in[5];
    const float* wq     = (const float*)d_in[6];
    const float* wk     = (const float*)d_in[7];
    const float* wv     = (const float*)d_in[8];
    const float* wo     = (const float*)d_in[9];
    const float* gate_w = (const float*)d_in[10];
    const float* w1     = (const float*)d_in[11];
    const float* w2     = (const float*)d_in[12];
    const float* w3     = (const float*)d_in[13];
    const float* w1_a   = (const float*)d_in[14];
    const float* w1_b   = (const float*)d_in[15];
    const float* w3_a   = (const float*)d_in[16];
    const float* w3_b   = (const float*)d_in[17];
    const float* w2_a   = (const float*)d_in[18];
    const float* w2_b   = (const float*)d_in[19];
    float* out = (float*)d_out;

    float *xn, *wqkv, *qkv, *attn, *sn, *c1, *c3, *h1, *h3, *u1, *u3, *u2;
    float *logits, *zmax, *zsum, *wgt, *expout;
    int *cnt, *off, *tok, *sel, *pos;
    cudaGetSymbolAddress((void**)&xn, g_xn);
    cudaGetSymbolAddress((void**)&wqkv, g_wqkv);
    cudaGetSymbolAddress((void**)&qkv, g_qkv);
    cudaGetSymbolAddress((void**)&attn, g_attn);
    cudaGetSymbolAddress((void**)&sn, g_sn);
    cudaGetSymbolAddress((void**)&c1, g_c1);
    cudaGetSymbolAddress((void**)&c3, g_c3);
    cudaGetSymbolAddress((void**)&h1, g_h1);
    cudaGetSymbolAddress((void**)&h3, g_h3);
    cudaGetSymbolAddress((void**)&u1, g_u1);
    cudaGetSymbolAddress((void**)&u3, g_u3);
    cudaGetSymbolAddress((void**)&u2, g_u2);
    cudaGetSymbolAddress((void**)&expout, g_expout);
    cudaGetSymbolAddress((void**)&logits, g_logits);
    cudaGetSymbolAddress((void**)&zmax, g_zmax);
    cudaGetSymbolAddress((void**)&zsum, g_zsum);
    cudaGetSymbolAddress((void**)&cnt, g_cnt);
    cudaGetSymbolAddress((void**)&off, g_off);
    cudaGetSymbolAddress((void**)&tok, g_tok);
    cudaGetSymbolAddress((void**)&sel, g_sel);
    cudaGetSymbolAddress((void**)&pos, g_pos);
    cudaGetSymbolAddress((void**)&wgt, g_wgt);

    cudaFuncSetAttribute(attn_kernel, cudaFuncAttributeMaxDynamicSharedMemorySize, ATTN_SMEM);

    reset_kernel<<<1, 32>>>(cnt);
    concat_w_kernel<<<(NQKV_*D_/4 + 255)/256, 256>>>(wq, wk, wv, wqkv);
    rmsnorm_kernel<<<T_, 256>>>(data, anw, xn);

    // Fused QKV projection: one GEMM, N=4096, grid 512 CTAs; rope on cols < 3072
    gemm_mma<<<dim3(NQKV_/128, T_/128, 1), 256>>>(xn, wqkv, qkv, T_, NQKV_, D_,
        nullptr, nullptr, nullptr, ropec, ropes, 3072);

    attn_kernel<<<dim3(S_/64, H_, B_), 256, ATTN_SMEM>>>(qkv, mask, attn);

    // out = data + attn @ wo^T
    gemm_mma<<<dim3(D_/128, T_/128, 1), 256>>>(attn, wo, out, T_, D_, D_,
        data, nullptr, nullptr, nullptr, nullptr, 0);

    rmsnorm_kernel<<<T_, 256>>>(out, fnw, sn);

    router_logits_kernel<<<T_, 256>>>(sn, gate_w, logits);
    col_softmax_stats<<<B_*E_, 256>>>(logits, zmax, zsum);
    top2_kernel<<<T_/256, 256>>>(logits, zmax, zsum, cnt, tok, sel, pos, wgt);
    offsets_kernel<<<1, 32>>>(cnt, off);

    // dense c1/c3
    gemm_mma<<<dim3(F_/128, T_/128, 1), 256>>>(sn, w1, c1, T_, F_, D_,
        nullptr, nullptr, nullptr, nullptr, nullptr, 0);
    gemm_mma<<<dim3(F_/128, T_/128, 1), 256>>>(sn, w3, c3, T_, F_, D_,
        nullptr, nullptr, nullptr, nullptr, nullptr, 0);

    // ---- expert-batched LoRA path (z = expert) ----
    gemm_small<<<dim3(1, T_/64, E_), 256>>>(sn, w3_a, u3, R_, D_,
        tok, 1, nullptr, 1.f, 0, cnt, off, (size_t)R_*D_, nullptr);
    gemm_small<<<dim3(F_/64, T_/64, E_), 256>>>(u3, w3_b, h3, F_, R_,
        tok, 0, c3, SCALE_, 0, cnt, off, (size_t)F_*R_, nullptr);
    gemm_small<<<dim3(1, T_/64, E_), 256>>>(sn, w1_a, u1, R_, D_,
        tok, 1, nullptr, 1.f, 0, cnt, off, (size_t)R_*D_, nullptr);
    gemm_small<<<dim3(F_/64, T_/64, E_), 256>>>(u1, w1_b, h1, F_, R_,
        tok, 0, c1, SCALE_, 0, cnt, off, (size_t)F_*R_, h3);
    // u2 = sr @ w2_a^T
    gemm_small<<<dim3(1, T_/64, E_), 256>>>(h1, w2_a, u2, R_, F_,
        tok, 0, nullptr, 1.f, 0, cnt, off, (size_t)R_*F_, nullptr);
    // expout = sr @ w2^T
    gemm_mma<<<dim3(D_/128, T_/128, E_), 256>>>(h1, w2, expout, T_, D_, F_,
        nullptr, cnt, off, nullptr, nullptr, 0);
    // expout += SCALE * u2 @ w2_b^T
    gemm_small<<<dim3(D_/64, T_/64, E_), 256>>>(u2, w2_b, expout, D_, R_,
        tok, 0, nullptr, SCALE_, 1, cnt, off, (size_t)D_*R_, nullptr);

    // out[t] += w0*expout[slot0] + w1*expout[slot1]
    gather_kernel<<<T_, 256>>>(expout, off, sel, pos, wgt, out);
}

// round 12
// speedup vs baseline: 1.0772x; 1.0772x over previous
#include <cuda_runtime.h>
#include <math.h>
#include <stdint.h>

#define B_ 2
#define S_ 1024
#define D_ 2048
#define H_ 16
#define HKV_ 8
#define HD_ 128
#define F_ 5632
#define E_ 8
#define R_ 16
#define T_ (B_*S_)
#define EPS_ 1e-5f
#define SCALE_ 2.0f
#define NQKV_ 4096

// ---------------- device scratch (static, allocation-free) ----------------
__device__ float g_xnr[T_*D_];
__device__ float g_sn[T_*D_];
__device__ float g_snr[T_*D_];
__device__ float g_wqkv[NQKV_*D_];
__device__ float g_qkv[(size_t)T_*NQKV_];
__device__ float g_attn[T_*D_];
__device__ float g_woc[D_*D_];
__device__ float g_w1c[F_*D_];
__device__ float g_w3c[F_*D_];
__device__ float g_w2c[(size_t)D_*F_];
__device__ float g_c1[T_*F_];
__device__ float g_c3[T_*F_];
__device__ float g_h1[2*T_*F_];
__device__ float g_h3[2*T_*F_];
__device__ float g_expout[2*T_*D_];
__device__ float g_u1[2*T_*R_];
__device__ float g_u3[2*T_*R_];
__device__ float g_u2[2*T_*R_];
__device__ float g_logits[T_*E_];
__device__ float g_zmax[B_*E_];
__device__ float g_zsum[B_*E_];
__device__ int   g_cnt[E_];
__device__ int   g_off[E_];
__device__ int   g_tok[E_*T_];
__device__ int   g_sel[2*T_];
__device__ int   g_pos[2*T_];
__device__ float g_wgt[2*T_];

// ---------------- helpers ----------------
__device__ __forceinline__ float tf32r(float x) {
    uint32_t y;
    asm("cvt.rna.tf32.f32 %0, %1;" : "=r"(y) : "f"(x));
    return __uint_as_float(y);
}
__device__ __forceinline__ uint32_t smem_addr(const void* p) {
    uint32_t a;
    asm("{ .reg .u64 t; cvta.to.shared.u64 t, %1; cvt.u32.u64 %0, t; }" : "=r"(a) : "l"(p));
    return a;
}
__device__ __forceinline__ void mma_tf32(float& d0, float& d1, float& d2, float& d3,
                                         float a0, float a1, float a2, float a3,
                                         float b0, float b1) {
    asm volatile(
        "mma.sync.aligned.m16n8k8.row.col.f32.tf32.tf32.f32 "
        "{%0,%1,%2,%3}, {%4,%5,%6,%7}, {%8,%9}, {%0,%1,%2,%3};"
        : "+f"(d0), "+f"(d1), "+f"(d2), "+f"(d3)
        : "r"(__float_as_uint(a0)), "r"(__float_as_uint(a1)),
          "r"(__float_as_uint(a2)), "r"(__float_as_uint(a3)),
          "r"(__float_as_uint(b0)), "r"(__float_as_uint(b1)));
}

// ---------------- tf32 mma.sync GEMM: 128x128 CTA, 64x32 warp, 4-stage cp.async ----------------
// Inputs MUST be pre-rounded to tf32 (RNA) by producers.
// C[(base+m), n] = A[(base+m)] @ Bw[n]^T (+Res[m,n]); rope on cols < ropeN.
// N multiple of 128, K multiple of 16.
#define GMS (4 * 5120 * 4)   // 4 stages x (A 128x20 + B 128x20) floats = 81920 B
__global__ __launch_bounds__(256, 2)
void gemm_mma(const float* __restrict__ A, const float* __restrict__ Bw,
              float* __restrict__ C, int M, int N, int K,
              const float* __restrict__ Res,
              const int* __restrict__ Mcnt, const int* __restrict__ Moff,
              const float* __restrict__ ropec, const float* __restrict__ ropes,
              int ropeN) {
    extern __shared__ float smdyn[];

    int z = blockIdx.z;
    if (Mcnt) M = Mcnt[z];
    int bm = blockIdx.y * 128;
    if (bm >= M) return;
    int bn = blockIdx.x * 128;
    int base = Moff ? Moff[z] : 0;

    int tid = threadIdx.x, wid = tid >> 5, lid = tid & 31;
    int wm = wid >> 2, wn = wid & 3;           // 2 x 4 warp grid
    int m0 = wm * 64, n0 = wn * 32;
    int lr = lid >> 2, lc = lid & 3;

    float acc[4][4][4];
#pragma unroll
    for (int i = 0; i < 4; i++)
#pragma unroll
        for (int j = 0; j < 4; j++)
#pragma unroll
            for (int q = 0; q < 4; q++) acc[i][j][q] = 0.f;

    int grA = tid >> 2;                        // 0..63 (+64 on second it)
    int gc  = (tid & 3) * 4;

    uint32_t sbase = smem_addr(smdyn);

#define LOADT(st, k0) do {                                                      \
        _Pragma("unroll")                                                       \
        for (int it = 0; it < 2; it++) {                                        \
            int gr = it * 64 + grA;                                             \
            int rowA = bm + gr;                                                 \
            int sz = (rowA < M) ? 16 : 0;                                       \
            int rA = (rowA < M) ? rowA : (M - 1);                               \
            const float* sa = A + (size_t)(base + rA) * K + (k0) + gc;          \
            uint32_t da = sbase + (uint32_t)(((st) * 5120 + gr * 20 + gc) * 4); \
            asm volatile("cp.async.cg.shared.global [%0], [%1], 16, %2;"        \
                         :: "r"(da), "l"(sa), "r"(sz));                         \
            const float* sb = Bw + (size_t)(bn + gr) * K + (k0) + gc;           \
            uint32_t db = da + 2560 * 4;                                        \
            asm volatile("cp.async.cg.shared.global [%0], [%1], 16;"            \
                         :: "r"(db), "l"(sb));                                  \
        }                                                                       \
    } while (0)

#define COMPUTE(st) do {                                                        \
        const float* Asb = smdyn + (st) * 5120;                                 \
        const float* Bsb = Asb + 2560;                                          \
        _Pragma("unroll")                                                       \
        for (int ks = 0; ks < 2; ks++) {                                        \
            int kk = ks * 8;                                                    \
            float a[4][4], b[4][2];                                             \
            _Pragma("unroll")                                                   \
            for (int mt = 0; mt < 4; mt++) {                                    \
                a[mt][0] = Asb[(m0 + mt*16 + lr) * 20 + kk + lc];               \
                a[mt][1] = Asb[(m0 + mt*16 + lr + 8) * 20 + kk + lc];           \
                a[mt][2] = Asb[(m0 + mt*16 + lr) * 20 + kk + lc + 4];           \
                a[mt][3] = Asb[(m0 + mt*16 + lr + 8) * 20 + kk + lc + 4];       \
            }                                                                   \
            _Pragma("unroll")                                                   \
            for (int nt = 0; nt < 4; nt++) {                                    \
                b[nt][0] = Bsb[(n0 + nt*8 + lr) * 20 + kk + lc];                \
                b[nt][1] = Bsb[(n0 + nt*8 + lr) * 20 + kk + lc + 4];            \
            }                                                                   \
            _Pragma("unroll")                                                   \
            for (int mt = 0; mt < 4; mt++)                                      \
                _Pragma("unroll")                                               \
                for (int nt = 0; nt < 4; nt++)                                  \
                    mma_tf32(acc[mt][nt][0], acc[mt][nt][1],                    \
                             acc[mt][nt][2], acc[mt][nt][3],                    \
                             a[mt][0], a[mt][1], a[mt][2], a[mt][3],            \
                             b[nt][0], b[nt][1]);                               \
        }                                                                       \
    } while (0)

    int nk = K / 16;
#pragma unroll
    for (int s = 0; s < 3; s++) {
        if (s < nk) LOADT(s, s * 16);
        asm volatile("cp.async.commit_group;");
    }
    for (int t = 0; t < nk; t++) {
        asm volatile("cp.async.wait_group 2;");
        __syncthreads();
        if (t + 3 < nk) LOADT((t + 3) & 3, (t + 3) * 16);
        asm volatile("cp.async.commit_group;");
        COMPUTE(t & 3);
    }
#undef LOADT
#undef COMPUTE

    // epilogue: per (mt, nt): rows (row, row+8), cols (col, col+1)
#pragma unroll
    for (int mt = 0; mt < 4; mt++) {
#pragma unroll
        for (int nt = 0; nt < 4; nt++) {
            int row = bm + m0 + mt * 16 + lr;
            int col = bn + n0 + nt * 8 + lc * 2;
#pragma unroll
            for (int hh = 0; hh < 2; hh++) {
                int r = row + hh * 8;
                if (r >= M) continue;
                float2 v = make_float2(acc[mt][nt][hh * 2], acc[mt][nt][hh * 2 + 1]);
                if (Res) {
                    const float2 rv = *reinterpret_cast<const float2*>(
                        Res + (size_t)(base + r) * N + col);
                    v.x += rv.x; v.y += rv.y;
                }
                if (ropec && col < ropeN) {
                    int p = (col & 127) >> 1;
                    int sp = (base + r) & (S_ - 1);
                    float cc = ropec[sp * 64 + p];
                    float ss = ropes[sp * 64 + p];
                    float o1 = v.x * cc - v.y * ss;
                    float o2 = v.x * ss + v.y * cc;
                    v.x = o1; v.y = o2;
                }
                *reinterpret_cast<float2*>(C + (size_t)(base + r) * N + col) = v;
            }
        }
    }
}

// ---------------- small kernels ----------------
__global__ void reset_kernel(int* cnt) {
    if (threadIdx.x < E_) cnt[threadIdx.x] = 0;
}

// concat wq|wk|wv with tf32 rounding
__global__ void concat_w_kernel(const float* __restrict__ wq, const float* __restrict__ wk,
                                const float* __restrict__ wv, float* __restrict__ wqkv) {
    size_t i = ((size_t)blockIdx.x * blockDim.x + threadIdx.x) * 4;
    size_t tot = (size_t)NQKV_ * D_;
    if (i >= tot) return;
    size_t row = i / D_;
    const float* src;
    size_t srow;
    if (row < 2048)      { src = wq; srow = row; }
    else if (row < 3072) { src = wk; srow = row - 2048; }
    else                 { src = wv; srow = row - 3072; }
    float4 v = *reinterpret_cast<const float4*>(src + srow * D_ + (i % D_));
    v.x = tf32r(v.x); v.y = tf32r(v.y); v.z = tf32r(v.z); v.w = tf32r(v.w);
    *reinterpret_cast<float4*>(wqkv + i) = v;
}

// tf32-round a weight matrix into scratch
__global__ void cvt_kernel(const float* __restrict__ src, float* __restrict__ dst, size_t n4) {
    size_t i = (size_t)blockIdx.x * blockDim.x + threadIdx.x;
    if (i >= n4) return;
    float4 v = reinterpret_cast<const float4*>(src)[i];
    v.x = tf32r(v.x); v.y = tf32r(v.y); v.z = tf32r(v.z); v.w = tf32r(v.w);
    reinterpret_cast<float4*>(dst)[i] = v;
}

// rmsnorm: out = exact, outR (if non-null) = tf32-rounded copy
__global__ void rmsnorm_kernel(const float* __restrict__ x, const float* __restrict__ w,
                               float* __restrict__ out, float* __restrict__ outR) {
    int row = blockIdx.x;
    const float* xr = x + (size_t)row * D_;
    float ss = 0.f;
    for (int i = threadIdx.x; i < D_; i += 256) { float v = xr[i]; ss += v * v; }
    __shared__ float red[256];
    red[threadIdx.x] = ss; __syncthreads();
    for (int s = 128; s > 0; s >>= 1) {
        if (threadIdx.x < s) red[threadIdx.x] += red[threadIdx.x + s];
        __syncthreads();
    }
    float inv = rsqrtf(red[0] / (float)D_ + EPS_);
    float* orow = out + (size_t)row * D_;
    float* rrow = outR ? outR + (size_t)row * D_ : nullptr;
    for (int i = threadIdx.x; i < D_; i += 256) {
        float v = xr[i] * inv * w[i];
        orow[i] = v;
        if (rrow) rrow[i] = tf32r(v);
    }
}

// ---------------- small SGEMM: 64x64 tile, expert-batched (LoRA path) ----------------
__global__ void gemm_small(const float* __restrict__ A, const float* __restrict__ Bw,
                           float* __restrict__ C, int N, int K,
                           const int* __restrict__ tokIdx, int gatherA,
                           const float* __restrict__ Res,
                           float alpha, int accumulate,
                           const int* __restrict__ Mcnt, const int* __restrict__ Moff,
                           size_t strideB, const float* __restrict__ siluMul) {
    int z = blockIdx.z;
    int M = Mcnt[z];
    int bm = blockIdx.y * 64;
    if (bm >= M) return;
    int bn = blockIdx.x * 64;
    int base = Moff[z];
    const int* tok = tokIdx + z * T_;
    const float* Bz = Bw + (size_t)z * strideB;

    __shared__ float As[16][64];
    __shared__ float Bs[16][64];
    int tid = threadIdx.x;
    int tx = tid & 15, ty = tid >> 4;
    float acc[4][4];
#pragma unroll
    for (int i = 0; i < 4; i++)
#pragma unroll
        for (int j = 0; j < 4; j++) acc[i][j] = 0.f;

    for (int k0 = 0; k0 < K; k0 += 16) {
#pragma unroll
        for (int l = 0; l < 4; l++) {
            int ii = l * 256 + tid;
            int m = ii >> 4, kk = ii & 15;
            int row = bm + m;
            float a = 0.f;
            if (row < M) {
                int ar = gatherA ? tok[row] : base + row;
                a = A[(size_t)ar * K + k0 + kk];
            }
            As[kk][m] = a;
            float bv = 0.f;
            if (bn + m < N) bv = Bz[(size_t)(bn + m) * K + k0 + kk];
            Bs[kk][m] = bv;
        }
        __syncthreads();
#pragma unroll
        for (int kk = 0; kk < 16; kk++) {
            float4 av = *reinterpret_cast<const float4*>(&As[kk][ty * 4]);
            float4 bv = *reinterpret_cast<const float4*>(&Bs[kk][tx * 4]);
            float a0 = av.x, a1 = av.y, a2 = av.z, a3 = av.w;
            float b0 = bv.x, b1 = bv.y, b2 = bv.z, b3 = bv.w;
            acc[0][0] += a0*b0; acc[0][1] += a0*b1; acc[0][2] += a0*b2; acc[0][3] += a0*b3;
            acc[1][0] += a1*b0; acc[1][1] += a1*b1; acc[1][2] += a1*b2; acc[1][3] += a1*b3;
            acc[2][0] += a2*b0; acc[2][1] += a2*b1; acc[2][2] += a2*b2; acc[2][3] += a2*b3;
            acc[3][0] += a3*b0; acc[3][1] += a3*b1; acc[3][2] += a3*b2; acc[3][3] += a3*b3;
        }
        __syncthreads();
    }
#pragma unroll
    for (int i = 0; i < 4; i++) {
        int row = bm + ty * 4 + i;
        if (row >= M) continue;
        size_t crow = (size_t)(base + row) * N;
#pragma unroll
        for (int j = 0; j < 4; j++) {
            int col = bn + tx * 4 + j;
            if (col >= N) continue;
            float val = alpha * acc[i][j];
            if (Res) val += Res[(size_t)tok[row] * N + col];
            if (siluMul) {
                float s = val / (1.f + expf(-val));
                val = tf32r(s * siluMul[crow + col]);   // sr feeds w2 gemm (tf32 A)
            }
            if (accumulate) C[crow + col] += val;
            else            C[crow + col] = val;
        }
    }
}

// ---------------- flash attention, fp32, 64-query tiles; reads packed qkv ----------------
#define ATTN_SMEM (20928 * 4)
__global__ void attn_kernel(const float* __restrict__ qkv, const float* __restrict__ mask,
                            float* __restrict__ o) {
    extern __shared__ float smf[];
    float* Qt   = smf;
    float* KV   = smf + 8320;
    float* Sc   = smf + 16640;
    float* mrow = smf + 20800;
    float* lrow = smf + 20864;

    int qt = blockIdx.x, h = blockIdx.y, b = blockIdx.z;
    int hkv = h >> 1;
    int tid = threadIdx.x;
    int q0 = qt * 64;

    for (int i = tid; i < 64 * 128; i += 256) {
        int r = i >> 7, d = i & 127;
        Qt[d * 65 + r] = qkv[(size_t)(b * S_ + q0 + r) * NQKV_ + h * HD_ + d];
    }
    if (tid < 64) { mrow[tid] = -3e38f; lrow[tid] = 0.f; }
    float acc[32];
#pragma unroll
    for (int i = 0; i < 32; i++) acc[i] = 0.f;
    int tx = tid & 15, ty = tid >> 4;
    int rg = tid >> 2, cg = tid & 3;
    __syncthreads();

    const float sca = 0.08838834764831845f;
    for (int kt = 0; kt < S_; kt += 64) {
        for (int i = tid; i < 64 * 128; i += 256) {
            int r = i >> 7, d = i & 127;
            KV[d * 65 + r] = qkv[(size_t)(b * S_ + kt + r) * NQKV_ + 2048 + hkv * HD_ + d];
        }
        __syncthreads();
        float sc[4][4];
#pragma unroll
        for (int i = 0; i < 4; i++)
#pragma unroll
            for (int j = 0; j < 4; j++) sc[i][j] = 0.f;
        for (int d = 0; d < 128; d++) {
            float a0 = Qt[d * 65 + ty * 4 + 0];
            float a1 = Qt[d * 65 + ty * 4 + 1];
            float a2 = Qt[d * 65 + ty * 4 + 2];
            float a3 = Qt[d * 65 + ty * 4 + 3];
            float b0 = KV[d * 65 + tx * 4 + 0];
            float b1 = KV[d * 65 + tx * 4 + 1];
            float b2 = KV[d * 65 + tx * 4 + 2];
            float b3 = KV[d * 65 + tx * 4 + 3];
            sc[0][0] += a0*b0; sc[0][1] += a0*b1; sc[0][2] += a0*b2; sc[0][3] += a0*b3;
            sc[1][0] += a1*b0; sc[1][1] += a1*b1; sc[1][2] += a1*b2; sc[1][3] += a1*b3;
            sc[2][0] += a2*b0; sc[2][1] += a2*b1; sc[2][2] += a2*b2; sc[2][3] += a2*b3;
            sc[3][0] += a3*b0; sc[3][1] += a3*b1; sc[3][2] += a3*b2; sc[3][3] += a3*b3;
        }
#pragma unroll
        for (int i = 0; i < 4; i++)
#pragma unroll
            for (int j = 0; j < 4; j++) {
                int rr = ty * 4 + i, cc = tx * 4 + j;
                Sc[rr * 65 + cc] = sc[i][j] * sca + mask[(q0 + rr) * S_ + kt + cc];
            }
        __syncthreads();
        for (int i = tid; i < 64 * 128; i += 256) {
            int r = i >> 7, d = i & 127;
            KV[r * 128 + d] = qkv[(size_t)(b * S_ + kt + r) * NQKV_ + 3072 + hkv * HD_ + d];
        }
        float tm = -3e38f;
#pragma unroll
        for (int ii = 0; ii < 16; ii++) tm = fmaxf(tm, Sc[rg * 65 + cg + 4 * ii]);
        tm = fmaxf(tm, __shfl_xor_sync(0xffffffffu, tm, 1));
        tm = fmaxf(tm, __shfl_xor_sync(0xffffffffu, tm, 2));
        float mprev = mrow[rg];
        float mnew = fmaxf(mprev, tm);
        float fac = expf(mprev - mnew);
        float ls = 0.f;
#pragma unroll
        for (int ii = 0; ii < 16; ii++) {
            float p = expf(Sc[rg * 65 + cg + 4 * ii] - mnew);
            Sc[rg * 65 + cg + 4 * ii] = p;
            ls += p;
        }
        ls += __shfl_xor_sync(0xffffffffu, ls, 1);
        ls += __shfl_xor_sync(0xffffffffu, ls, 2);
        if (cg == 0) { mrow[rg] = mnew; lrow[rg] = lrow[rg] * fac + ls; }
#pragma unroll
        for (int ii = 0; ii < 32; ii++) acc[ii] *= fac;
        __syncthreads();
        for (int j = 0; j < 64; j++) {
            float p = Sc[rg * 65 + j];
#pragma unroll
            for (int ii = 0; ii < 32; ii++) acc[ii] += p * KV[j * 128 + cg + 4 * ii];
        }
        __syncthreads();
    }
    float invl = 1.f / lrow[rg];
#pragma unroll
    for (int ii = 0; ii < 32; ii++)
        o[(((size_t)b * S_ + q0 + rg) * H_ + h) * HD_ + cg + 4 * ii] = tf32r(acc[ii] * invl);
}

// ---------------- router ----------------
__global__ void router_logits_kernel(const float* __restrict__ sn, const float* __restrict__ gw,
                                     float* __restrict__ logits) {
    int t = blockIdx.x;
    int wid = threadIdx.x >> 5, lid = threadIdx.x & 31;
    const float* x = sn + (size_t)t * D_;
    const float* g = gw + (size_t)wid * D_;
    float s = 0.f;
    for (int i = lid * 4; i < D_; i += 128) {
        float4 xv = *reinterpret_cast<const float4*>(x + i);
        float4 gv = *reinterpret_cast<const float4*>(g + i);
        s += xv.x * gv.x + xv.y * gv.y + xv.z * gv.z + xv.w * gv.w;
    }
#pragma unroll
    for (int o = 16; o > 0; o >>= 1) s += __shfl_xor_sync(0xffffffffu, s, o);
    if (lid == 0) logits[(size_t)t * E_ + wid] = s;
}

__global__ void col_softmax_stats(const float* __restrict__ logits, float* __restrict__ zmax,
                                  float* __restrict__ zsum) {
    int be = blockIdx.x;
    int b = be / E_, e = be % E_;
    __shared__ float red[256];
    float mx = -3e38f;
    for (int s = threadIdx.x; s < S_; s += 256)
        mx = fmaxf(mx, logits[((size_t)b * S_ + s) * E_ + e]);
    red[threadIdx.x] = mx; __syncthreads();
    for (int s = 128; s > 0; s >>= 1) {
        if (threadIdx.x < s) red[threadIdx.x] = fmaxf(red[threadIdx.x], red[threadIdx.x + s]);
        __syncthreads();
    }
    mx = red[0]; __syncthreads();
    float sum = 0.f;
    for (int s = threadIdx.x; s < S_; s += 256)
        sum += expf(logits[((size_t)b * S_ + s) * E_ + e] - mx);
    red[threadIdx.x] = sum; __syncthreads();
    for (int s = 128; s > 0; s >>= 1) {
        if (threadIdx.x < s) red[threadIdx.x] += red[threadIdx.x + s];
        __syncthreads();
    }
    if (threadIdx.x == 0) { zmax[be] = mx; zsum[be] = red[0]; }
}

__global__ void top2_kernel(const float* __restrict__ logits, const float* __restrict__ zmax,
                            const float* __restrict__ zsum, int* __restrict__ cnt,
                            int* __restrict__ tok, int* __restrict__ sel,
                            int* __restrict__ pos, float* __restrict__ wgt) {
    int t = blockIdx.x * blockDim.x + threadIdx.x;
    if (t >= T_) return;
    int b = t / S_;
    float rw[E_];
#pragma unroll
    for (int e = 0; e < E_; e++)
        rw[e] = expf(logits[(size_t)t * E_ + e] - zmax[b * E_ + e]) / zsum[b * E_ + e];
    int e0 = 0; float v0 = rw[0];
#pragma unroll
    for (int e = 1; e < E_; e++) if (rw[e] > v0) { v0 = rw[e]; e0 = e; }
    int e1 = -1; float v1 = -3e38f;
#pragma unroll
    for (int e = 0; e < E_; e++) if (e != e0 && rw[e] > v1) { v1 = rw[e]; e1 = e; }
    float inv = 1.f / (v0 + v1);
    int p0 = atomicAdd(&cnt[e0], 1);
    tok[e0 * T_ + p0] = t;
    int p1 = atomicAdd(&cnt[e1], 1);
    tok[e1 * T_ + p1] = t;
    sel[2*t] = e0; pos[2*t] = p0; wgt[2*t] = v0 * inv;
    sel[2*t+1] = e1; pos[2*t+1] = p1; wgt[2*t+1] = v1 * inv;
}

__global__ void offsets_kernel(const int* __restrict__ cnt, int* __restrict__ off) {
    if (threadIdx.x == 0) {
        int s = 0;
        for (int e = 0; e < E_; e++) { off[e] = s; s += cnt[e]; }
    }
}

__global__ void gather_kernel(const float* __restrict__ expout, const int* __restrict__ off,
                              const int* __restrict__ sel, const int* __restrict__ pos,
                              const float* __restrict__ wgt, float* __restrict__ out) {
    int t = blockIdx.x;
    int e0 = sel[2*t], e1 = sel[2*t+1];
    size_t r0 = (size_t)(off[e0] + pos[2*t]) * D_;
    size_t r1 = (size_t)(off[e1] + pos[2*t+1]) * D_;
    float w0 = wgt[2*t], w1 = wgt[2*t+1];
    for (int i = threadIdx.x; i < D_; i += 256)
        out[(size_t)t * D_ + i] += w0 * expout[r0 + i] + w1 * expout[r1 + i];
}

// ---------------- host launch ----------------
extern "C" void kernel_launch(void* const* d_in, const int* in_sizes, int n_in,
                              void* d_out, int out_size) {
    const float* data   = (const float*)d_in[0];
    const float* mask   = (const float*)d_in[1];
    const float* ropec  = (const float*)d_in[2];
    const float* ropes  = (const float*)d_in[3];
    const float* anw    = (const float*)d_in[4];
    const float* fnw    = (const float*)d_in[5];
    const float* wq     = (const float*)d_in[6];
    const float* wk     = (const float*)d_in[7];
    const float* wv     = (const float*)d_in[8];
    const float* wo     = (const float*)d_in[9];
    const float* gate_w = (const float*)d_in[10];
    const float* w1     = (const float*)d_in[11];
    const float* w2     = (const float*)d_in[12];
    const float* w3     = (const float*)d_in[13];
    const float* w1_a   = (const float*)d_in[14];
    const float* w1_b   = (const float*)d_in[15];
    const float* w3_a   = (const float*)d_in[16];
    const float* w3_b   = (const float*)d_in[17];
    const float* w2_a   = (const float*)d_in[18];
    const float* w2_b   = (const float*)d_in[19];
    float* out = (float*)d_out;

    float *xnr, *sn, *snr, *wqkv, *qkv, *attn, *woc, *w1c, *w3c, *w2c;
    float *c1, *c3, *h1, *h3, *u1, *u3, *u2;
    float *logits, *zmax, *zsum, *wgt, *expout;
    int *cnt, *off, *tok, *sel, *pos;
    cudaGetSymbolAddress((void**)&xnr, g_xnr);
    cudaGetSymbolAddress((void**)&sn, g_sn);
    cudaGetSymbolAddress((void**)&snr, g_snr);
    cudaGetSymbolAddress((void**)&wqkv, g_wqkv);
    cudaGetSymbolAddress((void**)&qkv, g_qkv);
    cudaGetSymbolAddress((void**)&attn, g_attn);
    cudaGetSymbolAddress((void**)&woc, g_woc);
    cudaGetSymbolAddress((void**)&w1c, g_w1c);
    cudaGetSymbolAddress((void**)&w3c, g_w3c);
    cudaGetSymbolAddress((void**)&w2c, g_w2c);
    cudaGetSymbolAddress((void**)&c1, g_c1);
    cudaGetSymbolAddress((void**)&c3, g_c3);
    cudaGetSymbolAddress((void**)&h1, g_h1);
    cudaGetSymbolAddress((void**)&h3, g_h3);
    cudaGetSymbolAddress((void**)&u1, g_u1);
    cudaGetSymbolAddress((void**)&u3, g_u3);
    cudaGetSymbolAddress((void**)&u2, g_u2);
    cudaGetSymbolAddress((void**)&expout, g_expout);
    cudaGetSymbolAddress((void**)&logits, g_logits);
    cudaGetSymbolAddress((void**)&zmax, g_zmax);
    cudaGetSymbolAddress((void**)&zsum, g_zsum);
    cudaGetSymbolAddress((void**)&cnt, g_cnt);
    cudaGetSymbolAddress((void**)&off, g_off);
    cudaGetSymbolAddress((void**)&tok, g_tok);
    cudaGetSymbolAddress((void**)&sel, g_sel);
    cudaGetSymbolAddress((void**)&pos, g_pos);
    cudaGetSymbolAddress((void**)&wgt, g_wgt);

    cudaFuncSetAttribute(attn_kernel, cudaFuncAttributeMaxDynamicSharedMemorySize, ATTN_SMEM);
    cudaFuncSetAttribute(gemm_mma, cudaFuncAttributeMaxDynamicSharedMemorySize, GMS);

    reset_kernel<<<1, 32>>>(cnt);
    concat_w_kernel<<<(NQKV_*D_/4 + 255)/256, 256>>>(wq, wk, wv, wqkv);
    cvt_kernel<<<((D_*D_/4) + 255)/256, 256>>>(wo, woc, (size_t)D_*D_/4);
    cvt_kernel<<<((F_*D_/4) + 255)/256, 256>>>(w1, w1c, (size_t)F_*D_/4);
    cvt_kernel<<<((F_*D_/4) + 255)/256, 256>>>(w3, w3c, (size_t)F_*D_/4);
    cvt_kernel<<<((D_*F_/4) + 255)/256, 256>>>(w2, w2c, (size_t)D_*F_/4);

    rmsnorm_kernel<<<T_, 256>>>(data, anw, xnr, xnr);   // xn: only rounded copy needed

    // Fused QKV projection: one GEMM, N=4096, grid 512 CTAs; rope on cols < 3072
    gemm_mma<<<dim3(NQKV_/128, T_/128, 1), 256, GMS>>>(xnr, wqkv, qkv, T_, NQKV_, D_,
        nullptr, nullptr, nullptr, ropec, ropes, 3072);

    attn_kernel<<<dim3(S_/64, H_, B_), 256, ATTN_SMEM>>>(qkv, mask, attn);

    // out = data + attn @ wo^T
    gemm_mma<<<dim3(D_/128, T_/128, 1), 256, GMS>>>(attn, woc, out, T_, D_, D_,
        data, nullptr, nullptr, nullptr, nullptr, 0);

    rmsnorm_kernel<<<T_, 256>>>(out, fnw, sn, snr);

    router_logits_kernel<<<T_, 256>>>(sn, gate_w, logits);
    col_softmax_stats<<<B_*E_, 256>>>(logits, zmax, zsum);
    top2_kernel<<<T_/256, 256>>>(logits, zmax, zsum, cnt, tok, sel, pos, wgt);
    offsets_kernel<<<1, 32>>>(cnt, off);

    // dense c1/c3
    gemm_mma<<<dim3(F_/128, T_/128, 1), 256, GMS>>>(snr, w1c, c1, T_, F_, D_,
        nullptr, nullptr, nullptr, nullptr, nullptr, 0);
    gemm_mma<<<dim3(F_/128, T_/128, 1), 256, GMS>>>(snr, w3c, c3, T_, F_, D_,
        nullptr, nullptr, nullptr, nullptr, nullptr, 0);

    // ---- expert-batched LoRA path (z = expert) ----
    gemm_small<<<dim3(1, T_/64, E_), 256>>>(sn, w3_a, u3, R_, D_,
        tok, 1, nullptr, 1.f, 0, cnt, off, (size_t)R_*D_, nullptr);
    gemm_small<<<dim3(F_/64, T_/64, E_), 256>>>(u3, w3_b, h3, F_, R_,
        tok, 0, c3, SCALE_, 0, cnt, off, (size_t)F_*R_, nullptr);
    gemm_small<<<dim3(1, T_/64, E_), 256>>>(sn, w1_a, u1, R_, D_,
        tok, 1, nullptr, 1.f, 0, cnt, off, (size_t)R_*D_, nullptr);
    gemm_small<<<dim3(F_/64, T_/64, E_), 256>>>(u1, w1_b, h1, F_, R_,
        tok, 0, c1, SCALE_, 0, cnt, off, (size_t)F_*R_, h3);
    // u2 = sr @ w2_a^T
    gemm_small<<<dim3(1, T_/64, E_), 256>>>(h1, w2_a, u2, R_, F_,
        tok, 0, nullptr, 1.f, 0, cnt, off, (size_t)R_*F_, nullptr);
    // expout = sr @ w2^T
    gemm_mma<<<dim3(D_/128, T_/128, E_), 256, GMS>>>(h1, w2c, expout, T_, D_, F_,
        nullptr, cnt, off, nullptr, nullptr, 0);
    // expout += SCALE * u2 @ w2_b^T
    gemm_small<<<dim3(D_/64, T_/64, E_), 256>>>(u2, w2_b, expout, D_, R_,
        tok, 0, nullptr, SCALE_, 1, cnt, off, (size_t)D_*R_, nullptr);

    // out[t] += w0*expout[slot0] + w1*expout[slot1]
    gather_kernel<<<T_, 256>>>(expout, off, sel, pos, wgt, out);
}

// round 13
// speedup vs baseline: 1.1890x; 1.1038x over previous
#include <cuda_runtime.h>
#include <math.h>
#include <stdint.h>

#define B_ 2
#define S_ 1024
#define D_ 2048
#define H_ 16
#define HKV_ 8
#define HD_ 128
#define F_ 5632
#define E_ 8
#define R_ 16
#define T_ (B_*S_)
#define EPS_ 1e-5f
#define SCALE_ 2.0f
#define NQKV_ 4096

// ---------------- device scratch (static, allocation-free) ----------------
__device__ float g_xnr[T_*D_];
__device__ float g_sn[T_*D_];
__device__ float g_snr[T_*D_];
__device__ float g_wqkv[NQKV_*D_];
__device__ float g_qkv[(size_t)T_*NQKV_];
__device__ float g_attn[T_*D_];
__device__ float g_woc[D_*D_];
__device__ float g_w13c[2*F_*D_];
__device__ float g_w2c[(size_t)D_*F_];
__device__ float g_c13[(size_t)T_*2*F_];
__device__ float g_h1[2*T_*F_];
__device__ float g_h3[2*T_*F_];
__device__ float g_expout[2*T_*D_];
__device__ float g_u1[2*T_*R_];
__device__ float g_u3[2*T_*R_];
__device__ float g_u2[2*T_*R_];
__device__ float g_logits[T_*E_];
__device__ float g_zmax[B_*E_];
__device__ float g_zsum[B_*E_];
__device__ int   g_cnt[E_];
__device__ int   g_off[E_];
__device__ int   g_tok[E_*T_];
__device__ int   g_sel[2*T_];
__device__ int   g_pos[2*T_];
__device__ float g_wgt[2*T_];

// ---------------- helpers ----------------
__device__ __forceinline__ float tf32r(float x) {
    uint32_t y;
    asm("cvt.rna.tf32.f32 %0, %1;" : "=r"(y) : "f"(x));
    return __uint_as_float(y);
}
__device__ __forceinline__ uint32_t smem_addr(const void* p) {
    uint32_t a;
    asm("{ .reg .u64 t; cvta.to.shared.u64 t, %1; cvt.u32.u64 %0, t; }" : "=r"(a) : "l"(p));
    return a;
}
__device__ __forceinline__ void mma_tf32(float& d0, float& d1, float& d2, float& d3,
                                         float a0, float a1, float a2, float a3,
                                         float b0, float b1) {
    asm volatile(
        "mma.sync.aligned.m16n8k8.row.col.f32.tf32.tf32.f32 "
        "{%0,%1,%2,%3}, {%4,%5,%6,%7}, {%8,%9}, {%0,%1,%2,%3};"
        : "+f"(d0), "+f"(d1), "+f"(d2), "+f"(d3)
        : "r"(__float_as_uint(a0)), "r"(__float_as_uint(a1)),
          "r"(__float_as_uint(a2)), "r"(__float_as_uint(a3)),
          "r"(__float_as_uint(b0)), "r"(__float_as_uint(b1)));
}

// ---------------- tf32 mma.sync GEMM: 128x128 CTA, 64x32 warp, 4-stage cp.async ----------------
// Inputs MUST be pre-rounded to tf32 (RNA) by producers.
#define GMS (4 * 5120 * 4)
__global__ __launch_bounds__(256, 2)
void gemm_mma(const float* __restrict__ A, const float* __restrict__ Bw,
              float* __restrict__ C, int M, int N, int K,
              const float* __restrict__ Res,
              const int* __restrict__ Mcnt, const int* __restrict__ Moff,
              const float* __restrict__ ropec, const float* __restrict__ ropes,
              int ropeN) {
    extern __shared__ float smdyn[];

    int z = blockIdx.z;
    if (Mcnt) M = Mcnt[z];
    int bm = blockIdx.y * 128;
    if (bm >= M) return;
    int bn = blockIdx.x * 128;
    int base = Moff ? Moff[z] : 0;

    int tid = threadIdx.x, wid = tid >> 5, lid = tid & 31;
    int wm = wid >> 2, wn = wid & 3;
    int m0 = wm * 64, n0 = wn * 32;
    int lr = lid >> 2, lc = lid & 3;

    float acc[4][4][4];
#pragma unroll
    for (int i = 0; i < 4; i++)
#pragma unroll
        for (int j = 0; j < 4; j++)
#pragma unroll
            for (int q = 0; q < 4; q++) acc[i][j][q] = 0.f;

    int grA = tid >> 2;
    int gc  = (tid & 3) * 4;

    uint32_t sbase = smem_addr(smdyn);

#define LOADT(st, k0) do {                                                      \
        _Pragma("unroll")                                                       \
        for (int it = 0; it < 2; it++) {                                        \
            int gr = it * 64 + grA;                                             \
            int rowA = bm + gr;                                                 \
            int sz = (rowA < M) ? 16 : 0;                                       \
            int rA = (rowA < M) ? rowA : (M - 1);                               \
            const float* sa = A + (size_t)(base + rA) * K + (k0) + gc;          \
            uint32_t da = sbase + (uint32_t)(((st) * 5120 + gr * 20 + gc) * 4); \
            asm volatile("cp.async.cg.shared.global [%0], [%1], 16, %2;"        \
                         :: "r"(da), "l"(sa), "r"(sz));                         \
            const float* sb = Bw + (size_t)(bn + gr) * K + (k0) + gc;           \
            uint32_t db = da + 2560 * 4;                                        \
            asm volatile("cp.async.cg.shared.global [%0], [%1], 16;"            \
                         :: "r"(db), "l"(sb));                                  \
        }                                                                       \
    } while (0)

#define COMPUTE(st) do {                                                        \
        const float* Asb = smdyn + (st) * 5120;                                 \
        const float* Bsb = Asb + 2560;                                          \
        _Pragma("unroll")                                                       \
        for (int ks = 0; ks < 2; ks++) {                                        \
            int kk = ks * 8;                                                    \
            float a[4][4], b[4][2];                                             \
            _Pragma("unroll")                                                   \
            for (int mt = 0; mt < 4; mt++) {                                    \
                a[mt][0] = Asb[(m0 + mt*16 + lr) * 20 + kk + lc];               \
                a[mt][1] = Asb[(m0 + mt*16 + lr + 8) * 20 + kk + lc];           \
                a[mt][2] = Asb[(m0 + mt*16 + lr) * 20 + kk + lc + 4];           \
                a[mt][3] = Asb[(m0 + mt*16 + lr + 8) * 20 + kk + lc + 4];       \
            }                                                                   \
            _Pragma("unroll")                                                   \
            for (int nt = 0; nt < 4; nt++) {                                    \
                b[nt][0] = Bsb[(n0 + nt*8 + lr) * 20 + kk + lc];                \
                b[nt][1] = Bsb[(n0 + nt*8 + lr) * 20 + kk + lc + 4];            \
            }                                                                   \
            _Pragma("unroll")                                                   \
            for (int mt = 0; mt < 4; mt++)                                      \
                _Pragma("unroll")                                               \
                for (int nt = 0; nt < 4; nt++)                                  \
                    mma_tf32(acc[mt][nt][0], acc[mt][nt][1],                    \
                             acc[mt][nt][2], acc[mt][nt][3],                    \
                             a[mt][0], a[mt][1], a[mt][2], a[mt][3],            \
                             b[nt][0], b[nt][1]);                               \
        }                                                                       \
    } while (0)

    int nk = K / 16;
#pragma unroll
    for (int s = 0; s < 3; s++) {
        if (s < nk) LOADT(s, s * 16);
        asm volatile("cp.async.commit_group;");
    }
    for (int t = 0; t < nk; t++) {
        asm volatile("cp.async.wait_group 2;");
        __syncthreads();
        if (t + 3 < nk) LOADT((t + 3) & 3, (t + 3) * 16);
        asm volatile("cp.async.commit_group;");
        COMPUTE(t & 3);
    }
#undef LOADT
#undef COMPUTE

#pragma unroll
    for (int mt = 0; mt < 4; mt++) {
#pragma unroll
        for (int nt = 0; nt < 4; nt++) {
            int row = bm + m0 + mt * 16 + lr;
            int col = bn + n0 + nt * 8 + lc * 2;
#pragma unroll
            for (int hh = 0; hh < 2; hh++) {
                int r = row + hh * 8;
                if (r >= M) continue;
                float2 v = make_float2(acc[mt][nt][hh * 2], acc[mt][nt][hh * 2 + 1]);
                if (Res) {
                    const float2 rv = *reinterpret_cast<const float2*>(
                        Res + (size_t)(base + r) * N + col);
                    v.x += rv.x; v.y += rv.y;
                }
                if (ropec && col < ropeN) {
                    int p = (col & 127) >> 1;
                    int sp = (base + r) & (S_ - 1);
                    float cc = ropec[sp * 64 + p];
                    float ss = ropes[sp * 64 + p];
                    float o1 = v.x * cc - v.y * ss;
                    float o2 = v.x * ss + v.y * cc;
                    v.x = o1; v.y = o2;
                }
                *reinterpret_cast<float2*>(C + (size_t)(base + r) * N + col) = v;
            }
        }
    }
}

// ---------------- small kernels ----------------
__global__ void reset_kernel(int* cnt) {
    if (threadIdx.x < E_) cnt[threadIdx.x] = 0;
}

__global__ void concat_w_kernel(const float* __restrict__ wq, const float* __restrict__ wk,
                                const float* __restrict__ wv, float* __restrict__ wqkv) {
    size_t i = ((size_t)blockIdx.x * blockDim.x + threadIdx.x) * 4;
    size_t tot = (size_t)NQKV_ * D_;
    if (i >= tot) return;
    size_t row = i / D_;
    const float* src;
    size_t srow;
    if (row < 2048)      { src = wq; srow = row; }
    else if (row < 3072) { src = wk; srow = row - 2048; }
    else                 { src = wv; srow = row - 3072; }
    float4 v = *reinterpret_cast<const float4*>(src + srow * D_ + (i % D_));
    v.x = tf32r(v.x); v.y = tf32r(v.y); v.z = tf32r(v.z); v.w = tf32r(v.w);
    *reinterpret_cast<float4*>(wqkv + i) = v;
}

__global__ void cvt_kernel(const float* __restrict__ src, float* __restrict__ dst, size_t n4) {
    size_t i = (size_t)blockIdx.x * blockDim.x + threadIdx.x;
    if (i >= n4) return;
    float4 v = reinterpret_cast<const float4*>(src)[i];
    v.x = tf32r(v.x); v.y = tf32r(v.y); v.z = tf32r(v.z); v.w = tf32r(v.w);
    reinterpret_cast<float4*>(dst)[i] = v;
}

__global__ void rmsnorm_kernel(const float* __restrict__ x, const float* __restrict__ w,
                               float* __restrict__ out, float* __restrict__ outR) {
    int row = blockIdx.x;
    const float* xr = x + (size_t)row * D_;
    float ss = 0.f;
    for (int i = threadIdx.x; i < D_; i += 256) { float v = xr[i]; ss += v * v; }
    __shared__ float red[256];
    red[threadIdx.x] = ss; __syncthreads();
    for (int s = 128; s > 0; s >>= 1) {
        if (threadIdx.x < s) red[threadIdx.x] += red[threadIdx.x + s];
        __syncthreads();
    }
    float inv = rsqrtf(red[0] / (float)D_ + EPS_);
    float* orow = out + (size_t)row * D_;
    float* rrow = outR ? outR + (size_t)row * D_ : nullptr;
    for (int i = threadIdx.x; i < D_; i += 256) {
        float v = xr[i] * inv * w[i];
        orow[i] = v;
        if (rrow) rrow[i] = tf32r(v);
    }
}

// ---------------- small SGEMM: 64x64 tile, expert-batched (LoRA path) ----------------
__global__ void gemm_small(const float* __restrict__ A, const float* __restrict__ Bw,
                           float* __restrict__ C, int N, int K,
                           const int* __restrict__ tokIdx, int gatherA,
                           const float* __restrict__ Res, size_t resStride,
                           float alpha, int accumulate,
                           const int* __restrict__ Mcnt, const int* __restrict__ Moff,
                           size_t strideB, const float* __restrict__ siluMul) {
    int z = blockIdx.z;
    int M = Mcnt[z];
    int bm = blockIdx.y * 64;
    if (bm >= M) return;
    int bn = blockIdx.x * 64;
    int base = Moff[z];
    const int* tok = tokIdx + z * T_;
    const float* Bz = Bw + (size_t)z * strideB;

    __shared__ float As[16][64];
    __shared__ float Bs[16][64];
    int tid = threadIdx.x;
    int tx = tid & 15, ty = tid >> 4;
    float acc[4][4];
#pragma unroll
    for (int i = 0; i < 4; i++)
#pragma unroll
        for (int j = 0; j < 4; j++) acc[i][j] = 0.f;

    for (int k0 = 0; k0 < K; k0 += 16) {
#pragma unroll
        for (int l = 0; l < 4; l++) {
            int ii = l * 256 + tid;
            int m = ii >> 4, kk = ii & 15;
            int row = bm + m;
            float a = 0.f;
            if (row < M) {
                int ar = gatherA ? tok[row] : base + row;
                a = A[(size_t)ar * K + k0 + kk];
            }
            As[kk][m] = a;
            float bv = 0.f;
            if (bn + m < N) bv = Bz[(size_t)(bn + m) * K + k0 + kk];
            Bs[kk][m] = bv;
        }
        __syncthreads();
#pragma unroll
        for (int kk = 0; kk < 16; kk++) {
            float4 av = *reinterpret_cast<const float4*>(&As[kk][ty * 4]);
            float4 bv = *reinterpret_cast<const float4*>(&Bs[kk][tx * 4]);
            float a0 = av.x, a1 = av.y, a2 = av.z, a3 = av.w;
            float b0 = bv.x, b1 = bv.y, b2 = bv.z, b3 = bv.w;
            acc[0][0] += a0*b0; acc[0][1] += a0*b1; acc[0][2] += a0*b2; acc[0][3] += a0*b3;
            acc[1][0] += a1*b0; acc[1][1] += a1*b1; acc[1][2] += a1*b2; acc[1][3] += a1*b3;
            acc[2][0] += a2*b0; acc[2][1] += a2*b1; acc[2][2] += a2*b2; acc[2][3] += a2*b3;
            acc[3][0] += a3*b0; acc[3][1] += a3*b1; acc[3][2] += a3*b2; acc[3][3] += a3*b3;
        }
        __syncthreads();
    }
#pragma unroll
    for (int i = 0; i < 4; i++) {
        int row = bm + ty * 4 + i;
        if (row >= M) continue;
        size_t crow = (size_t)(base + row) * N;
#pragma unroll
        for (int j = 0; j < 4; j++) {
            int col = bn + tx * 4 + j;
            if (col >= N) continue;
            float val = alpha * acc[i][j];
            if (Res) val += Res[(size_t)tok[row] * resStride + col];
            if (siluMul) {
                float s = val / (1.f + expf(-val));
                val = tf32r(s * siluMul[crow + col]);
            }
            if (accumulate) C[crow + col] += val;
            else            C[crow + col] = val;
        }
    }
}

// ---------------- flash attention, tf32 mma, 64-query tiles ----------------
// smem floats: Qs[64][132]=8448, KV union(K[64][132]=8448, Vt[128][68]=8704)=8704,
//              Sc[64][68]=4352, mrow/lrow/facrow 192 -> 21696 floats
#define ATTN_SMEM (21696 * 4)
__global__ __launch_bounds__(256, 1)
void attn_mma(const float* __restrict__ qkv, const float* __restrict__ mask,
              float* __restrict__ o) {
    extern __shared__ float sm[];
    float* Qs    = sm;            // [64][132]
    float* KV    = sm + 8448;     // K [64][132] then V^T [128][68]
    float* Sc    = sm + 17152;    // [64][68]
    float* mrow  = sm + 21504;
    float* lrow  = sm + 21568;
    float* facrw = sm + 21632;

    int qt = blockIdx.x, h = blockIdx.y, b = blockIdx.z;
    int hkv = h >> 1;
    int tid = threadIdx.x, wid = tid >> 5, lid = tid & 31;
    int q0 = qt * 64;
    int wm = wid >> 1, wn = wid & 1;     // 4x2 warps
    int m0 = wm * 16;
    int n0s = wn * 32, n0p = wn * 64;
    int lr = lid >> 2, lc = lid & 3;
    int rg = tid >> 2, cg = tid & 3;

    for (int i = tid; i < 64 * 128; i += 256) {
        int r = i >> 7, d = i & 127;
        Qs[r * 132 + d] = tf32r(qkv[(size_t)(b * S_ + q0 + r) * NQKV_ + h * HD_ + d]);
    }
    if (tid < 64) { mrow[tid] = -3e38f; lrow[tid] = 0.f; }
    float oa[8][4];
#pragma unroll
    for (int i = 0; i < 8; i++)
#pragma unroll
        for (int q = 0; q < 4; q++) oa[i][q] = 0.f;
    __syncthreads();

    const float sca = 0.08838834764831845f;   // 1/sqrt(128)
    for (int kt = 0; kt < S_; kt += 64) {
        // K tile row-major [key][dim]
        for (int i = tid; i < 64 * 128; i += 256) {
            int r = i >> 7, d = i & 127;
            KV[r * 132 + d] = tf32r(qkv[(size_t)(b * S_ + kt + r) * NQKV_ + 2048 + hkv * HD_ + d]);
        }
        __syncthreads();
        // scores: 64x64, warp tile 16x32
        float sc_[4][4];
#pragma unroll
        for (int i = 0; i < 4; i++)
#pragma unroll
            for (int q = 0; q < 4; q++) sc_[i][q] = 0.f;
#pragma unroll
        for (int ks = 0; ks < 16; ks++) {
            int kk = ks * 8;
            float a0 = Qs[(m0 + lr) * 132 + kk + lc];
            float a1 = Qs[(m0 + lr + 8) * 132 + kk + lc];
            float a2 = Qs[(m0 + lr) * 132 + kk + lc + 4];
            float a3 = Qs[(m0 + lr + 8) * 132 + kk + lc + 4];
#pragma unroll
            for (int nt = 0; nt < 4; nt++) {
                float b0 = KV[(n0s + nt * 8 + lr) * 132 + kk + lc];
                float b1 = KV[(n0s + nt * 8 + lr) * 132 + kk + lc + 4];
                mma_tf32(sc_[nt][0], sc_[nt][1], sc_[nt][2], sc_[nt][3],
                         a0, a1, a2, a3, b0, b1);
            }
        }
        // write scores (+scale +mask) into Sc
#pragma unroll
        for (int nt = 0; nt < 4; nt++) {
#pragma unroll
            for (int hh = 0; hh < 2; hh++) {
                int row = m0 + lr + hh * 8;
                int col = n0s + nt * 8 + lc * 2;
                Sc[row * 68 + col]     = sc_[nt][hh * 2]     * sca + mask[(q0 + row) * S_ + kt + col];
                Sc[row * 68 + col + 1] = sc_[nt][hh * 2 + 1] * sca + mask[(q0 + row) * S_ + kt + col + 1];
            }
        }
        __syncthreads();
        // V tile transposed [dim][key] (overwrites K)
        for (int i = tid; i < 64 * 128; i += 256) {
            int r = i >> 7, d = i & 127;
            KV[d * 68 + r] = tf32r(qkv[(size_t)(b * S_ + kt + r) * NQKV_ + 3072 + hkv * HD_ + d]);
        }
        // streaming softmax: 4 lanes per row
        float tm = -3e38f;
#pragma unroll
        for (int ii = 0; ii < 16; ii++) tm = fmaxf(tm, Sc[rg * 68 + cg + 4 * ii]);
        tm = fmaxf(tm, __shfl_xor_sync(0xffffffffu, tm, 1));
        tm = fmaxf(tm, __shfl_xor_sync(0xffffffffu, tm, 2));
        float mprev = mrow[rg];
        float mnew = fmaxf(mprev, tm);
        float fac = expf(mprev - mnew);
        float ls = 0.f;
#pragma unroll
        for (int ii = 0; ii < 16; ii++) {
            float p = expf(Sc[rg * 68 + cg + 4 * ii] - mnew);
            Sc[rg * 68 + cg + 4 * ii] = tf32r(p);
            ls += p;
        }
        ls += __shfl_xor_sync(0xffffffffu, ls, 1);
        ls += __shfl_xor_sync(0xffffffffu, ls, 2);
        if (cg == 0) { mrow[rg] = mnew; lrow[rg] = lrow[rg] * fac + ls; facrw[rg] = fac; }
        __syncthreads();
        // rescale running output
        float f0 = facrw[m0 + lr], f1 = facrw[m0 + lr + 8];
#pragma unroll
        for (int nt = 0; nt < 8; nt++) {
            oa[nt][0] *= f0; oa[nt][1] *= f0;
            oa[nt][2] *= f1; oa[nt][3] *= f1;
        }
        // PV: 64x128x64, warp tile 16x64
#pragma unroll
        for (int ks = 0; ks < 8; ks++) {
            int kk = ks * 8;
            float a0 = Sc[(m0 + lr) * 68 + kk + lc];
            float a1 = Sc[(m0 + lr + 8) * 68 + kk + lc];
            float a2 = Sc[(m0 + lr) * 68 + kk + lc + 4];
            float a3 = Sc[(m0 + lr + 8) * 68 + kk + lc + 4];
#pragma unroll
            for (int nt = 0; nt < 8; nt++) {
                float b0 = KV[(n0p + nt * 8 + lr) * 68 + kk + lc];
                float b1 = KV[(n0p + nt * 8 + lr) * 68 + kk + lc + 4];
                mma_tf32(oa[nt][0], oa[nt][1], oa[nt][2], oa[nt][3],
                         a0, a1, a2, a3, b0, b1);
            }
        }
        __syncthreads();    // before next K load overwrites V
    }
    float i0 = 1.f / lrow[m0 + lr];
    float i1 = 1.f / lrow[m0 + lr + 8];
#pragma unroll
    for (int nt = 0; nt < 8; nt++) {
        int row0 = m0 + lr, row1 = row0 + 8;
        int col = n0p + nt * 8 + lc * 2;
        float* p0 = o + ((size_t)(b * S_ + q0 + row0) * H_ + h) * HD_ + col;
        float* p1 = o + ((size_t)(b * S_ + q0 + row1) * H_ + h) * HD_ + col;
        p0[0] = tf32r(oa[nt][0] * i0); p0[1] = tf32r(oa[nt][1] * i0);
        p1[0] = tf32r(oa[nt][2] * i1); p1[1] = tf32r(oa[nt][3] * i1);
    }
}

// ---------------- router ----------------
__global__ void router_logits_kernel(const float* __restrict__ sn, const float* __restrict__ gw,
                                     float* __restrict__ logits) {
    int t = blockIdx.x;
    int wid = threadIdx.x >> 5, lid = threadIdx.x & 31;
    const float* x = sn + (size_t)t * D_;
    const float* g = gw + (size_t)wid * D_;
    float s = 0.f;
    for (int i = lid * 4; i < D_; i += 128) {
        float4 xv = *reinterpret_cast<const float4*>(x + i);
        float4 gv = *reinterpret_cast<const float4*>(g + i);
        s += xv.x * gv.x + xv.y * gv.y + xv.z * gv.z + xv.w * gv.w;
    }
#pragma unroll
    for (int o = 16; o > 0; o >>= 1) s += __shfl_xor_sync(0xffffffffu, s, o);
    if (lid == 0) logits[(size_t)t * E_ + wid] = s;
}

__global__ void col_softmax_stats(const float* __restrict__ logits, float* __restrict__ zmax,
                                  float* __restrict__ zsum) {
    int be = blockIdx.x;
    int b = be / E_, e = be % E_;
    __shared__ float red[256];
    float mx = -3e38f;
    for (int s = threadIdx.x; s < S_; s += 256)
        mx = fmaxf(mx, logits[((size_t)b * S_ + s) * E_ + e]);
    red[threadIdx.x] = mx; __syncthreads();
    for (int s = 128; s > 0; s >>= 1) {
        if (threadIdx.x < s) red[threadIdx.x] = fmaxf(red[threadIdx.x], red[threadIdx.x + s]);
        __syncthreads();
    }
    mx = red[0]; __syncthreads();
    float sum = 0.f;
    for (int s = threadIdx.x; s < S_; s += 256)
        sum += expf(logits[((size_t)b * S_ + s) * E_ + e] - mx);
    red[threadIdx.x] = sum; __syncthreads();
    for (int s = 128; s > 0; s >>= 1) {
        if (threadIdx.x < s) red[threadIdx.x] += red[threadIdx.x + s];
        __syncthreads();
    }
    if (threadIdx.x == 0) { zmax[be] = mx; zsum[be] = red[0]; }
}

__global__ void top2_kernel(const float* __restrict__ logits, const float* __restrict__ zmax,
                            const float* __restrict__ zsum, int* __restrict__ cnt,
                            int* __restrict__ tok, int* __restrict__ sel,
                            int* __restrict__ pos, float* __restrict__ wgt) {
    int t = blockIdx.x * blockDim.x + threadIdx.x;
    if (t >= T_) return;
    int b = t / S_;
    float rw[E_];
#pragma unroll
    for (int e = 0; e < E_; e++)
        rw[e] = expf(logits[(size_t)t * E_ + e] - zmax[b * E_ + e]) / zsum[b * E_ + e];
    int e0 = 0; float v0 = rw[0];
#pragma unroll
    for (int e = 1; e < E_; e++) if (rw[e] > v0) { v0 = rw[e]; e0 = e; }
    int e1 = -1; float v1 = -3e38f;
#pragma unroll
    for (int e = 0; e < E_; e++) if (e != e0 && rw[e] > v1) { v1 = rw[e]; e1 = e; }
    float inv = 1.f / (v0 + v1);
    int p0 = atomicAdd(&cnt[e0], 1);
    tok[e0 * T_ + p0] = t;
    int p1 = atomicAdd(&cnt[e1], 1);
    tok[e1 * T_ + p1] = t;
    sel[2*t] = e0; pos[2*t] = p0; wgt[2*t] = v0 * inv;
    sel[2*t+1] = e1; pos[2*t+1] = p1; wgt[2*t+1] = v1 * inv;
}

__global__ void offsets_kernel(const int* __restrict__ cnt, int* __restrict__ off) {
    if (threadIdx.x == 0) {
        int s = 0;
        for (int e = 0; e < E_; e++) { off[e] = s; s += cnt[e]; }
    }
}

__global__ void gather_kernel(const float* __restrict__ expout, const int* __restrict__ off,
                              const int* __restrict__ sel, const int* __restrict__ pos,
                              const float* __restrict__ wgt, float* __restrict__ out) {
    int t = blockIdx.x;
    int e0 = sel[2*t], e1 = sel[2*t+1];
    size_t r0 = (size_t)(off[e0] + pos[2*t]) * D_;
    size_t r1 = (size_t)(off[e1] + pos[2*t+1]) * D_;
    float w0 = wgt[2*t], w1 = wgt[2*t+1];
    for (int i = threadIdx.x; i < D_; i += 256)
        out[(size_t)t * D_ + i] += w0 * expout[r0 + i] + w1 * expout[r1 + i];
}

// ---------------- host launch ----------------
extern "C" void kernel_launch(void* const* d_in, const int* in_sizes, int n_in,
                              void* d_out, int out_size) {
    const float* data   = (const float*)d_in[0];
    const float* mask   = (const float*)d_in[1];
    const float* ropec  = (const float*)d_in[2];
    const float* ropes  = (const float*)d_in[3];
    const float* anw    = (const float*)d_in[4];
    const float* fnw    = (const float*)d_in[5];
    const float* wq     = (const float*)d_in[6];
    const float* wk     = (const float*)d_in[7];
    const float* wv     = (const float*)d_in[8];
    const float* wo     = (const float*)d_in[9];
    const float* gate_w = (const float*)d_in[10];
    const float* w1     = (const float*)d_in[11];
    const float* w2     = (const float*)d_in[12];
    const float* w3     = (const float*)d_in[13];
    const float* w1_a   = (const float*)d_in[14];
    const float* w1_b   = (const float*)d_in[15];
    const float* w3_a   = (const float*)d_in[16];
    const float* w3_b   = (const float*)d_in[17];
    const float* w2_a   = (const float*)d_in[18];
    const float* w2_b   = (const float*)d_in[19];
    float* out = (float*)d_out;

    float *xnr, *sn, *snr, *wqkv, *qkv, *attn, *woc, *w13c, *w2c, *c13;
    float *h1, *h3, *u1, *u3, *u2;
    float *logits, *zmax, *zsum, *wgt, *expout;
    int *cnt, *off, *tok, *sel, *pos;
    cudaGetSymbolAddress((void**)&xnr, g_xnr);
    cudaGetSymbolAddress((void**)&sn, g_sn);
    cudaGetSymbolAddress((void**)&snr, g_snr);
    cudaGetSymbolAddress((void**)&wqkv, g_wqkv);
    cudaGetSymbolAddress((void**)&qkv, g_qkv);
    cudaGetSymbolAddress((void**)&attn, g_attn);
    cudaGetSymbolAddress((void**)&woc, g_woc);
    cudaGetSymbolAddress((void**)&w13c, g_w13c);
    cudaGetSymbolAddress((void**)&w2c, g_w2c);
    cudaGetSymbolAddress((void**)&c13, g_c13);
    cudaGetSymbolAddress((void**)&h1, g_h1);
    cudaGetSymbolAddress((void**)&h3, g_h3);
    cudaGetSymbolAddress((void**)&u1, g_u1);
    cudaGetSymbolAddress((void**)&u3, g_u3);
    cudaGetSymbolAddress((void**)&u2, g_u2);
    cudaGetSymbolAddress((void**)&expout, g_expout);
    cudaGetSymbolAddress((void**)&logits, g_logits);
    cudaGetSymbolAddress((void**)&zmax, g_zmax);
    cudaGetSymbolAddress((void**)&zsum, g_zsum);
    cudaGetSymbolAddress((void**)&cnt, g_cnt);
    cudaGetSymbolAddress((void**)&off, g_off);
    cudaGetSymbolAddress((void**)&tok, g_tok);
    cudaGetSymbolAddress((void**)&sel, g_sel);
    cudaGetSymbolAddress((void**)&pos, g_pos);
    cudaGetSymbolAddress((void**)&wgt, g_wgt);

    cudaFuncSetAttribute(attn_mma, cudaFuncAttributeMaxDynamicSharedMemorySize, ATTN_SMEM);
    cudaFuncSetAttribute(gemm_mma, cudaFuncAttributeMaxDynamicSharedMemorySize, GMS);

    reset_kernel<<<1, 32>>>(cnt);
    concat_w_kernel<<<(NQKV_*D_/4 + 255)/256, 256>>>(wq, wk, wv, wqkv);
    cvt_kernel<<<((D_*D_/4) + 255)/256, 256>>>(wo, woc, (size_t)D_*D_/4);
    cvt_kernel<<<((F_*D_/4) + 255)/256, 256>>>(w1, w13c, (size_t)F_*D_/4);
    cvt_kernel<<<((F_*D_/4) + 255)/256, 256>>>(w3, w13c + (size_t)F_*D_, (size_t)F_*D_/4);
    cvt_kernel<<<((D_*F_/4) + 255)/256, 256>>>(w2, w2c, (size_t)D_*F_/4);

    rmsnorm_kernel<<<T_, 256>>>(data, anw, xnr, xnr);

    // Fused QKV projection; rope on cols < 3072
    gemm_mma<<<dim3(NQKV_/128, T_/128, 1), 256, GMS>>>(xnr, wqkv, qkv, T_, NQKV_, D_,
        nullptr, nullptr, nullptr, ropec, ropes, 3072);

    attn_mma<<<dim3(S_/64, H_, B_), 256, ATTN_SMEM>>>(qkv, mask, attn);

    // out = data + attn @ wo^T
    gemm_mma<<<dim3(D_/128, T_/128, 1), 256, GMS>>>(attn, woc, out, T_, D_, D_,
        data, nullptr, nullptr, nullptr, nullptr, 0);

    rmsnorm_kernel<<<T_, 256>>>(out, fnw, sn, snr);

    router_logits_kernel<<<T_, 256>>>(sn, gate_w, logits);
    col_softmax_stats<<<B_*E_, 256>>>(logits, zmax, zsum);
    top2_kernel<<<T_/256, 256>>>(logits, zmax, zsum, cnt, tok, sel, pos, wgt);
    offsets_kernel<<<1, 32>>>(cnt, off);

    // merged dense c1|c3: one GEMM, N=11264
    gemm_mma<<<dim3(2*F_/128, T_/128, 1), 256, GMS>>>(snr, w13c, c13, T_, 2*F_, D_,
        nullptr, nullptr, nullptr, nullptr, nullptr, 0);

    // ---- expert-batched LoRA path (z = expert) ----
    gemm_small<<<dim3(1, T_/64, E_), 256>>>(sn, w3_a, u3, R_, D_,
        tok, 1, nullptr, 0, 1.f, 0, cnt, off, (size_t)R_*D_, nullptr);
    gemm_small<<<dim3(F_/64, T_/64, E_), 256>>>(u3, w3_b, h3, F_, R_,
        tok, 0, c13 + F_, (size_t)(2*F_), SCALE_, 0, cnt, off, (size_t)F_*R_, nullptr);
    gemm_small<<<dim3(1, T_/64, E_), 256>>>(sn, w1_a, u1, R_, D_,
        tok, 1, nullptr, 0, 1.f, 0, cnt, off, (size_t)R_*D_, nullptr);
    gemm_small<<<dim3(F_/64, T_/64, E_), 256>>>(u1, w1_b, h1, F_, R_,
        tok, 0, c13, (size_t)(2*F_), SCALE_, 0, cnt, off, (size_t)F_*R_, h3);
    // u2 = sr @ w2_a^T
    gemm_small<<<dim3(1, T_/64, E_), 256>>>(h1, w2_a, u2, R_, F_,
        tok, 0, nullptr, 0, 1.f, 0, cnt, off, (size_t)R_*F_, nullptr);
    // expout = sr @ w2^T
    gemm_mma<<<dim3(D_/128, T_/128, E_), 256, GMS>>>(h1, w2c, expout, T_, D_, F_,
        nullptr, cnt, off, nullptr, nullptr, 0);
    // expout += SCALE * u2 @ w2_b^T
    gemm_small<<<dim3(D_/64, T_/64, E_), 256>>>(u2, w2_b, expout, D_, R_,
        tok, 0, nullptr, 0, SCALE_, 1, cnt, off, (size_t)D_*R_, nullptr);

    // out[t] += w0*expout[slot0] + w1*expout[slot1]
    gather_kernel<<<T_, 256>>>(expout, off, sel, pos, wgt, out);
}

// round 14
// speedup vs baseline: 1.2360x; 1.0395x over previous
#include <cuda_runtime.h>
#include <math.h>
#include <stdint.h>

#define B_ 2
#define S_ 1024
#define D_ 2048
#define H_ 16
#define HKV_ 8
#define HD_ 128
#define F_ 5632
#define E_ 8
#define R_ 16
#define T_ (B_*S_)
#define EPS_ 1e-5f
#define SCALE_ 2.0f
#define NQKV_ 4096

// ---------------- device scratch (static, allocation-free) ----------------
__device__ float g_xnr[T_*D_];
__device__ float g_sn[T_*D_];
__device__ float g_snr[T_*D_];
__device__ float g_wqkv[NQKV_*D_];
__device__ float g_qkv[(size_t)T_*NQKV_];
__device__ float g_attn[T_*D_];
__device__ float g_woc[D_*D_];
__device__ float g_w13c[2*F_*D_];
__device__ float g_w2c[(size_t)D_*F_];
__device__ float g_c13[(size_t)T_*2*F_];
__device__ float g_h1[2*T_*F_];
__device__ float g_h3[2*T_*F_];
__device__ float g_expout[2*T_*D_];
__device__ float g_u1[2*T_*R_];
__device__ float g_u3[2*T_*R_];
__device__ float g_u2[2*T_*R_];
__device__ float g_logits[T_*E_];
__device__ float g_zmax[B_*E_];
__device__ float g_zsum[B_*E_];
__device__ int   g_cnt[E_];
__device__ int   g_off[E_];
__device__ int   g_tok[E_*T_];
__device__ int   g_sel[2*T_];
__device__ int   g_pos[2*T_];
__device__ float g_wgt[2*T_];

// ---------------- helpers ----------------
__device__ __forceinline__ float tf32r(float x) {
    uint32_t y;
    asm("cvt.rna.tf32.f32 %0, %1;" : "=r"(y) : "f"(x));
    return __uint_as_float(y);
}
__device__ __forceinline__ uint32_t smem_addr(const void* p) {
    uint32_t a;
    asm("{ .reg .u64 t; cvta.to.shared.u64 t, %1; cvt.u32.u64 %0, t; }" : "=r"(a) : "l"(p));
    return a;
}
__device__ __forceinline__ void mma_tf32(float& d0, float& d1, float& d2, float& d3,
                                         float a0, float a1, float a2, float a3,
                                         float b0, float b1) {
    asm volatile(
        "mma.sync.aligned.m16n8k8.row.col.f32.tf32.tf32.f32 "
        "{%0,%1,%2,%3}, {%4,%5,%6,%7}, {%8,%9}, {%0,%1,%2,%3};"
        : "+f"(d0), "+f"(d1), "+f"(d2), "+f"(d3)
        : "r"(__float_as_uint(a0)), "r"(__float_as_uint(a1)),
          "r"(__float_as_uint(a2)), "r"(__float_as_uint(a3)),
          "r"(__float_as_uint(b0)), "r"(__float_as_uint(b1)));
}

// ---------------- tf32 mma.sync GEMM: 128x128 CTA (128 thr, 2x2 warps of 64x64), 4-stage cp.async ----------------
// Inputs MUST be pre-rounded to tf32 (RNA) by producers.
#define GMS (4 * 5120 * 4)
__global__ __launch_bounds__(128, 2)
void gemm_mma(const float* __restrict__ A, const float* __restrict__ Bw,
              float* __restrict__ C, int M, int N, int K,
              const float* __restrict__ Res,
              const int* __restrict__ Mcnt, const int* __restrict__ Moff,
              const float* __restrict__ ropec, const float* __restrict__ ropes,
              int ropeN) {
    extern __shared__ float smdyn[];

    int z = blockIdx.z;
    if (Mcnt) M = Mcnt[z];
    int bm = blockIdx.y * 128;
    if (bm >= M) return;
    int bn = blockIdx.x * 128;
    int base = Moff ? Moff[z] : 0;

    int tid = threadIdx.x, wid = tid >> 5, lid = tid & 31;
    int wm = wid >> 1, wn = wid & 1;           // 2 x 2 warp grid, 64x64 tiles
    int m0 = wm * 64, n0 = wn * 64;
    int lr = lid >> 2, lc = lid & 3;

    float acc[4][8][4];
#pragma unroll
    for (int i = 0; i < 4; i++)
#pragma unroll
        for (int j = 0; j < 8; j++)
#pragma unroll
            for (int q = 0; q < 4; q++) acc[i][j][q] = 0.f;

    int grA = tid >> 2;                        // 0..31
    int gc  = (tid & 3) * 4;

    uint32_t sbase = smem_addr(smdyn);

#define LOADT(st, k0) do {                                                      \
        _Pragma("unroll")                                                       \
        for (int it = 0; it < 4; it++) {                                        \
            int gr = it * 32 + grA;                                             \
            int rowA = bm + gr;                                                 \
            int sz = (rowA < M) ? 16 : 0;                                       \
            int rA = (rowA < M) ? rowA : (M - 1);                               \
            const float* sa = A + (size_t)(base + rA) * K + (k0) + gc;          \
            uint32_t da = sbase + (uint32_t)(((st) * 5120 + gr * 20 + gc) * 4); \
            asm volatile("cp.async.cg.shared.global [%0], [%1], 16, %2;"        \
                         :: "r"(da), "l"(sa), "r"(sz));                         \
            const float* sb = Bw + (size_t)(bn + gr) * K + (k0) + gc;           \
            uint32_t db = da + 2560 * 4;                                        \
            asm volatile("cp.async.cg.shared.global [%0], [%1], 16;"            \
                         :: "r"(db), "l"(sb));                                  \
        }                                                                       \
    } while (0)

#define COMPUTE(st) do {                                                        \
        const float* Asb = smdyn + (st) * 5120;                                 \
        const float* Bsb = Asb + 2560;                                          \
        _Pragma("unroll")                                                       \
        for (int ks = 0; ks < 2; ks++) {                                        \
            int kk = ks * 8;                                                    \
            float a[4][4], b[8][2];                                             \
            _Pragma("unroll")                                                   \
            for (int mt = 0; mt < 4; mt++) {                                    \
                a[mt][0] = Asb[(m0 + mt*16 + lr) * 20 + kk + lc];               \
                a[mt][1] = Asb[(m0 + mt*16 + lr + 8) * 20 + kk + lc];           \
                a[mt][2] = Asb[(m0 + mt*16 + lr) * 20 + kk + lc + 4];           \
                a[mt][3] = Asb[(m0 + mt*16 + lr + 8) * 20 + kk + lc + 4];       \
            }                                                                   \
            _Pragma("unroll")                                                   \
            for (int nt = 0; nt < 8; nt++) {                                    \
                b[nt][0] = Bsb[(n0 + nt*8 + lr) * 20 + kk + lc];                \
                b[nt][1] = Bsb[(n0 + nt*8 + lr) * 20 + kk + lc + 4];            \
            }                                                                   \
            _Pragma("unroll")                                                   \
            for (int mt = 0; mt < 4; mt++)                                      \
                _Pragma("unroll")                                               \
                for (int nt = 0; nt < 8; nt++)                                  \
                    mma_tf32(acc[mt][nt][0], acc[mt][nt][1],                    \
                             acc[mt][nt][2], acc[mt][nt][3],                    \
                             a[mt][0], a[mt][1], a[mt][2], a[mt][3],            \
                             b[nt][0], b[nt][1]);                               \
        }                                                                       \
    } while (0)

    int nk = K / 16;
#pragma unroll
    for (int s = 0; s < 3; s++) {
        if (s < nk) LOADT(s, s * 16);
        asm volatile("cp.async.commit_group;");
    }
    for (int t = 0; t < nk; t++) {
        asm volatile("cp.async.wait_group 2;");
        __syncthreads();
        if (t + 3 < nk) LOADT((t + 3) & 3, (t + 3) * 16);
        asm volatile("cp.async.commit_group;");
        COMPUTE(t & 3);
    }
#undef LOADT
#undef COMPUTE

#pragma unroll
    for (int mt = 0; mt < 4; mt++) {
#pragma unroll
        for (int nt = 0; nt < 8; nt++) {
            int row = bm + m0 + mt * 16 + lr;
            int col = bn + n0 + nt * 8 + lc * 2;
#pragma unroll
            for (int hh = 0; hh < 2; hh++) {
                int r = row + hh * 8;
                if (r >= M) continue;
                float2 v = make_float2(acc[mt][nt][hh * 2], acc[mt][nt][hh * 2 + 1]);
                if (Res) {
                    const float2 rv = *reinterpret_cast<const float2*>(
                        Res + (size_t)(base + r) * N + col);
                    v.x += rv.x; v.y += rv.y;
                }
                if (ropec && col < ropeN) {
                    int p = (col & 127) >> 1;
                    int sp = (base + r) & (S_ - 1);
                    float cc = ropec[sp * 64 + p];
                    float ss = ropes[sp * 64 + p];
                    float o1 = v.x * cc - v.y * ss;
                    float o2 = v.x * ss + v.y * cc;
                    v.x = o1; v.y = o2;
                }
                *reinterpret_cast<float2*>(C + (size_t)(base + r) * N + col) = v;
            }
        }
    }
}

// ---------------- small kernels ----------------
__global__ void reset_kernel(int* cnt) {
    if (threadIdx.x < E_) cnt[threadIdx.x] = 0;
}

__global__ void concat_w_kernel(const float* __restrict__ wq, const float* __restrict__ wk,
                                const float* __restrict__ wv, float* __restrict__ wqkv) {
    size_t i = ((size_t)blockIdx.x * blockDim.x + threadIdx.x) * 4;
    size_t tot = (size_t)NQKV_ * D_;
    if (i >= tot) return;
    size_t row = i / D_;
    const float* src;
    size_t srow;
    if (row < 2048)      { src = wq; srow = row; }
    else if (row < 3072) { src = wk; srow = row - 2048; }
    else                 { src = wv; srow = row - 3072; }
    float4 v = *reinterpret_cast<const float4*>(src + srow * D_ + (i % D_));
    v.x = tf32r(v.x); v.y = tf32r(v.y); v.z = tf32r(v.z); v.w = tf32r(v.w);
    *reinterpret_cast<float4*>(wqkv + i) = v;
}

__global__ void cvt_kernel(const float* __restrict__ src, float* __restrict__ dst, size_t n4) {
    size_t i = (size_t)blockIdx.x * blockDim.x + threadIdx.x;
    if (i >= n4) return;
    float4 v = reinterpret_cast<const float4*>(src)[i];
    v.x = tf32r(v.x); v.y = tf32r(v.y); v.z = tf32r(v.z); v.w = tf32r(v.w);
    reinterpret_cast<float4*>(dst)[i] = v;
}

__global__ void rmsnorm_kernel(const float* __restrict__ x, const float* __restrict__ w,
                               float* __restrict__ out, float* __restrict__ outR) {
    int row = blockIdx.x;
    const float* xr = x + (size_t)row * D_;
    float ss = 0.f;
    for (int i = threadIdx.x; i < D_; i += 256) { float v = xr[i]; ss += v * v; }
    __shared__ float red[256];
    red[threadIdx.x] = ss; __syncthreads();
    for (int s = 128; s > 0; s >>= 1) {
        if (threadIdx.x < s) red[threadIdx.x] += red[threadIdx.x + s];
        __syncthreads();
    }
    float inv = rsqrtf(red[0] / (float)D_ + EPS_);
    float* orow = out + (size_t)row * D_;
    float* rrow = outR ? outR + (size_t)row * D_ : nullptr;
    for (int i = threadIdx.x; i < D_; i += 256) {
        float v = xr[i] * inv * w[i];
        orow[i] = v;
        if (rrow) rrow[i] = tf32r(v);
    }
}

// ---------------- small SGEMM: 64x64 tile, expert-batched (LoRA path) ----------------
__global__ void gemm_small(const float* __restrict__ A, const float* __restrict__ Bw,
                           float* __restrict__ C, int N, int K,
                           const int* __restrict__ tokIdx, int gatherA,
                           const float* __restrict__ Res, size_t resStride,
                           float alpha, int accumulate,
                           const int* __restrict__ Mcnt, const int* __restrict__ Moff,
                           size_t strideB, const float* __restrict__ siluMul) {
    int z = blockIdx.z;
    int M = Mcnt[z];
    int bm = blockIdx.y * 64;
    if (bm >= M) return;
    int bn = blockIdx.x * 64;
    int base = Moff[z];
    const int* tok = tokIdx + z * T_;
    const float* Bz = Bw + (size_t)z * strideB;

    __shared__ float As[16][64];
    __shared__ float Bs[16][64];
    int tid = threadIdx.x;
    int tx = tid & 15, ty = tid >> 4;
    float acc[4][4];
#pragma unroll
    for (int i = 0; i < 4; i++)
#pragma unroll
        for (int j = 0; j < 4; j++) acc[i][j] = 0.f;

    for (int k0 = 0; k0 < K; k0 += 16) {
#pragma unroll
        for (int l = 0; l < 4; l++) {
            int ii = l * 256 + tid;
            int m = ii >> 4, kk = ii & 15;
            int row = bm + m;
            float a = 0.f;
            if (row < M) {
                int ar = gatherA ? tok[row] : base + row;
                a = A[(size_t)ar * K + k0 + kk];
            }
            As[kk][m] = a;
            float bv = 0.f;
            if (bn + m < N) bv = Bz[(size_t)(bn + m) * K + k0 + kk];
            Bs[kk][m] = bv;
        }
        __syncthreads();
#pragma unroll
        for (int kk = 0; kk < 16; kk++) {
            float4 av = *reinterpret_cast<const float4*>(&As[kk][ty * 4]);
            float4 bv = *reinterpret_cast<const float4*>(&Bs[kk][tx * 4]);
            float a0 = av.x, a1 = av.y, a2 = av.z, a3 = av.w;
            float b0 = bv.x, b1 = bv.y, b2 = bv.z, b3 = bv.w;
            acc[0][0] += a0*b0; acc[0][1] += a0*b1; acc[0][2] += a0*b2; acc[0][3] += a0*b3;
            acc[1][0] += a1*b0; acc[1][1] += a1*b1; acc[1][2] += a1*b2; acc[1][3] += a1*b3;
            acc[2][0] += a2*b0; acc[2][1] += a2*b1; acc[2][2] += a2*b2; acc[2][3] += a2*b3;
            acc[3][0] += a3*b0; acc[3][1] += a3*b1; acc[3][2] += a3*b2; acc[3][3] += a3*b3;
        }
        __syncthreads();
    }
#pragma unroll
    for (int i = 0; i < 4; i++) {
        int row = bm + ty * 4 + i;
        if (row >= M) continue;
        size_t crow = (size_t)(base + row) * N;
#pragma unroll
        for (int j = 0; j < 4; j++) {
            int col = bn + tx * 4 + j;
            if (col >= N) continue;
            float val = alpha * acc[i][j];
            if (Res) val += Res[(size_t)tok[row] * resStride + col];
            if (siluMul) {
                float s = val / (1.f + expf(-val));
                val = tf32r(s * siluMul[crow + col]);
            }
            if (accumulate) C[crow + col] += val;
            else            C[crow + col] = val;
        }
    }
}

// ---------------- flash attention, tf32 mma, 64-query tiles ----------------
#define ATTN_SMEM (21696 * 4)
__global__ __launch_bounds__(256, 1)
void attn_mma(const float* __restrict__ qkv, const float* __restrict__ mask,
              float* __restrict__ o) {
    extern __shared__ float sm[];
    float* Qs    = sm;            // [64][132]
    float* KV    = sm + 8448;     // K [64][132] then V^T [128][68]
    float* Sc    = sm + 17152;    // [64][68]
    float* mrow  = sm + 21504;
    float* lrow  = sm + 21568;
    float* facrw = sm + 21632;

    int qt = blockIdx.x, h = blockIdx.y, b = blockIdx.z;
    int hkv = h >> 1;
    int tid = threadIdx.x, wid = tid >> 5, lid = tid & 31;
    int q0 = qt * 64;
    int wm = wid >> 1, wn = wid & 1;     // 4x2 warps
    int m0 = wm * 16;
    int n0s = wn * 32, n0p = wn * 64;
    int lr = lid >> 2, lc = lid & 3;
    int rg = tid >> 2, cg = tid & 3;

    for (int i = tid; i < 64 * 128; i += 256) {
        int r = i >> 7, d = i & 127;
        Qs[r * 132 + d] = tf32r(qkv[(size_t)(b * S_ + q0 + r) * NQKV_ + h * HD_ + d]);
    }
    if (tid < 64) { mrow[tid] = -3e38f; lrow[tid] = 0.f; }
    float oa[8][4];
#pragma unroll
    for (int i = 0; i < 8; i++)
#pragma unroll
        for (int q = 0; q < 4; q++) oa[i][q] = 0.f;
    __syncthreads();

    const float sca = 0.08838834764831845f;
    for (int kt = 0; kt < S_; kt += 64) {
        for (int i = tid; i < 64 * 128; i += 256) {
            int r = i >> 7, d = i & 127;
            KV[r * 132 + d] = tf32r(qkv[(size_t)(b * S_ + kt + r) * NQKV_ + 2048 + hkv * HD_ + d]);
        }
        __syncthreads();
        float sc_[4][4];
#pragma unroll
        for (int i = 0; i < 4; i++)
#pragma unroll
            for (int q = 0; q < 4; q++) sc_[i][q] = 0.f;
#pragma unroll
        for (int ks = 0; ks < 16; ks++) {
            int kk = ks * 8;
            float a0 = Qs[(m0 + lr) * 132 + kk + lc];
            float a1 = Qs[(m0 + lr + 8) * 132 + kk + lc];
            float a2 = Qs[(m0 + lr) * 132 + kk + lc + 4];
            float a3 = Qs[(m0 + lr + 8) * 132 + kk + lc + 4];
#pragma unroll
            for (int nt = 0; nt < 4; nt++) {
                float b0 = KV[(n0s + nt * 8 + lr) * 132 + kk + lc];
                float b1 = KV[(n0s + nt * 8 + lr) * 132 + kk + lc + 4];
                mma_tf32(sc_[nt][0], sc_[nt][1], sc_[nt][2], sc_[nt][3],
                         a0, a1, a2, a3, b0, b1);
            }
        }
#pragma unroll
        for (int nt = 0; nt < 4; nt++) {
#pragma unroll
            for (int hh = 0; hh < 2; hh++) {
                int row = m0 + lr + hh * 8;
                int col = n0s + nt * 8 + lc * 2;
                Sc[row * 68 + col]     = sc_[nt][hh * 2]     * sca + mask[(q0 + row) * S_ + kt + col];
                Sc[row * 68 + col + 1] = sc_[nt][hh * 2 + 1] * sca + mask[(q0 + row) * S_ + kt + col + 1];
            }
        }
        __syncthreads();
        for (int i = tid; i < 64 * 128; i += 256) {
            int r = i >> 7, d = i & 127;
            KV[d * 68 + r] = tf32r(qkv[(size_t)(b * S_ + kt + r) * NQKV_ + 3072 + hkv * HD_ + d]);
        }
        float tm = -3e38f;
#pragma unroll
        for (int ii = 0; ii < 16; ii++) tm = fmaxf(tm, Sc[rg * 68 + cg + 4 * ii]);
        tm = fmaxf(tm, __shfl_xor_sync(0xffffffffu, tm, 1));
        tm = fmaxf(tm, __shfl_xor_sync(0xffffffffu, tm, 2));
        float mprev = mrow[rg];
        float mnew = fmaxf(mprev, tm);
        float fac = expf(mprev - mnew);
        float ls = 0.f;
#pragma unroll
        for (int ii = 0; ii < 16; ii++) {
            float p = expf(Sc[rg * 68 + cg + 4 * ii] - mnew);
            Sc[rg * 68 + cg + 4 * ii] = tf32r(p);
            ls += p;
        }
        ls += __shfl_xor_sync(0xffffffffu, ls, 1);
        ls += __shfl_xor_sync(0xffffffffu, ls, 2);
        if (cg == 0) { mrow[rg] = mnew; lrow[rg] = lrow[rg] * fac + ls; facrw[rg] = fac; }
        __syncthreads();
        float f0 = facrw[m0 + lr], f1 = facrw[m0 + lr + 8];
#pragma unroll
        for (int nt = 0; nt < 8; nt++) {
            oa[nt][0] *= f0; oa[nt][1] *= f0;
            oa[nt][2] *= f1; oa[nt][3] *= f1;
        }
#pragma unroll
        for (int ks = 0; ks < 8; ks++) {
            int kk = ks * 8;
            float a0 = Sc[(m0 + lr) * 68 + kk + lc];
            float a1 = Sc[(m0 + lr + 8) * 68 + kk + lc];
            float a2 = Sc[(m0 + lr) * 68 + kk + lc + 4];
            float a3 = Sc[(m0 + lr + 8) * 68 + kk + lc + 4];
#pragma unroll
            for (int nt = 0; nt < 8; nt++) {
                float b0 = KV[(n0p + nt * 8 + lr) * 68 + kk + lc];
                float b1 = KV[(n0p + nt * 8 + lr) * 68 + kk + lc + 4];
                mma_tf32(oa[nt][0], oa[nt][1], oa[nt][2], oa[nt][3],
                         a0, a1, a2, a3, b0, b1);
            }
        }
        __syncthreads();
    }
    float i0 = 1.f / lrow[m0 + lr];
    float i1 = 1.f / lrow[m0 + lr + 8];
#pragma unroll
    for (int nt = 0; nt < 8; nt++) {
        int row0 = m0 + lr, row1 = row0 + 8;
        int col = n0p + nt * 8 + lc * 2;
        float* p0 = o + ((size_t)(b * S_ + q0 + row0) * H_ + h) * HD_ + col;
        float* p1 = o + ((size_t)(b * S_ + q0 + row1) * H_ + h) * HD_ + col;
        p0[0] = tf32r(oa[nt][0] * i0); p0[1] = tf32r(oa[nt][1] * i0);
        p1[0] = tf32r(oa[nt][2] * i1); p1[1] = tf32r(oa[nt][3] * i1);
    }
}

// ---------------- router ----------------
__global__ void router_logits_kernel(const float* __restrict__ sn, const float* __restrict__ gw,
                                     float* __restrict__ logits) {
    int t = blockIdx.x;
    int wid = threadIdx.x >> 5, lid = threadIdx.x & 31;
    const float* x = sn + (size_t)t * D_;
    const float* g = gw + (size_t)wid * D_;
    float s = 0.f;
    for (int i = lid * 4; i < D_; i += 128) {
        float4 xv = *reinterpret_cast<const float4*>(x + i);
        float4 gv = *reinterpret_cast<const float4*>(g + i);
        s += xv.x * gv.x + xv.y * gv.y + xv.z * gv.z + xv.w * gv.w;
    }
#pragma unroll
    for (int o = 16; o > 0; o >>= 1) s += __shfl_xor_sync(0xffffffffu, s, o);
    if (lid == 0) logits[(size_t)t * E_ + wid] = s;
}

__global__ void col_softmax_stats(const float* __restrict__ logits, float* __restrict__ zmax,
                                  float* __restrict__ zsum) {
    int be = blockIdx.x;
    int b = be / E_, e = be % E_;
    __shared__ float red[256];
    float mx = -3e38f;
    for (int s = threadIdx.x; s < S_; s += 256)
        mx = fmaxf(mx, logits[((size_t)b * S_ + s) * E_ + e]);
    red[threadIdx.x] = mx; __syncthreads();
    for (int s = 128; s > 0; s >>= 1) {
        if (threadIdx.x < s) red[threadIdx.x] = fmaxf(red[threadIdx.x], red[threadIdx.x + s]);
        __syncthreads();
    }
    mx = red[0]; __syncthreads();
    float sum = 0.f;
    for (int s = threadIdx.x; s < S_; s += 256)
        sum += expf(logits[((size_t)b * S_ + s) * E_ + e] - mx);
    red[threadIdx.x] = sum; __syncthreads();
    for (int s = 128; s > 0; s >>= 1) {
        if (threadIdx.x < s) red[threadIdx.x] += red[threadIdx.x + s];
        __syncthreads();
    }
    if (threadIdx.x == 0) { zmax[be] = mx; zsum[be] = red[0]; }
}

__global__ void top2_kernel(const float* __restrict__ logits, const float* __restrict__ zmax,
                            const float* __restrict__ zsum, int* __restrict__ cnt,
                            int* __restrict__ tok, int* __restrict__ sel,
                            int* __restrict__ pos, float* __restrict__ wgt) {
    int t = blockIdx.x * blockDim.x + threadIdx.x;
    if (t >= T_) return;
    int b = t / S_;
    float rw[E_];
#pragma unroll
    for (int e = 0; e < E_; e++)
        rw[e] = expf(logits[(size_t)t * E_ + e] - zmax[b * E_ + e]) / zsum[b * E_ + e];
    int e0 = 0; float v0 = rw[0];
#pragma unroll
    for (int e = 1; e < E_; e++) if (rw[e] > v0) { v0 = rw[e]; e0 = e; }
    int e1 = -1; float v1 = -3e38f;
#pragma unroll
    for (int e = 0; e < E_; e++) if (e != e0 && rw[e] > v1) { v1 = rw[e]; e1 = e; }
    float inv = 1.f / (v0 + v1);
    int p0 = atomicAdd(&cnt[e0], 1);
    tok[e0 * T_ + p0] = t;
    int p1 = atomicAdd(&cnt[e1], 1);
    tok[e1 * T_ + p1] = t;
    sel[2*t] = e0; pos[2*t] = p0; wgt[2*t] = v0 * inv;
    sel[2*t+1] = e1; pos[2*t+1] = p1; wgt[2*t+1] = v1 * inv;
}

__global__ void offsets_kernel(const int* __restrict__ cnt, int* __restrict__ off) {
    if (threadIdx.x == 0) {
        int s = 0;
        for (int e = 0; e < E_; e++) { off[e] = s; s += cnt[e]; }
    }
}

__global__ void gather_kernel(const float* __restrict__ expout, const int* __restrict__ off,
                              const int* __restrict__ sel, const int* __restrict__ pos,
                              const float* __restrict__ wgt, float* __restrict__ out) {
    int t = blockIdx.x;
    int e0 = sel[2*t], e1 = sel[2*t+1];
    size_t r0 = (size_t)(off[e0] + pos[2*t]) * D_;
    size_t r1 = (size_t)(off[e1] + pos[2*t+1]) * D_;
    float w0 = wgt[2*t], w1 = wgt[2*t+1];
    for (int i = threadIdx.x; i < D_; i += 256)
        out[(size_t)t * D_ + i] += w0 * expout[r0 + i] + w1 * expout[r1 + i];
}

// ---------------- host launch ----------------
extern "C" void kernel_launch(void* const* d_in, const int* in_sizes, int n_in,
                              void* d_out, int out_size) {
    const float* data   = (const float*)d_in[0];
    const float* mask   = (const float*)d_in[1];
    const float* ropec  = (const float*)d_in[2];
    const float* ropes  = (const float*)d_in[3];
    const float* anw    = (const float*)d_in[4];
    const float* fnw    = (const float*)d_in[5];
    const float* wq     = (const float*)d_in[6];
    const float* wk     = (const float*)d_in[7];
    const float* wv     = (const float*)d_in[8];
    const float* wo     = (const float*)d_in[9];
    const float* gate_w = (const float*)d_in[10];
    const float* w1     = (const float*)d_in[11];
    const float* w2     = (const float*)d_in[12];
    const float* w3     = (const float*)d_in[13];
    const float* w1_a   = (const float*)d_in[14];
    const float* w1_b   = (const float*)d_in[15];
    const float* w3_a   = (const float*)d_in[16];
    const float* w3_b   = (const float*)d_in[17];
    const float* w2_a   = (const float*)d_in[18];
    const float* w2_b   = (const float*)d_in[19];
    float* out = (float*)d_out;

    float *xnr, *sn, *snr, *wqkv, *qkv, *attn, *woc, *w13c, *w2c, *c13;
    float *h1, *h3, *u1, *u3, *u2;
    float *logits, *zmax, *zsum, *wgt, *expout;
    int *cnt, *off, *tok, *sel, *pos;
    cudaGetSymbolAddress((void**)&xnr, g_xnr);
    cudaGetSymbolAddress((void**)&sn, g_sn);
    cudaGetSymbolAddress((void**)&snr, g_snr);
    cudaGetSymbolAddress((void**)&wqkv, g_wqkv);
    cudaGetSymbolAddress((void**)&qkv, g_qkv);
    cudaGetSymbolAddress((void**)&attn, g_attn);
    cudaGetSymbolAddress((void**)&woc, g_woc);
    cudaGetSymbolAddress((void**)&w13c, g_w13c);
    cudaGetSymbolAddress((void**)&w2c, g_w2c);
    cudaGetSymbolAddress((void**)&c13, g_c13);
    cudaGetSymbolAddress((void**)&h1, g_h1);
    cudaGetSymbolAddress((void**)&h3, g_h3);
    cudaGetSymbolAddress((void**)&u1, g_u1);
    cudaGetSymbolAddress((void**)&u3, g_u3);
    cudaGetSymbolAddress((void**)&u2, g_u2);
    cudaGetSymbolAddress((void**)&expout, g_expout);
    cudaGetSymbolAddress((void**)&logits, g_logits);
    cudaGetSymbolAddress((void**)&zmax, g_zmax);
    cudaGetSymbolAddress((void**)&zsum, g_zsum);
    cudaGetSymbolAddress((void**)&cnt, g_cnt);
    cudaGetSymbolAddress((void**)&off, g_off);
    cudaGetSymbolAddress((void**)&tok, g_tok);
    cudaGetSymbolAddress((void**)&sel, g_sel);
    cudaGetSymbolAddress((void**)&pos, g_pos);
    cudaGetSymbolAddress((void**)&wgt, g_wgt);

    cudaFuncSetAttribute(attn_mma, cudaFuncAttributeMaxDynamicSharedMemorySize, ATTN_SMEM);
    cudaFuncSetAttribute(gemm_mma, cudaFuncAttributeMaxDynamicSharedMemorySize, GMS);

    reset_kernel<<<1, 32>>>(cnt);
    concat_w_kernel<<<(NQKV_*D_/4 + 255)/256, 256>>>(wq, wk, wv, wqkv);
    cvt_kernel<<<((D_*D_/4) + 255)/256, 256>>>(wo, woc, (size_t)D_*D_/4);
    cvt_kernel<<<((F_*D_/4) + 255)/256, 256>>>(w1, w13c, (size_t)F_*D_/4);
    cvt_kernel<<<((F_*D_/4) + 255)/256, 256>>>(w3, w13c + (size_t)F_*D_, (size_t)F_*D_/4);
    cvt_kernel<<<((D_*F_/4) + 255)/256, 256>>>(w2, w2c, (size_t)D_*F_/4);

    rmsnorm_kernel<<<T_, 256>>>(data, anw, xnr, xnr);

    // Fused QKV projection; rope on cols < 3072
    gemm_mma<<<dim3(NQKV_/128, T_/128, 1), 128, GMS>>>(xnr, wqkv, qkv, T_, NQKV_, D_,
        nullptr, nullptr, nullptr, ropec, ropes, 3072);

    attn_mma<<<dim3(S_/64, H_, B_), 256, ATTN_SMEM>>>(qkv, mask, attn);

    // out = data + attn @ wo^T
    gemm_mma<<<dim3(D_/128, T_/128, 1), 128, GMS>>>(attn, woc, out, T_, D_, D_,
        data, nullptr, nullptr, nullptr, nullptr, 0);

    rmsnorm_kernel<<<T_, 256>>>(out, fnw, sn, snr);

    router_logits_kernel<<<T_, 256>>>(sn, gate_w, logits);
    col_softmax_stats<<<B_*E_, 256>>>(logits, zmax, zsum);
    top2_kernel<<<T_/256, 256>>>(logits, zmax, zsum, cnt, tok, sel, pos, wgt);
    offsets_kernel<<<1, 32>>>(cnt, off);

    // merged dense c1|c3: one GEMM, N=11264
    gemm_mma<<<dim3(2*F_/128, T_/128, 1), 128, GMS>>>(snr, w13c, c13, T_, 2*F_, D_,
        nullptr, nullptr, nullptr, nullptr, nullptr, 0);

    // ---- expert-batched LoRA path (z = expert) ----
    gemm_small<<<dim3(1, T_/64, E_), 256>>>(sn, w3_a, u3, R_, D_,
        tok, 1, nullptr, 0, 1.f, 0, cnt, off, (size_t)R_*D_, nullptr);
    gemm_small<<<dim3(F_/64, T_/64, E_), 256>>>(u3, w3_b, h3, F_, R_,
        tok, 0, c13 + F_, (size_t)(2*F_), SCALE_, 0, cnt, off, (size_t)F_*R_, nullptr);
    gemm_small<<<dim3(1, T_/64, E_), 256>>>(sn, w1_a, u1, R_, D_,
        tok, 1, nullptr, 0, 1.f, 0, cnt, off, (size_t)R_*D_, nullptr);
    gemm_small<<<dim3(F_/64, T_/64, E_), 256>>>(u1, w1_b, h1, F_, R_,
        tok, 0, c13, (size_t)(2*F_), SCALE_, 0, cnt, off, (size_t)F_*R_, h3);
    // u2 = sr @ w2_a^T
    gemm_small<<<dim3(1, T_/64, E_), 256>>>(h1, w2_a, u2, R_, F_,
        tok, 0, nullptr, 0, 1.f, 0, cnt, off, (size_t)R_*F_, nullptr);
    // expout = sr @ w2^T
    gemm_mma<<<dim3(D_/128, T_/128, E_), 128, GMS>>>(h1, w2c, expout, T_, D_, F_,
        nullptr, cnt, off, nullptr, nullptr, 0);
    // expout += SCALE * u2 @ w2_b^T
    gemm_small<<<dim3(D_/64, T_/64, E_), 256>>>(u2, w2_b, expout, D_, R_,
        tok, 0, nullptr, 0, SCALE_, 1, cnt, off, (size_t)D_*R_, nullptr);

    // out[t] += w0*expout[slot0] + w1*expout[slot1]
    gather_kernel<<<T_, 256>>>(expout, off, sel, pos, wgt, out);
}

// round 15
// speedup vs baseline: 1.3541x; 1.0956x over previous
#include <cuda_runtime.h>
#include <math.h>
#include <stdint.h>

#define B_ 2
#define S_ 1024
#define D_ 2048
#define H_ 16
#define HKV_ 8
#define HD_ 128
#define F_ 5632
#define E_ 8
#define R_ 16
#define T_ (B_*S_)
#define EPS_ 1e-5f
#define SCALE_ 2.0f
#define NQKV_ 4096

// ---------------- device scratch (static, allocation-free) ----------------
__device__ float g_xnr[T_*D_];
__device__ float g_sn[T_*D_];
__device__ float g_snr[T_*D_];
__device__ float g_wqkv[NQKV_*D_];
__device__ float g_qkv[(size_t)T_*NQKV_];
__device__ float g_attn[T_*D_];
__device__ float g_woc[D_*D_];
__device__ float g_w13c[2*F_*D_];
__device__ float g_w2c[(size_t)D_*F_];
__device__ float g_w13a[E_*2*R_*D_];
__device__ float g_c13[(size_t)T_*2*F_];
__device__ float g_h1[2*T_*F_];
__device__ float g_expout[2*T_*D_];
__device__ float g_u13[2*T_*2*R_];
__device__ float g_u2[2*T_*R_];
__device__ float g_logits[T_*E_];
__device__ float g_zmax[B_*E_];
__device__ float g_zsum[B_*E_];
__device__ int   g_cnt[E_];
__device__ int   g_off[E_];
__device__ int   g_tok[E_*T_];
__device__ int   g_sel[2*T_];
__device__ int   g_pos[2*T_];
__device__ float g_wgt[2*T_];

// ---------------- helpers ----------------
__device__ __forceinline__ float tf32r(float x) {
    uint32_t y;
    asm("cvt.rna.tf32.f32 %0, %1;" : "=r"(y) : "f"(x));
    return __uint_as_float(y);
}
__device__ __forceinline__ uint32_t smem_addr(const void* p) {
    uint32_t a;
    asm("{ .reg .u64 t; cvta.to.shared.u64 t, %1; cvt.u32.u64 %0, t; }" : "=r"(a) : "l"(p));
    return a;
}
__device__ __forceinline__ void mma_tf32(float& d0, float& d1, float& d2, float& d3,
                                         float a0, float a1, float a2, float a3,
                                         float b0, float b1) {
    asm volatile(
        "mma.sync.aligned.m16n8k8.row.col.f32.tf32.tf32.f32 "
        "{%0,%1,%2,%3}, {%4,%5,%6,%7}, {%8,%9}, {%0,%1,%2,%3};"
        : "+f"(d0), "+f"(d1), "+f"(d2), "+f"(d3)
        : "r"(__float_as_uint(a0)), "r"(__float_as_uint(a1)),
          "r"(__float_as_uint(a2)), "r"(__float_as_uint(a3)),
          "r"(__float_as_uint(b0)), "r"(__float_as_uint(b1)));
}

// ---------------- tf32 mma.sync GEMM: 128x128 CTA (128 thr, 2x2 warps of 64x64), 4-stage cp.async ----------------
#define GMS (4 * 5120 * 4)
__global__ __launch_bounds__(128, 2)
void gemm_mma(const float* __restrict__ A, const float* __restrict__ Bw,
              float* __restrict__ C, int M, int N, int K,
              const float* __restrict__ Res,
              const int* __restrict__ Mcnt, const int* __restrict__ Moff,
              const float* __restrict__ ropec, const float* __restrict__ ropes,
              int ropeN) {
    extern __shared__ float smdyn[];

    int z = blockIdx.z;
    if (Mcnt) M = Mcnt[z];
    int bm = blockIdx.y * 128;
    if (bm >= M) return;
    int bn = blockIdx.x * 128;
    int base = Moff ? Moff[z] : 0;

    int tid = threadIdx.x, wid = tid >> 5, lid = tid & 31;
    int wm = wid >> 1, wn = wid & 1;
    int m0 = wm * 64, n0 = wn * 64;
    int lr = lid >> 2, lc = lid & 3;

    float acc[4][8][4];
#pragma unroll
    for (int i = 0; i < 4; i++)
#pragma unroll
        for (int j = 0; j < 8; j++)
#pragma unroll
            for (int q = 0; q < 4; q++) acc[i][j][q] = 0.f;

    int grA = tid >> 2;
    int gc  = (tid & 3) * 4;

    uint32_t sbase = smem_addr(smdyn);

#define LOADT(st, k0) do {                                                      \
        _Pragma("unroll")                                                       \
        for (int it = 0; it < 4; it++) {                                        \
            int gr = it * 32 + grA;                                             \
            int rowA = bm + gr;                                                 \
            int sz = (rowA < M) ? 16 : 0;                                       \
            int rA = (rowA < M) ? rowA : (M - 1);                               \
            const float* sa = A + (size_t)(base + rA) * K + (k0) + gc;          \
            uint32_t da = sbase + (uint32_t)(((st) * 5120 + gr * 20 + gc) * 4); \
            asm volatile("cp.async.cg.shared.global [%0], [%1], 16, %2;"        \
                         :: "r"(da), "l"(sa), "r"(sz));                         \
            const float* sb = Bw + (size_t)(bn + gr) * K + (k0) + gc;           \
            uint32_t db = da + 2560 * 4;                                        \
            asm volatile("cp.async.cg.shared.global [%0], [%1], 16;"            \
                         :: "r"(db), "l"(sb));                                  \
        }                                                                       \
    } while (0)

#define COMPUTE(st) do {                                                        \
        const float* Asb = smdyn + (st) * 5120;                                 \
        const float* Bsb = Asb + 2560;                                          \
        _Pragma("unroll")                                                       \
        for (int ks = 0; ks < 2; ks++) {                                        \
            int kk = ks * 8;                                                    \
            float a[4][4], b[8][2];                                             \
            _Pragma("unroll")                                                   \
            for (int mt = 0; mt < 4; mt++) {                                    \
                a[mt][0] = Asb[(m0 + mt*16 + lr) * 20 + kk + lc];               \
                a[mt][1] = Asb[(m0 + mt*16 + lr + 8) * 20 + kk + lc];           \
                a[mt][2] = Asb[(m0 + mt*16 + lr) * 20 + kk + lc + 4];           \
                a[mt][3] = Asb[(m0 + mt*16 + lr + 8) * 20 + kk + lc + 4];       \
            }                                                                   \
            _Pragma("unroll")                                                   \
            for (int nt = 0; nt < 8; nt++) {                                    \
                b[nt][0] = Bsb[(n0 + nt*8 + lr) * 20 + kk + lc];                \
                b[nt][1] = Bsb[(n0 + nt*8 + lr) * 20 + kk + lc + 4];            \
            }                                                                   \
            _Pragma("unroll")                                                   \
            for (int mt = 0; mt < 4; mt++)                                      \
                _Pragma("unroll")                                               \
                for (int nt = 0; nt < 8; nt++)                                  \
                    mma_tf32(acc[mt][nt][0], acc[mt][nt][1],                    \
                             acc[mt][nt][2], acc[mt][nt][3],                    \
                             a[mt][0], a[mt][1], a[mt][2], a[mt][3],            \
                             b[nt][0], b[nt][1]);                               \
        }                                                                       \
    } while (0)

    int nk = K / 16;
#pragma unroll
    for (int s = 0; s < 3; s++) {
        if (s < nk) LOADT(s, s * 16);
        asm volatile("cp.async.commit_group;");
    }
    for (int t = 0; t < nk; t++) {
        asm volatile("cp.async.wait_group 2;");
        __syncthreads();
        if (t + 3 < nk) LOADT((t + 3) & 3, (t + 3) * 16);
        asm volatile("cp.async.commit_group;");
        COMPUTE(t & 3);
    }
#undef LOADT
#undef COMPUTE

#pragma unroll
    for (int mt = 0; mt < 4; mt++) {
#pragma unroll
        for (int nt = 0; nt < 8; nt++) {
            int row = bm + m0 + mt * 16 + lr;
            int col = bn + n0 + nt * 8 + lc * 2;
#pragma unroll
            for (int hh = 0; hh < 2; hh++) {
                int r = row + hh * 8;
                if (r >= M) continue;
                float2 v = make_float2(acc[mt][nt][hh * 2], acc[mt][nt][hh * 2 + 1]);
                if (Res) {
                    const float2 rv = *reinterpret_cast<const float2*>(
                        Res + (size_t)(base + r) * N + col);
                    v.x += rv.x; v.y += rv.y;
                }
                if (ropec && col < ropeN) {
                    int p = (col & 127) >> 1;
                    int sp = (base + r) & (S_ - 1);
                    float cc = ropec[sp * 64 + p];
                    float ss = ropes[sp * 64 + p];
                    float o1 = v.x * cc - v.y * ss;
                    float o2 = v.x * ss + v.y * cc;
                    v.x = o1; v.y = o2;
                }
                *reinterpret_cast<float2*>(C + (size_t)(base + r) * N + col) = v;
            }
        }
    }
}

// ---------------- small kernels ----------------
__global__ void reset_kernel(int* cnt) {
    if (threadIdx.x < E_) cnt[threadIdx.x] = 0;
}

__global__ void concat_w_kernel(const float* __restrict__ wq, const float* __restrict__ wk,
                                const float* __restrict__ wv, float* __restrict__ wqkv) {
    size_t i = ((size_t)blockIdx.x * blockDim.x + threadIdx.x) * 4;
    size_t tot = (size_t)NQKV_ * D_;
    if (i >= tot) return;
    size_t row = i / D_;
    const float* src;
    size_t srow;
    if (row < 2048)      { src = wq; srow = row; }
    else if (row < 3072) { src = wk; srow = row - 2048; }
    else                 { src = wv; srow = row - 3072; }
    float4 v = *reinterpret_cast<const float4*>(src + srow * D_ + (i % D_));
    v.x = tf32r(v.x); v.y = tf32r(v.y); v.z = tf32r(v.z); v.w = tf32r(v.w);
    *reinterpret_cast<float4*>(wqkv + i) = v;
}

// per expert: rows 0..R-1 = w1_a[e], rows R..2R-1 = w3_a[e] (no rounding: SIMT path)
__global__ void concat_a_kernel(const float* __restrict__ w1a, const float* __restrict__ w3a,
                                float* __restrict__ w13a) {
    size_t idx = ((size_t)blockIdx.x * blockDim.x + threadIdx.x) * 4;
    size_t tot = (size_t)E_ * 2 * R_ * D_;
    if (idx >= tot) return;
    size_t e = idx / (2 * R_ * D_);
    size_t rem = idx % (2 * R_ * D_);
    size_t row = rem / D_;
    size_t cc = rem % D_;
    const float* src = (row < R_) ? (w1a + ((size_t)e * R_ + row) * D_ + cc)
                                  : (w3a + ((size_t)e * R_ + row - R_) * D_ + cc);
    *reinterpret_cast<float4*>(w13a + idx) = *reinterpret_cast<const float4*>(src);
}

__global__ void cvt_kernel(const float* __restrict__ src, float* __restrict__ dst, size_t n4) {
    size_t i = (size_t)blockIdx.x * blockDim.x + threadIdx.x;
    if (i >= n4) return;
    float4 v = reinterpret_cast<const float4*>(src)[i];
    v.x = tf32r(v.x); v.y = tf32r(v.y); v.z = tf32r(v.z); v.w = tf32r(v.w);
    reinterpret_cast<float4*>(dst)[i] = v;
}

__global__ void rmsnorm_kernel(const float* __restrict__ x, const float* __restrict__ w,
                               float* __restrict__ out, float* __restrict__ outR) {
    int row = blockIdx.x;
    const float* xr = x + (size_t)row * D_;
    float ss = 0.f;
    for (int i = threadIdx.x; i < D_; i += 256) { float v = xr[i]; ss += v * v; }
    __shared__ float red[256];
    red[threadIdx.x] = ss; __syncthreads();
    for (int s = 128; s > 0; s >>= 1) {
        if (threadIdx.x < s) red[threadIdx.x] += red[threadIdx.x + s];
        __syncthreads();
    }
    float inv = rsqrtf(red[0] / (float)D_ + EPS_);
    float* orow = out + (size_t)row * D_;
    float* rrow = outR ? outR + (size_t)row * D_ : nullptr;
    for (int i = threadIdx.x; i < D_; i += 256) {
        float v = xr[i] * inv * w[i];
        orow[i] = v;
        if (rrow) rrow[i] = tf32r(v);
    }
}

// ---------------- small SGEMM: 64x64 tile, expert-batched (LoRA u-path) ----------------
__global__ void gemm_small(const float* __restrict__ A, const float* __restrict__ Bw,
                           float* __restrict__ C, int N, int K,
                           const int* __restrict__ tokIdx, int gatherA,
                           float alpha, int accumulate,
                           const int* __restrict__ Mcnt, const int* __restrict__ Moff,
                           size_t strideB) {
    int z = blockIdx.z;
    int M = Mcnt[z];
    int bm = blockIdx.y * 64;
    if (bm >= M) return;
    int bn = blockIdx.x * 64;
    int base = Moff[z];
    const int* tok = tokIdx + z * T_;
    const float* Bz = Bw + (size_t)z * strideB;

    __shared__ float As[16][64];
    __shared__ float Bs[16][64];
    int tid = threadIdx.x;
    int tx = tid & 15, ty = tid >> 4;
    float acc[4][4];
#pragma unroll
    for (int i = 0; i < 4; i++)
#pragma unroll
        for (int j = 0; j < 4; j++) acc[i][j] = 0.f;

    for (int k0 = 0; k0 < K; k0 += 16) {
#pragma unroll
        for (int l = 0; l < 4; l++) {
            int ii = l * 256 + tid;
            int m = ii >> 4, kk = ii & 15;
            int row = bm + m;
            float a = 0.f;
            if (row < M) {
                int ar = gatherA ? tok[row] : base + row;
                a = A[(size_t)ar * K + k0 + kk];
            }
            As[kk][m] = a;
            float bv = 0.f;
            if (bn + m < N) bv = Bz[(size_t)(bn + m) * K + k0 + kk];
            Bs[kk][m] = bv;
        }
        __syncthreads();
#pragma unroll
        for (int kk = 0; kk < 16; kk++) {
            float4 av = *reinterpret_cast<const float4*>(&As[kk][ty * 4]);
            float4 bv = *reinterpret_cast<const float4*>(&Bs[kk][tx * 4]);
            float a0 = av.x, a1 = av.y, a2 = av.z, a3 = av.w;
            float b0 = bv.x, b1 = bv.y, b2 = bv.z, b3 = bv.w;
            acc[0][0] += a0*b0; acc[0][1] += a0*b1; acc[0][2] += a0*b2; acc[0][3] += a0*b3;
            acc[1][0] += a1*b0; acc[1][1] += a1*b1; acc[1][2] += a1*b2; acc[1][3] += a1*b3;
            acc[2][0] += a2*b0; acc[2][1] += a2*b1; acc[2][2] += a2*b2; acc[2][3] += a2*b3;
            acc[3][0] += a3*b0; acc[3][1] += a3*b1; acc[3][2] += a3*b2; acc[3][3] += a3*b3;
        }
        __syncthreads();
    }
#pragma unroll
    for (int i = 0; i < 4; i++) {
        int row = bm + ty * 4 + i;
        if (row >= M) continue;
        size_t crow = (size_t)(base + row) * N;
#pragma unroll
        for (int j = 0; j < 4; j++) {
            int col = bn + tx * 4 + j;
            if (col >= N) continue;
            float val = alpha * acc[i][j];
            if (accumulate) C[crow + col] += val;
            else            C[crow + col] = val;
        }
    }
}

// ---------------- fused LoRA h-kernel: sr = tf32r(silu(c1 + 2*u1@w1b^T) * (c3 + 2*u3@w3b^T)) ----------------
__global__ void lora_h_kernel(const float* __restrict__ u13,
                              const float* __restrict__ w1b, const float* __restrict__ w3b,
                              const float* __restrict__ c13, float* __restrict__ sr,
                              const int* __restrict__ tokIdx,
                              const int* __restrict__ Mcnt, const int* __restrict__ Moff) {
    int z = blockIdx.z;
    int M = Mcnt[z];
    int bm = blockIdx.y * 64;
    if (bm >= M) return;
    int bn = blockIdx.x * 64;
    int base = Moff[z];
    const int* tok = tokIdx + z * T_;
    const float* B1 = w1b + (size_t)z * F_ * R_;
    const float* B3 = w3b + (size_t)z * F_ * R_;

    __shared__ float Au[64][32];    // [row][k]: k<16 -> u1, k>=16 -> u3
    __shared__ float Bs1[16][64];
    __shared__ float Bs3[16][64];
    int tid = threadIdx.x;
    int tx = tid & 15, ty = tid >> 4;

    for (int i = tid; i < 64 * 32; i += 256) {
        int r = i >> 5, k = i & 31;
        float v = 0.f;
        if (bm + r < M) v = u13[(size_t)(base + bm + r) * 32 + k];
        Au[r][k] = v;
    }
    for (int i = tid; i < 64 * 16; i += 256) {
        int m = i >> 4, kk = i & 15;
        Bs1[kk][m] = B1[(size_t)(bn + m) * R_ + kk];
        Bs3[kk][m] = B3[(size_t)(bn + m) * R_ + kk];
    }
    __syncthreads();

    float acc1[4][4], acc3[4][4];
#pragma unroll
    for (int i = 0; i < 4; i++)
#pragma unroll
        for (int j = 0; j < 4; j++) { acc1[i][j] = 0.f; acc3[i][j] = 0.f; }

#pragma unroll
    for (int kk = 0; kk < 16; kk++) {
        float a1[4], a3[4];
#pragma unroll
        for (int i = 0; i < 4; i++) {
            a1[i] = Au[ty * 4 + i][kk];
            a3[i] = Au[ty * 4 + i][16 + kk];
        }
        float4 b1 = *reinterpret_cast<const float4*>(&Bs1[kk][tx * 4]);
        float4 b3 = *reinterpret_cast<const float4*>(&Bs3[kk][tx * 4]);
        float bb1[4] = {b1.x, b1.y, b1.z, b1.w};
        float bb3[4] = {b3.x, b3.y, b3.z, b3.w};
#pragma unroll
        for (int i = 0; i < 4; i++)
#pragma unroll
            for (int j = 0; j < 4; j++) {
                acc1[i][j] += a1[i] * bb1[j];
                acc3[i][j] += a3[i] * bb3[j];
            }
    }

#pragma unroll
    for (int i = 0; i < 4; i++) {
        int row = bm + ty * 4 + i;
        if (row >= M) continue;
        int t = tok[row];
        size_t crow = (size_t)(base + row) * F_;
#pragma unroll
        for (int j = 0; j < 4; j++) {
            int col = bn + tx * 4 + j;
            float v1 = SCALE_ * acc1[i][j] + c13[(size_t)t * (2 * F_) + col];
            float v3 = SCALE_ * acc3[i][j] + c13[(size_t)t * (2 * F_) + F_ + col];
            float s = v1 / (1.f + expf(-v1));
            sr[crow + col] = tf32r(s * v3);
        }
    }
}

// ---------------- LoRA w2_b epilogue: expout += SCALE * u2 @ w2_b^T ----------------
__global__ void lora_o_kernel(const float* __restrict__ u2, const float* __restrict__ w2b,
                              float* __restrict__ expout,
                              const int* __restrict__ Mcnt, const int* __restrict__ Moff) {
    int z = blockIdx.z;
    int M = Mcnt[z];
    int bm = blockIdx.y * 64;
    if (bm >= M) return;
    int bn = blockIdx.x * 64;
    int base = Moff[z];
    const float* Bz = w2b + (size_t)z * D_ * R_;

    __shared__ float Au[64][16];
    __shared__ float Bs[16][64];
    int tid = threadIdx.x;
    int tx = tid & 15, ty = tid >> 4;

    for (int i = tid; i < 64 * 16; i += 256) {
        int r = i >> 4, k = i & 15;
        float v = 0.f;
        if (bm + r < M) v = u2[(size_t)(base + bm + r) * R_ + k];
        Au[r][k] = v;
        int m = i >> 4, kk = i & 15;
        Bs[kk][m] = Bz[(size_t)(bn + m) * R_ + kk];
    }
    __syncthreads();

    float acc[4][4];
#pragma unroll
    for (int i = 0; i < 4; i++)
#pragma unroll
        for (int j = 0; j < 4; j++) acc[i][j] = 0.f;
#pragma unroll
    for (int kk = 0; kk < 16; kk++) {
        float a[4];
#pragma unroll
        for (int i = 0; i < 4; i++) a[i] = Au[ty * 4 + i][kk];
        float4 bv = *reinterpret_cast<const float4*>(&Bs[kk][tx * 4]);
        float bb[4] = {bv.x, bv.y, bv.z, bv.w};
#pragma unroll
        for (int i = 0; i < 4; i++)
#pragma unroll
            for (int j = 0; j < 4; j++) acc[i][j] += a[i] * bb[j];
    }
#pragma unroll
    for (int i = 0; i < 4; i++) {
        int row = bm + ty * 4 + i;
        if (row >= M) continue;
        size_t crow = (size_t)(base + row) * D_;
#pragma unroll
        for (int j = 0; j < 4; j++) {
            int col = bn + tx * 4 + j;
            expout[crow + col] += SCALE_ * acc[i][j];
        }
    }
}

// ---------------- flash attention, tf32 mma, 64-query tiles ----------------
#define ATTN_SMEM (21696 * 4)
__global__ __launch_bounds__(256, 1)
void attn_mma(const float* __restrict__ qkv, const float* __restrict__ mask,
              float* __restrict__ o) {
    extern __shared__ float sm[];
    float* Qs    = sm;
    float* KV    = sm + 8448;
    float* Sc    = sm + 17152;
    float* mrow  = sm + 21504;
    float* lrow  = sm + 21568;
    float* facrw = sm + 21632;

    int qt = blockIdx.x, h = blockIdx.y, b = blockIdx.z;
    int hkv = h >> 1;
    int tid = threadIdx.x, wid = tid >> 5, lid = tid & 31;
    int q0 = qt * 64;
    int wm = wid >> 1, wn = wid & 1;
    int m0 = wm * 16;
    int n0s = wn * 32, n0p = wn * 64;
    int lr = lid >> 2, lc = lid & 3;
    int rg = tid >> 2, cg = tid & 3;

    for (int i = tid; i < 64 * 128; i += 256) {
        int r = i >> 7, d = i & 127;
        Qs[r * 132 + d] = tf32r(qkv[(size_t)(b * S_ + q0 + r) * NQKV_ + h * HD_ + d]);
    }
    if (tid < 64) { mrow[tid] = -3e38f; lrow[tid] = 0.f; }
    float oa[8][4];
#pragma unroll
    for (int i = 0; i < 8; i++)
#pragma unroll
        for (int q = 0; q < 4; q++) oa[i][q] = 0.f;
    __syncthreads();

    const float sca = 0.08838834764831845f;
    for (int kt = 0; kt < S_; kt += 64) {
        for (int i = tid; i < 64 * 128; i += 256) {
            int r = i >> 7, d = i & 127;
            KV[r * 132 + d] = tf32r(qkv[(size_t)(b * S_ + kt + r) * NQKV_ + 2048 + hkv * HD_ + d]);
        }
        __syncthreads();
        float sc_[4][4];
#pragma unroll
        for (int i = 0; i < 4; i++)
#pragma unroll
            for (int q = 0; q < 4; q++) sc_[i][q] = 0.f;
#pragma unroll
        for (int ks = 0; ks < 16; ks++) {
            int kk = ks * 8;
            float a0 = Qs[(m0 + lr) * 132 + kk + lc];
            float a1 = Qs[(m0 + lr + 8) * 132 + kk + lc];
            float a2 = Qs[(m0 + lr) * 132 + kk + lc + 4];
            float a3 = Qs[(m0 + lr + 8) * 132 + kk + lc + 4];
#pragma unroll
            for (int nt = 0; nt < 4; nt++) {
                float b0 = KV[(n0s + nt * 8 + lr) * 132 + kk + lc];
                float b1 = KV[(n0s + nt * 8 + lr) * 132 + kk + lc + 4];
                mma_tf32(sc_[nt][0], sc_[nt][1], sc_[nt][2], sc_[nt][3],
                         a0, a1, a2, a3, b0, b1);
            }
        }
#pragma unroll
        for (int nt = 0; nt < 4; nt++) {
#pragma unroll
            for (int hh = 0; hh < 2; hh++) {
                int row = m0 + lr + hh * 8;
                int col = n0s + nt * 8 + lc * 2;
                Sc[row * 68 + col]     = sc_[nt][hh * 2]     * sca + mask[(q0 + row) * S_ + kt + col];
                Sc[row * 68 + col + 1] = sc_[nt][hh * 2 + 1] * sca + mask[(q0 + row) * S_ + kt + col + 1];
            }
        }
        __syncthreads();
        for (int i = tid; i < 64 * 128; i += 256) {
            int r = i >> 7, d = i & 127;
            KV[d * 68 + r] = tf32r(qkv[(size_t)(b * S_ + kt + r) * NQKV_ + 3072 + hkv * HD_ + d]);
        }
        float tm = -3e38f;
#pragma unroll
        for (int ii = 0; ii < 16; ii++) tm = fmaxf(tm, Sc[rg * 68 + cg + 4 * ii]);
        tm = fmaxf(tm, __shfl_xor_sync(0xffffffffu, tm, 1));
        tm = fmaxf(tm, __shfl_xor_sync(0xffffffffu, tm, 2));
        float mprev = mrow[rg];
        float mnew = fmaxf(mprev, tm);
        float fac = expf(mprev - mnew);
        float ls = 0.f;
#pragma unroll
        for (int ii = 0; ii < 16; ii++) {
            float p = expf(Sc[rg * 68 + cg + 4 * ii] - mnew);
            Sc[rg * 68 + cg + 4 * ii] = tf32r(p);
            ls += p;
        }
        ls += __shfl_xor_sync(0xffffffffu, ls, 1);
        ls += __shfl_xor_sync(0xffffffffu, ls, 2);
        if (cg == 0) { mrow[rg] = mnew; lrow[rg] = lrow[rg] * fac + ls; facrw[rg] = fac; }
        __syncthreads();
        float f0 = facrw[m0 + lr], f1 = facrw[m0 + lr + 8];
#pragma unroll
        for (int nt = 0; nt < 8; nt++) {
            oa[nt][0] *= f0; oa[nt][1] *= f0;
            oa[nt][2] *= f1; oa[nt][3] *= f1;
        }
#pragma unroll
        for (int ks = 0; ks < 8; ks++) {
            int kk = ks * 8;
            float a0 = Sc[(m0 + lr) * 68 + kk + lc];
            float a1 = Sc[(m0 + lr + 8) * 68 + kk + lc];
            float a2 = Sc[(m0 + lr) * 68 + kk + lc + 4];
            float a3 = Sc[(m0 + lr + 8) * 68 + kk + lc + 4];
#pragma unroll
            for (int nt = 0; nt < 8; nt++) {
                float b0 = KV[(n0p + nt * 8 + lr) * 68 + kk + lc];
                float b1 = KV[(n0p + nt * 8 + lr) * 68 + kk + lc + 4];
                mma_tf32(oa[nt][0], oa[nt][1], oa[nt][2], oa[nt][3],
                         a0, a1, a2, a3, b0, b1);
            }
        }
        __syncthreads();
    }
    float i0 = 1.f / lrow[m0 + lr];
    float i1 = 1.f / lrow[m0 + lr + 8];
#pragma unroll
    for (int nt = 0; nt < 8; nt++) {
        int row0 = m0 + lr, row1 = row0 + 8;
        int col = n0p + nt * 8 + lc * 2;
        float* p0 = o + ((size_t)(b * S_ + q0 + row0) * H_ + h) * HD_ + col;
        float* p1 = o + ((size_t)(b * S_ + q0 + row1) * H_ + h) * HD_ + col;
        p0[0] = tf32r(oa[nt][0] * i0); p0[1] = tf32r(oa[nt][1] * i0);
        p1[0] = tf32r(oa[nt][2] * i1); p1[1] = tf32r(oa[nt][3] * i1);
    }
}

// ---------------- router ----------------
__global__ void router_logits_kernel(const float* __restrict__ sn, const float* __restrict__ gw,
                                     float* __restrict__ logits) {
    int t = blockIdx.x;
    int wid = threadIdx.x >> 5, lid = threadIdx.x & 31;
    const float* x = sn + (size_t)t * D_;
    const float* g = gw + (size_t)wid * D_;
    float s = 0.f;
    for (int i = lid * 4; i < D_; i += 128) {
        float4 xv = *reinterpret_cast<const float4*>(x + i);
        float4 gv = *reinterpret_cast<const float4*>(g + i);
        s += xv.x * gv.x + xv.y * gv.y + xv.z * gv.z + xv.w * gv.w;
    }
#pragma unroll
    for (int o = 16; o > 0; o >>= 1) s += __shfl_xor_sync(0xffffffffu, s, o);
    if (lid == 0) logits[(size_t)t * E_ + wid] = s;
}

__global__ void col_softmax_stats(const float* __restrict__ logits, float* __restrict__ zmax,
                                  float* __restrict__ zsum) {
    int be = blockIdx.x;
    int b = be / E_, e = be % E_;
    __shared__ float red[256];
    float mx = -3e38f;
    for (int s = threadIdx.x; s < S_; s += 256)
        mx = fmaxf(mx, logits[((size_t)b * S_ + s) * E_ + e]);
    red[threadIdx.x] = mx; __syncthreads();
    for (int s = 128; s > 0; s >>= 1) {
        if (threadIdx.x < s) red[threadIdx.x] = fmaxf(red[threadIdx.x], red[threadIdx.x + s]);
        __syncthreads();
    }
    mx = red[0]; __syncthreads();
    float sum = 0.f;
    for (int s = threadIdx.x; s < S_; s += 256)
        sum += expf(logits[((size_t)b * S_ + s) * E_ + e] - mx);
    red[threadIdx.x] = sum; __syncthreads();
    for (int s = 128; s > 0; s >>= 1) {
        if (threadIdx.x < s) red[threadIdx.x] += red[threadIdx.x + s];
        __syncthreads();
    }
    if (threadIdx.x == 0) { zmax[be] = mx; zsum[be] = red[0]; }
}

__global__ void top2_kernel(const float* __restrict__ logits, const float* __restrict__ zmax,
                            const float* __restrict__ zsum, int* __restrict__ cnt,
                            int* __restrict__ tok, int* __restrict__ sel,
                            int* __restrict__ pos, float* __restrict__ wgt) {
    int t = blockIdx.x * blockDim.x + threadIdx.x;
    if (t >= T_) return;
    int b = t / S_;
    float rw[E_];
#pragma unroll
    for (int e = 0; e < E_; e++)
        rw[e] = expf(logits[(size_t)t * E_ + e] - zmax[b * E_ + e]) / zsum[b * E_ + e];
    int e0 = 0; float v0 = rw[0];
#pragma unroll
    for (int e = 1; e < E_; e++) if (rw[e] > v0) { v0 = rw[e]; e0 = e; }
    int e1 = -1; float v1 = -3e38f;
#pragma unroll
    for (int e = 0; e < E_; e++) if (e != e0 && rw[e] > v1) { v1 = rw[e]; e1 = e; }
    float inv = 1.f / (v0 + v1);
    int p0 = atomicAdd(&cnt[e0], 1);
    tok[e0 * T_ + p0] = t;
    int p1 = atomicAdd(&cnt[e1], 1);
    tok[e1 * T_ + p1] = t;
    sel[2*t] = e0; pos[2*t] = p0; wgt[2*t] = v0 * inv;
    sel[2*t+1] = e1; pos[2*t+1] = p1; wgt[2*t+1] = v1 * inv;
}

__global__ void offsets_kernel(const int* __restrict__ cnt, int* __restrict__ off) {
    if (threadIdx.x == 0) {
        int s = 0;
        for (int e = 0; e < E_; e++) { off[e] = s; s += cnt[e]; }
    }
}

__global__ void gather_kernel(const float* __restrict__ expout, const int* __restrict__ off,
                              const int* __restrict__ sel, const int* __restrict__ pos,
                              const float* __restrict__ wgt, float* __restrict__ out) {
    int t = blockIdx.x;
    int e0 = sel[2*t], e1 = sel[2*t+1];
    size_t r0 = (size_t)(off[e0] + pos[2*t]) * D_;
    size_t r1 = (size_t)(off[e1] + pos[2*t+1]) * D_;
    float w0 = wgt[2*t], w1 = wgt[2*t+1];
    for (int i = threadIdx.x; i < D_; i += 256)
        out[(size_t)t * D_ + i] += w0 * expout[r0 + i] + w1 * expout[r1 + i];
}

// ---------------- host launch ----------------
extern "C" void kernel_launch(void* const* d_in, const int* in_sizes, int n_in,
                              void* d_out, int out_size) {
    const float* data   = (const float*)d_in[0];
    const float* mask   = (const float*)d_in[1];
    const float* ropec  = (const float*)d_in[2];
    const float* ropes  = (const float*)d_in[3];
    const float* anw    = (const float*)d_in[4];
    const float* fnw    = (const float*)d_in[5];
    const float* wq     = (const float*)d_in[6];
    const float* wk     = (const float*)d_in[7];
    const float* wv     = (const float*)d_in[8];
    const float* wo     = (const float*)d_in[9];
    const float* gate_w = (const float*)d_in[10];
    const float* w1     = (const float*)d_in[11];
    const float* w2     = (const float*)d_in[12];
    const float* w3     = (const float*)d_in[13];
    const float* w1_a   = (const float*)d_in[14];
    const float* w1_b   = (const float*)d_in[15];
    const float* w3_a   = (const float*)d_in[16];
    const float* w3_b   = (const float*)d_in[17];
    const float* w2_a   = (const float*)d_in[18];
    const float* w2_b   = (const float*)d_in[19];
    float* out = (float*)d_out;

    float *xnr, *sn, *snr, *wqkv, *qkv, *attn, *woc, *w13c, *w2c, *w13a, *c13;
    float *h1, *u13, *u2;
    float *logits, *zmax, *zsum, *wgt, *expout;
    int *cnt, *off, *tok, *sel, *pos;
    cudaGetSymbolAddress((void**)&xnr, g_xnr);
    cudaGetSymbolAddress((void**)&sn, g_sn);
    cudaGetSymbolAddress((void**)&snr, g_snr);
    cudaGetSymbolAddress((void**)&wqkv, g_wqkv);
    cudaGetSymbolAddress((void**)&qkv, g_qkv);
    cudaGetSymbolAddress((void**)&attn, g_attn);
    cudaGetSymbolAddress((void**)&woc, g_woc);
    cudaGetSymbolAddress((void**)&w13c, g_w13c);
    cudaGetSymbolAddress((void**)&w2c, g_w2c);
    cudaGetSymbolAddress((void**)&w13a, g_w13a);
    cudaGetSymbolAddress((void**)&c13, g_c13);
    cudaGetSymbolAddress((void**)&h1, g_h1);
    cudaGetSymbolAddress((void**)&u13, g_u13);
    cudaGetSymbolAddress((void**)&u2, g_u2);
    cudaGetSymbolAddress((void**)&expout, g_expout);
    cudaGetSymbolAddress((void**)&logits, g_logits);
    cudaGetSymbolAddress((void**)&zmax, g_zmax);
    cudaGetSymbolAddress((void**)&zsum, g_zsum);
    cudaGetSymbolAddress((void**)&cnt, g_cnt);
    cudaGetSymbolAddress((void**)&off, g_off);
    cudaGetSymbolAddress((void**)&tok, g_tok);
    cudaGetSymbolAddress((void**)&sel, g_sel);
    cudaGetSymbolAddress((void**)&pos, g_pos);
    cudaGetSymbolAddress((void**)&wgt, g_wgt);

    cudaFuncSetAttribute(attn_mma, cudaFuncAttributeMaxDynamicSharedMemorySize, ATTN_SMEM);
    cudaFuncSetAttribute(gemm_mma, cudaFuncAttributeMaxDynamicSharedMemorySize, GMS);

    reset_kernel<<<1, 32>>>(cnt);
    concat_w_kernel<<<(NQKV_*D_/4 + 255)/256, 256>>>(wq, wk, wv, wqkv);
    concat_a_kernel<<<((E_*2*R_*D_/4) + 255)/256, 256>>>(w1_a, w3_a, w13a);
    cvt_kernel<<<((D_*D_/4) + 255)/256, 256>>>(wo, woc, (size_t)D_*D_/4);
    cvt_kernel<<<((F_*D_/4) + 255)/256, 256>>>(w1, w13c, (size_t)F_*D_/4);
    cvt_kernel<<<((F_*D_/4) + 255)/256, 256>>>(w3, w13c + (size_t)F_*D_, (size_t)F_*D_/4);
    cvt_kernel<<<((D_*F_/4) + 255)/256, 256>>>(w2, w2c, (size_t)D_*F_/4);

    rmsnorm_kernel<<<T_, 256>>>(data, anw, xnr, xnr);

    // Fused QKV projection; rope on cols < 3072
    gemm_mma<<<dim3(NQKV_/128, T_/128, 1), 128, GMS>>>(xnr, wqkv, qkv, T_, NQKV_, D_,
        nullptr, nullptr, nullptr, ropec, ropes, 3072);

    attn_mma<<<dim3(S_/64, H_, B_), 256, ATTN_SMEM>>>(qkv, mask, attn);

    // out = data + attn @ wo^T
    gemm_mma<<<dim3(D_/128, T_/128, 1), 128, GMS>>>(attn, woc, out, T_, D_, D_,
        data, nullptr, nullptr, nullptr, nullptr, 0);

    rmsnorm_kernel<<<T_, 256>>>(out, fnw, sn, snr);

    router_logits_kernel<<<T_, 256>>>(sn, gate_w, logits);
    col_softmax_stats<<<B_*E_, 256>>>(logits, zmax, zsum);
    top2_kernel<<<T_/256, 256>>>(logits, zmax, zsum, cnt, tok, sel, pos, wgt);
    offsets_kernel<<<1, 32>>>(cnt, off);

    // merged dense c1|c3: one GEMM, N=11264
    gemm_mma<<<dim3(2*F_/128, T_/128, 1), 128, GMS>>>(snr, w13c, c13, T_, 2*F_, D_,
        nullptr, nullptr, nullptr, nullptr, nullptr, 0);

    // ---- expert-batched LoRA path (z = expert) ----
    // u13 = sn[tok] @ (w1_a|w3_a)^T   (cols 0..15 = u1, 16..31 = u3)
    gemm_small<<<dim3(1, T_/64, E_), 256>>>(sn, w13a, u13, 2*R_, D_,
        tok, 1, 1.f, 0, cnt, off, (size_t)(2*R_)*D_);
    // sr = silu(c1 + 2*u1@w1b^T) * (c3 + 2*u3@w3b^T)   (fused, writes h1 only)
    lora_h_kernel<<<dim3(F_/64, T_/64, E_), 256>>>(u13, w1_b, w3_b, c13, h1,
        tok, cnt, off);
    // u2 = sr @ w2_a^T
    gemm_small<<<dim3(1, T_/64, E_), 256>>>(h1, w2_a, u2, R_, F_,
        tok, 0, 1.f, 0, cnt, off, (size_t)R_*F_);
    // expout = sr @ w2^T
    gemm_mma<<<dim3(D_/128, T_/128, E_), 128, GMS>>>(h1, w2c, expout, T_, D_, F_,
        nullptr, cnt, off, nullptr, nullptr, 0);
    // expout += SCALE * u2 @ w2_b^T
    lora_o_kernel<<<dim3(D_/64, T_/64, E_), 256>>>(u2, w2_b, expout, cnt, off);

    // out[t] += w0*expout[slot0] + w1*expout[slot1]
    gather_kernel<<<T_, 256>>>(expout, off, sel, pos, wgt, out);
}

// round 17
// speedup vs baseline: 1.3889x; 1.0257x over previous
#include <cuda_runtime.h>
#include <math.h>
#include <stdint.h>

#define B_ 2
#define S_ 1024
#define D_ 2048
#define H_ 16
#define HKV_ 8
#define HD_ 128
#define F_ 5632
#define E_ 8
#define R_ 16
#define T_ (B_*S_)
#define EPS_ 1e-5f
#define SCALE_ 2.0f
#define NQKV_ 4096

// ---------------- device scratch (static, allocation-free) ----------------
__device__ float g_xnr[T_*D_];
__device__ float g_sn[T_*D_];
__device__ float g_snr[T_*D_];
__device__ float g_wqkv[NQKV_*D_];
__device__ float g_qkv[(size_t)T_*NQKV_];
__device__ float g_attn[T_*D_];
__device__ float g_woc[D_*D_];
__device__ float g_w13c[2*F_*D_];
__device__ float g_w2c[(size_t)D_*F_];
__device__ float g_w13a[E_*2*R_*D_];
__device__ float g_c13[(size_t)T_*2*F_];
__device__ float g_h1[2*T_*F_];
__device__ float g_expout[2*T_*D_];
__device__ float g_u13[2*T_*2*R_];
__device__ float g_u2[2*T_*R_];
__device__ float g_logits[T_*E_];
__device__ float g_zmax[B_*E_];
__device__ float g_zsum[B_*E_];
__device__ int   g_cnt[E_];
__device__ int   g_off[E_];
__device__ int   g_tok[E_*T_];
__device__ int   g_sel[2*T_];
__device__ int   g_pos[2*T_];
__device__ float g_wgt[2*T_];

// ---------------- helpers ----------------
__device__ __forceinline__ float tf32r(float x) {
    uint32_t y;
    asm("cvt.rna.tf32.f32 %0, %1;" : "=r"(y) : "f"(x));
    return __uint_as_float(y);
}
__device__ __forceinline__ uint32_t smem_addr(const void* p) {
    uint32_t a;
    asm("{ .reg .u64 t; cvta.to.shared.u64 t, %1; cvt.u32.u64 %0, t; }" : "=r"(a) : "l"(p));
    return a;
}
__device__ __forceinline__ void mma_tf32(float& d0, float& d1, float& d2, float& d3,
                                         float a0, float a1, float a2, float a3,
                                         float b0, float b1) {
    asm volatile(
        "mma.sync.aligned.m16n8k8.row.col.f32.tf32.tf32.f32 "
        "{%0,%1,%2,%3}, {%4,%5,%6,%7}, {%8,%9}, {%0,%1,%2,%3};"
        : "+f"(d0), "+f"(d1), "+f"(d2), "+f"(d3)
        : "r"(__float_as_uint(a0)), "r"(__float_as_uint(a1)),
          "r"(__float_as_uint(a2)), "r"(__float_as_uint(a3)),
          "r"(__float_as_uint(b0)), "r"(__float_as_uint(b1)));
}

// ---------------- tf32 mma.sync GEMM: 128x128 CTA (128 thr, 2x2 warps of 64x64) ----------------
// 5-stage cp.async ring, 2 k-chunks per barrier. Inputs pre-rounded to tf32.
#define GMS (5 * 5120 * 4)
__global__ __launch_bounds__(128, 2)
void gemm_mma(const float* __restrict__ A, const float* __restrict__ Bw,
              float* __restrict__ C, int M, int N, int K,
              const float* __restrict__ Res,
              const int* __restrict__ Mcnt, const int* __restrict__ Moff,
              const float* __restrict__ ropec, const float* __restrict__ ropes,
              int ropeN) {
    extern __shared__ float smdyn[];

    int z = blockIdx.z;
    if (Mcnt) M = Mcnt[z];
    int bm = blockIdx.y * 128;
    if (bm >= M) return;
    int bn = blockIdx.x * 128;
    int base = Moff ? Moff[z] : 0;

    int tid = threadIdx.x, wid = tid >> 5, lid = tid & 31;
    int wm = wid >> 1, wn = wid & 1;
    int m0 = wm * 64, n0 = wn * 64;
    int lr = lid >> 2, lc = lid & 3;

    float acc[4][8][4];
#pragma unroll
    for (int i = 0; i < 4; i++)
#pragma unroll
        for (int j = 0; j < 8; j++)
#pragma unroll
            for (int q = 0; q < 4; q++) acc[i][j][q] = 0.f;

    int grA = tid >> 2;
    int gc  = (tid & 3) * 4;

    uint32_t sbase = smem_addr(smdyn);

#define LOADT(st, k0) do {                                                      \
        _Pragma("unroll")                                                       \
        for (int it = 0; it < 4; it++) {                                        \
            int gr = it * 32 + grA;                                             \
            int rowA = bm + gr;                                                 \
            int sz = (rowA < M) ? 16 : 0;                                       \
            int rA = (rowA < M) ? rowA : (M - 1);                               \
            const float* sa = A + (size_t)(base + rA) * K + (k0) + gc;          \
            uint32_t da = sbase + (uint32_t)(((st) * 5120 + gr * 20 + gc) * 4); \
            asm volatile("cp.async.cg.shared.global [%0], [%1], 16, %2;"        \
                         :: "r"(da), "l"(sa), "r"(sz));                         \
            const float* sb = Bw + (size_t)(bn + gr) * K + (k0) + gc;           \
            uint32_t db = da + 2560 * 4;                                        \
            asm volatile("cp.async.cg.shared.global [%0], [%1], 16;"            \
                         :: "r"(db), "l"(sb));                                  \
        }                                                                       \
    } while (0)

#define COMPUTE(st) do {                                                        \
        const float* Asb = smdyn + (st) * 5120;                                 \
        const float* Bsb = Asb + 2560;                                          \
        _Pragma("unroll")                                                       \
        for (int ks = 0; ks < 2; ks++) {                                        \
            int kk = ks * 8;                                                    \
            float a[4][4], b[8][2];                                             \
            _Pragma("unroll")                                                   \
            for (int mt = 0; mt < 4; mt++) {                                    \
                a[mt][0] = Asb[(m0 + mt*16 + lr) * 20 + kk + lc];               \
                a[mt][1] = Asb[(m0 + mt*16 + lr + 8) * 20 + kk + lc];           \
                a[mt][2] = Asb[(m0 + mt*16 + lr) * 20 + kk + lc + 4];           \
                a[mt][3] = Asb[(m0 + mt*16 + lr + 8) * 20 + kk + lc + 4];       \
            }                                                                   \
            _Pragma("unroll")                                                   \
            for (int nt = 0; nt < 8; nt++) {                                    \
                b[nt][0] = Bsb[(n0 + nt*8 + lr) * 20 + kk + lc];                \
                b[nt][1] = Bsb[(n0 + nt*8 + lr) * 20 + kk + lc + 4];            \
            }                                                                   \
            _Pragma("unroll")                                                   \
            for (int mt = 0; mt < 4; mt++)                                      \
                _Pragma("unroll")                                               \
                for (int nt = 0; nt < 8; nt++)                                  \
                    mma_tf32(acc[mt][nt][0], acc[mt][nt][1],                    \
                             acc[mt][nt][2], acc[mt][nt][3],                    \
                             a[mt][0], a[mt][1], a[mt][2], a[mt][3],            \
                             b[nt][0], b[nt][1]);                               \
        }                                                                       \
    } while (0)

    int nk = K / 16;            // even for all call sites (K % 32 == 0)
#pragma unroll
    for (int s = 0; s < 3; s++) {
        if (s < nk) LOADT(s, s * 16);
        asm volatile("cp.async.commit_group;");
    }
    int np = nk >> 1;
    for (int tp = 0; tp < np; tp++) {
        int t = tp * 2;
        asm volatile("cp.async.wait_group 1;");
        __syncthreads();
        if (t + 3 < nk) LOADT((t + 3) % 5, (t + 3) * 16);
        asm volatile("cp.async.commit_group;");
        if (t + 4 < nk) LOADT((t + 4) % 5, (t + 4) * 16);
        asm volatile("cp.async.commit_group;");
        COMPUTE(t % 5);
        COMPUTE((t + 1) % 5);
    }
#undef LOADT
#undef COMPUTE

#pragma unroll
    for (int mt = 0; mt < 4; mt++) {
#pragma unroll
        for (int nt = 0; nt < 8; nt++) {
            int row = bm + m0 + mt * 16 + lr;
            int col = bn + n0 + nt * 8 + lc * 2;
#pragma unroll
            for (int hh = 0; hh < 2; hh++) {
                int r = row + hh * 8;
                if (r >= M) continue;
                float2 v = make_float2(acc[mt][nt][hh * 2], acc[mt][nt][hh * 2 + 1]);
                if (Res) {
                    const float2 rv = *reinterpret_cast<const float2*>(
                        Res + (size_t)(base + r) * N + col);
                    v.x += rv.x; v.y += rv.y;
                }
                if (ropec && col < ropeN) {
                    int p = (col & 127) >> 1;
                    int sp = (base + r) & (S_ - 1);
                    float cc = ropec[sp * 64 + p];
                    float ss = ropes[sp * 64 + p];
                    float o1 = v.x * cc - v.y * ss;
                    float o2 = v.x * ss + v.y * cc;
                    v.x = o1; v.y = o2;
                }
                *reinterpret_cast<float2*>(C + (size_t)(base + r) * N + col) = v;
            }
        }
    }
}

// ---------------- small kernels ----------------
__global__ void reset_kernel(int* cnt) {
    if (threadIdx.x < E_) cnt[threadIdx.x] = 0;
}

__global__ void concat_w_kernel(const float* __restrict__ wq, const float* __restrict__ wk,
                                const float* __restrict__ wv, float* __restrict__ wqkv) {
    size_t i = ((size_t)blockIdx.x * blockDim.x + threadIdx.x) * 4;
    size_t tot = (size_t)NQKV_ * D_;
    if (i >= tot) return;
    size_t row = i / D_;
    const float* src;
    size_t srow;
    if (row < 2048)      { src = wq; srow = row; }
    else if (row < 3072) { src = wk; srow = row - 2048; }
    else                 { src = wv; srow = row - 3072; }
    float4 v = *reinterpret_cast<const float4*>(src + srow * D_ + (i % D_));
    v.x = tf32r(v.x); v.y = tf32r(v.y); v.z = tf32r(v.z); v.w = tf32r(v.w);
    *reinterpret_cast<float4*>(wqkv + i) = v;
}

__global__ void concat_a_kernel(const float* __restrict__ w1a, const float* __restrict__ w3a,
                                float* __restrict__ w13a) {
    size_t idx = ((size_t)blockIdx.x * blockDim.x + threadIdx.x) * 4;
    size_t tot = (size_t)E_ * 2 * R_ * D_;
    if (idx >= tot) return;
    size_t e = idx / (2 * R_ * D_);
    size_t rem = idx % (2 * R_ * D_);
    size_t row = rem / D_;
    size_t cc = rem % D_;
    const float* src = (row < R_) ? (w1a + ((size_t)e * R_ + row) * D_ + cc)
                                  : (w3a + ((size_t)e * R_ + row - R_) * D_ + cc);
    *reinterpret_cast<float4*>(w13a + idx) = *reinterpret_cast<const float4*>(src);
}

__global__ void cvt_kernel(const float* __restrict__ src, float* __restrict__ dst, size_t n4) {
    size_t i = (size_t)blockIdx.x * blockDim.x + threadIdx.x;
    if (i >= n4) return;
    float4 v = reinterpret_cast<const float4*>(src)[i];
    v.x = tf32r(v.x); v.y = tf32r(v.y); v.z = tf32r(v.z); v.w = tf32r(v.w);
    reinterpret_cast<float4*>(dst)[i] = v;
}

__global__ void rmsnorm_kernel(const float* __restrict__ x, const float* __restrict__ w,
                               float* __restrict__ out, float* __restrict__ outR) {
    int row = blockIdx.x;
    const float* xr = x + (size_t)row * D_;
    float ss = 0.f;
    for (int i = threadIdx.x; i < D_; i += 256) { float v = xr[i]; ss += v * v; }
    __shared__ float red[256];
    red[threadIdx.x] = ss; __syncthreads();
    for (int s = 128; s > 0; s >>= 1) {
        if (threadIdx.x < s) red[threadIdx.x] += red[threadIdx.x + s];
        __syncthreads();
    }
    float inv = rsqrtf(red[0] / (float)D_ + EPS_);
    float* orow = out + (size_t)row * D_;
    float* rrow = outR ? outR + (size_t)row * D_ : nullptr;
    for (int i = threadIdx.x; i < D_; i += 256) {
        float v = xr[i] * inv * w[i];
        orow[i] = v;
        if (rrow) rrow[i] = tf32r(v);
    }
}

// ---------------- small SGEMM: 64x64 tile, expert-batched (LoRA u-path) ----------------
__global__ void gemm_small(const float* __restrict__ A, const float* __restrict__ Bw,
                           float* __restrict__ C, int N, int K,
                           const int* __restrict__ tokIdx, int gatherA,
                           float alpha, int accumulate,
                           const int* __restrict__ Mcnt, const int* __restrict__ Moff,
                           size_t strideB) {
    int z = blockIdx.z;
    int M = Mcnt[z];
    int bm = blockIdx.y * 64;
    if (bm >= M) return;
    int bn = blockIdx.x * 64;
    int base = Moff[z];
    const int* tok = tokIdx + z * T_;
    const float* Bz = Bw + (size_t)z * strideB;

    __shared__ float As[16][64];
    __shared__ float Bs[16][64];
    int tid = threadIdx.x;
    int tx = tid & 15, ty = tid >> 4;
    float acc[4][4];
#pragma unroll
    for (int i = 0; i < 4; i++)
#pragma unroll
        for (int j = 0; j < 4; j++) acc[i][j] = 0.f;

    for (int k0 = 0; k0 < K; k0 += 16) {
#pragma unroll
        for (int l = 0; l < 4; l++) {
            int ii = l * 256 + tid;
            int m = ii >> 4, kk = ii & 15;
            int row = bm + m;
            float a = 0.f;
            if (row < M) {
                int ar = gatherA ? tok[row] : base + row;
                a = A[(size_t)ar * K + k0 + kk];
            }
            As[kk][m] = a;
            float bv = 0.f;
            if (bn + m < N) bv = Bz[(size_t)(bn + m) * K + k0 + kk];
            Bs[kk][m] = bv;
        }
        __syncthreads();
#pragma unroll
        for (int kk = 0; kk < 16; kk++) {
            float4 av = *reinterpret_cast<const float4*>(&As[kk][ty * 4]);
            float4 bv = *reinterpret_cast<const float4*>(&Bs[kk][tx * 4]);
            float a0 = av.x, a1 = av.y, a2 = av.z, a3 = av.w;
            float b0 = bv.x, b1 = bv.y, b2 = bv.z, b3 = bv.w;
            acc[0][0] += a0*b0; acc[0][1] += a0*b1; acc[0][2] += a0*b2; acc[0][3] += a0*b3;
            acc[1][0] += a1*b0; acc[1][1] += a1*b1; acc[1][2] += a1*b2; acc[1][3] += a1*b3;
            acc[2][0] += a2*b0; acc[2][1] += a2*b1; acc[2][2] += a2*b2; acc[2][3] += a2*b3;
            acc[3][0] += a3*b0; acc[3][1] += a3*b1; acc[3][2] += a3*b2; acc[3][3] += a3*b3;
        }
        __syncthreads();
    }
#pragma unroll
    for (int i = 0; i < 4; i++) {
        int row = bm + ty * 4 + i;
        if (row >= M) continue;
        size_t crow = (size_t)(base + row) * N;
#pragma unroll
        for (int j = 0; j < 4; j++) {
            int col = bn + tx * 4 + j;
            if (col >= N) continue;
            float val = alpha * acc[i][j];
            if (accumulate) C[crow + col] += val;
            else            C[crow + col] = val;
        }
    }
}

// ---------------- fused LoRA h-kernel ----------------
__global__ void lora_h_kernel(const float* __restrict__ u13,
                              const float* __restrict__ w1b, const float* __restrict__ w3b,
                              const float* __restrict__ c13, float* __restrict__ sr,
                              const int* __restrict__ tokIdx,
                              const int* __restrict__ Mcnt, const int* __restrict__ Moff) {
    int z = blockIdx.z;
    int M = Mcnt[z];
    int bm = blockIdx.y * 64;
    if (bm >= M) return;
    int bn = blockIdx.x * 64;
    int base = Moff[z];
    const int* tok = tokIdx + z * T_;
    const float* B1 = w1b + (size_t)z * F_ * R_;
    const float* B3 = w3b + (size_t)z * F_ * R_;

    __shared__ float Au[64][32];
    __shared__ float Bs1[16][64];
    __shared__ float Bs3[16][64];
    int tid = threadIdx.x;
    int tx = tid & 15, ty = tid >> 4;

    for (int i = tid; i < 64 * 32; i += 256) {
        int r = i >> 5, k = i & 31;
        float v = 0.f;
        if (bm + r < M) v = u13[(size_t)(base + bm + r) * 32 + k];
        Au[r][k] = v;
    }
    for (int i = tid; i < 64 * 16; i += 256) {
        int m = i >> 4, kk = i & 15;
        Bs1[kk][m] = B1[(size_t)(bn + m) * R_ + kk];
        Bs3[kk][m] = B3[(size_t)(bn + m) * R_ + kk];
    }
    __syncthreads();

    float acc1[4][4], acc3[4][4];
#pragma unroll
    for (int i = 0; i < 4; i++)
#pragma unroll
        for (int j = 0; j < 4; j++) { acc1[i][j] = 0.f; acc3[i][j] = 0.f; }

#pragma unroll
    for (int kk = 0; kk < 16; kk++) {
        float a1[4], a3[4];
#pragma unroll
        for (int i = 0; i < 4; i++) {
            a1[i] = Au[ty * 4 + i][kk];
            a3[i] = Au[ty * 4 + i][16 + kk];
        }
        float4 b1 = *reinterpret_cast<const float4*>(&Bs1[kk][tx * 4]);
        float4 b3 = *reinterpret_cast<const float4*>(&Bs3[kk][tx * 4]);
        float bb1[4] = {b1.x, b1.y, b1.z, b1.w};
        float bb3[4] = {b3.x, b3.y, b3.z, b3.w};
#pragma unroll
        for (int i = 0; i < 4; i++)
#pragma unroll
            for (int j = 0; j < 4; j++) {
                acc1[i][j] += a1[i] * bb1[j];
                acc3[i][j] += a3[i] * bb3[j];
            }
    }

#pragma unroll
    for (int i = 0; i < 4; i++) {
        int row = bm + ty * 4 + i;
        if (row >= M) continue;
        int t = tok[row];
        size_t crow = (size_t)(base + row) * F_;
#pragma unroll
        for (int j = 0; j < 4; j++) {
            int col = bn + tx * 4 + j;
            float v1 = SCALE_ * acc1[i][j] + c13[(size_t)t * (2 * F_) + col];
            float v3 = SCALE_ * acc3[i][j] + c13[(size_t)t * (2 * F_) + F_ + col];
            float s = v1 / (1.f + expf(-v1));
            sr[crow + col] = tf32r(s * v3);
        }
    }
}

// ---------------- LoRA w2_b epilogue ----------------
__global__ void lora_o_kernel(const float* __restrict__ u2, const float* __restrict__ w2b,
                              float* __restrict__ expout,
                              const int* __restrict__ Mcnt, const int* __restrict__ Moff) {
    int z = blockIdx.z;
    int M = Mcnt[z];
    int bm = blockIdx.y * 64;
    if (bm >= M) return;
    int bn = blockIdx.x * 64;
    int base = Moff[z];
    const float* Bz = w2b + (size_t)z * D_ * R_;

    __shared__ float Au[64][16];
    __shared__ float Bs[16][64];
    int tid = threadIdx.x;
    int tx = tid & 15, ty = tid >> 4;

    for (int i = tid; i < 64 * 16; i += 256) {
        int r = i >> 4, k = i & 15;
        float v = 0.f;
        if (bm + r < M) v = u2[(size_t)(base + bm + r) * R_ + k];
        Au[r][k] = v;
        int m = i >> 4, kk = i & 15;
        Bs[kk][m] = Bz[(size_t)(bn + m) * R_ + kk];
    }
    __syncthreads();

    float acc[4][4];
#pragma unroll
    for (int i = 0; i < 4; i++)
#pragma unroll
        for (int j = 0; j < 4; j++) acc[i][j] = 0.f;
#pragma unroll
    for (int kk = 0; kk < 16; kk++) {
        float a[4];
#pragma unroll
        for (int i = 0; i < 4; i++) a[i] = Au[ty * 4 + i][kk];
        float4 bv = *reinterpret_cast<const float4*>(&Bs[kk][tx * 4]);
        float bb[4] = {bv.x, bv.y, bv.z, bv.w};
#pragma unroll
        for (int i = 0; i < 4; i++)
#pragma unroll
            for (int j = 0; j < 4; j++) acc[i][j] += a[i] * bb[j];
    }
#pragma unroll
    for (int i = 0; i < 4; i++) {
        int row = bm + ty * 4 + i;
        if (row >= M) continue;
        size_t crow = (size_t)(base + row) * D_;
#pragma unroll
        for (int j = 0; j < 4; j++) {
            int col = bn + tx * 4 + j;
            expout[crow + col] += SCALE_ * acc[i][j];
        }
    }
}

// ---------------- flash attention, tf32 mma, 64-query tiles ----------------
#define ATTN_SMEM (21696 * 4)
__global__ __launch_bounds__(256, 2)
void attn_mma(const float* __restrict__ qkv, const float* __restrict__ mask,
              float* __restrict__ o) {
    extern __shared__ float sm[];
    float* Qs    = sm;
    float* KV    = sm + 8448;
    float* Sc    = sm + 17152;
    float* mrow  = sm + 21504;
    float* lrow  = sm + 21568;
    float* facrw = sm + 21632;

    int qt = blockIdx.x, h = blockIdx.y, b = blockIdx.z;
    int hkv = h >> 1;
    int tid = threadIdx.x, wid = tid >> 5, lid = tid & 31;
    int q0 = qt * 64;
    int wm = wid >> 1, wn = wid & 1;
    int m0 = wm * 16;
    int n0s = wn * 32, n0p = wn * 64;
    int lr = lid >> 2, lc = lid & 3;
    int rg = tid >> 2, cg = tid & 3;

    for (int i = tid; i < 64 * 128; i += 256) {
        int r = i >> 7, d = i & 127;
        Qs[r * 132 + d] = tf32r(qkv[(size_t)(b * S_ + q0 + r) * NQKV_ + h * HD_ + d]);
    }
    if (tid < 64) { mrow[tid] = -3e38f; lrow[tid] = 0.f; }
    float oa[8][4];
#pragma unroll
    for (int i = 0; i < 8; i++)
#pragma unroll
        for (int q = 0; q < 4; q++) oa[i][q] = 0.f;
    __syncthreads();

    const float sca = 0.08838834764831845f;
    for (int kt = 0; kt < S_; kt += 64) {
        for (int i = tid; i < 64 * 128; i += 256) {
            int r = i >> 7, d = i & 127;
            KV[r * 132 + d] = tf32r(qkv[(size_t)(b * S_ + kt + r) * NQKV_ + 2048 + hkv * HD_ + d]);
        }
        __syncthreads();
        float sc_[4][4];
#pragma unroll
        for (int i = 0; i < 4; i++)
#pragma unroll
            for (int q = 0; q < 4; q++) sc_[i][q] = 0.f;
#pragma unroll
        for (int ks = 0; ks < 16; ks++) {
            int kk = ks * 8;
            float a0 = Qs[(m0 + lr) * 132 + kk + lc];
            float a1 = Qs[(m0 + lr + 8) * 132 + kk + lc];
            float a2 = Qs[(m0 + lr) * 132 + kk + lc + 4];
            float a3 = Qs[(m0 + lr + 8) * 132 + kk + lc + 4];
#pragma unroll
            for (int nt = 0; nt < 4; nt++) {
                float b0 = KV[(n0s + nt * 8 + lr) * 132 + kk + lc];
                float b1 = KV[(n0s + nt * 8 + lr) * 132 + kk + lc + 4];
                mma_tf32(sc_[nt][0], sc_[nt][1], sc_[nt][2], sc_[nt][3],
                         a0, a1, a2, a3, b0, b1);
            }
        }
#pragma unroll
        for (int nt = 0; nt < 4; nt++) {
#pragma unroll
            for (int hh = 0; hh < 2; hh++) {
                int row = m0 + lr + hh * 8;
                int col = n0s + nt * 8 + lc * 2;
                Sc[row * 68 + col]     = sc_[nt][hh * 2]     * sca + mask[(q0 + row) * S_ + kt + col];
                Sc[row * 68 + col + 1] = sc_[nt][hh * 2 + 1] * sca + mask[(q0 + row) * S_ + kt + col + 1];
            }
        }
        __syncthreads();
        for (int i = tid; i < 64 * 128; i += 256) {
            int r = i >> 7, d = i & 127;
            KV[d * 68 + r] = tf32r(qkv[(size_t)(b * S_ + kt + r) * NQKV_ + 3072 + hkv * HD_ + d]);
        }
        float tm = -3e38f;
#pragma unroll
        for (int ii = 0; ii < 16; ii++) tm = fmaxf(tm, Sc[rg * 68 + cg + 4 * ii]);
        tm = fmaxf(tm, __shfl_xor_sync(0xffffffffu, tm, 1));
        tm = fmaxf(tm, __shfl_xor_sync(0xffffffffu, tm, 2));
        float mprev = mrow[rg];
        float mnew = fmaxf(mprev, tm);
        float fac = expf(mprev - mnew);
        float ls = 0.f;
#pragma unroll
        for (int ii = 0; ii < 16; ii++) {
            float p = expf(Sc[rg * 68 + cg + 4 * ii] - mnew);
            Sc[rg * 68 + cg + 4 * ii] = tf32r(p);
            ls += p;
        }
        ls += __shfl_xor_sync(0xffffffffu, ls, 1);
        ls += __shfl_xor_sync(0xffffffffu, ls, 2);
        if (cg == 0) { mrow[rg] = mnew; lrow[rg] = lrow[rg] * fac + ls; facrw[rg] = fac; }
        __syncthreads();
        float f0 = facrw[m0 + lr], f1 = facrw[m0 + lr + 8];
#pragma unroll
        for (int nt = 0; nt < 8; nt++) {
            oa[nt][0] *= f0; oa[nt][1] *= f0;
            oa[nt][2] *= f1; oa[nt][3] *= f1;
        }
#pragma unroll
        for (int ks = 0; ks < 8; ks++) {
            int kk = ks * 8;
            float a0 = Sc[(m0 + lr) * 68 + kk + lc];
            float a1 = Sc[(m0 + lr + 8) * 68 + kk + lc];
            float a2 = Sc[(m0 + lr) * 68 + kk + lc + 4];
            float a3 = Sc[(m0 + lr + 8) * 68 + kk + lc + 4];
#pragma unroll
            for (int nt = 0; nt < 8; nt++) {
                float b0 = KV[(n0p + nt * 8 + lr) * 68 + kk + lc];
                float b1 = KV[(n0p + nt * 8 + lr) * 68 + kk + lc + 4];
                mma_tf32(oa[nt][0], oa[nt][1], oa[nt][2], oa[nt][3],
                         a0, a1, a2, a3, b0, b1);
            }
        }
        __syncthreads();
    }
    float i0 = 1.f / lrow[m0 + lr];
    float i1 = 1.f / lrow[m0 + lr + 8];
#pragma unroll
    for (int nt = 0; nt < 8; nt++) {
        int row0 = m0 + lr, row1 = row0 + 8;
        int col = n0p + nt * 8 + lc * 2;
        float* p0 = o + ((size_t)(b * S_ + q0 + row0) * H_ + h) * HD_ + col;
        float* p1 = o + ((size_t)(b * S_ + q0 + row1) * H_ + h) * HD_ + col;
        p0[0] = tf32r(oa[nt][0] * i0); p0[1] = tf32r(oa[nt][1] * i0);
        p1[0] = tf32r(oa[nt][2] * i1); p1[1] = tf32r(oa[nt][3] * i1);
    }
}

// ---------------- router ----------------
__global__ void router_logits_kernel(const float* __restrict__ sn, const float* __restrict__ gw,
                                     float* __restrict__ logits) {
    int t = blockIdx.x;
    int wid = threadIdx.x >> 5, lid = threadIdx.x & 31;
    const float* x = sn + (size_t)t * D_;
    const float* g = gw + (size_t)wid * D_;
    float s = 0.f;
    for (int i = lid * 4; i < D_; i += 128) {
        float4 xv = *reinterpret_cast<const float4*>(x + i);
        float4 gv = *reinterpret_cast<const float4*>(g + i);
        s += xv.x * gv.x + xv.y * gv.y + xv.z * gv.z + xv.w * gv.w;
    }
#pragma unroll
    for (int o = 16; o > 0; o >>= 1) s += __shfl_xor_sync(0xffffffffu, s, o);
    if (lid == 0) logits[(size_t)t * E_ + wid] = s;
}

__global__ void col_softmax_stats(const float* __restrict__ logits, float* __restrict__ zmax,
                                  float* __restrict__ zsum) {
    int be = blockIdx.x;
    int b = be / E_, e = be % E_;
    __shared__ float red[256];
    float mx = -3e38f;
    for (int s = threadIdx.x; s < S_; s += 256)
        mx = fmaxf(mx, logits[((size_t)b * S_ + s) * E_ + e]);
    red[threadIdx.x] = mx; __syncthreads();
    for (int s = 128; s > 0; s >>= 1) {
        if (threadIdx.x < s) red[threadIdx.x] = fmaxf(red[threadIdx.x], red[threadIdx.x + s]);
        __syncthreads();
    }
    mx = red[0]; __syncthreads();
    float sum = 0.f;
    for (int s = threadIdx.x; s < S_; s += 256)
        sum += expf(logits[((size_t)b * S_ + s) * E_ + e] - mx);
    red[threadIdx.x] = sum; __syncthreads();
    for (int s = 128; s > 0; s >>= 1) {
        if (threadIdx.x < s) red[threadIdx.x] += red[threadIdx.x + s];
        __syncthreads();
    }
    if (threadIdx.x == 0) { zmax[be] = mx; zsum[be] = red[0]; }
}

__global__ void top2_kernel(const float* __restrict__ logits, const float* __restrict__ zmax,
                            const float* __restrict__ zsum, int* __restrict__ cnt,
                            int* __restrict__ tok, int* __restrict__ sel,
                            int* __restrict__ pos, float* __restrict__ wgt) {
    int t = blockIdx.x * blockDim.x + threadIdx.x;
    if (t >= T_) return;
    int b = t / S_;
    float rw[E_];
#pragma unroll
    for (int e = 0; e < E_; e++)
        rw[e] = expf(logits[(size_t)t * E_ + e] - zmax[b * E_ + e]) / zsum[b * E_ + e];
    int e0 = 0; float v0 = rw[0];
#pragma unroll
    for (int e = 1; e < E_; e++) if (rw[e] > v0) { v0 = rw[e]; e0 = e; }
    int e1 = -1; float v1 = -3e38f;
#pragma unroll
    for (int e = 0; e < E_; e++) if (e != e0 && rw[e] > v1) { v1 = rw[e]; e1 = e; }
    float inv = 1.f / (v0 + v1);
    int p0 = atomicAdd(&cnt[e0], 1);
    tok[e0 * T_ + p0] = t;
    int p1 = atomicAdd(&cnt[e1], 1);
    tok[e1 * T_ + p1] = t;
    sel[2*t] = e0; pos[2*t] = p0; wgt[2*t] = v0 * inv;
    sel[2*t+1] = e1; pos[2*t+1] = p1; wgt[2*t+1] = v1 * inv;
}

__global__ void offsets_kernel(const int* __restrict__ cnt, int* __restrict__ off) {
    if (threadIdx.x == 0) {
        int s = 0;
        for (int e = 0; e < E_; e++) { off[e] = s; s += cnt[e]; }
    }
}

__global__ void gather_kernel(const float* __restrict__ expout, const int* __restrict__ off,
                              const int* __restrict__ sel, const int* __restrict__ pos,
                              const float* __restrict__ wgt, float* __restrict__ out) {
    int t = blockIdx.x;
    int e0 = sel[2*t], e1 = sel[2*t+1];
    size_t r0 = (size_t)(off[e0] + pos[2*t]) * D_;
    size_t r1 = (size_t)(off[e1] + pos[2*t+1]) * D_;
    float w0 = wgt[2*t], w1 = wgt[2*t+1];
    for (int i = threadIdx.x; i < D_; i += 256)
        out[(size_t)t * D_ + i] += w0 * expout[r0 + i] + w1 * expout[r1 + i];
}

// ---------------- host launch ----------------
extern "C" void kernel_launch(void* const* d_in, const int* in_sizes, int n_in,
                              void* d_out, int out_size) {
    const float* data   = (const float*)d_in[0];
    const float* mask   = (const float*)d_in[1];
    const float* ropec  = (const float*)d_in[2];
    const float* ropes  = (const float*)d_in[3];
    const float* anw    = (const float*)d_in[4];
    const float* fnw    = (const float*)d_in[5];
    const float* wq     = (const float*)d_in[6];
    const float* wk     = (const float*)d_in[7];
    const float* wv     = (const float*)d_in[8];
    const float* wo     = (const float*)d_in[9];
    const float* gate_w = (const float*)d_in[10];
    const float* w1     = (const float*)d_in[11];
    const float* w2     = (const float*)d_in[12];
    const float* w3     = (const float*)d_in[13];
    const float* w1_a   = (const float*)d_in[14];
    const float* w1_b   = (const float*)d_in[15];
    const float* w3_a   = (const float*)d_in[16];
    const float* w3_b   = (const float*)d_in[17];
    const float* w2_a   = (const float*)d_in[18];
    const float* w2_b   = (const float*)d_in[19];
    float* out = (float*)d_out;

    float *xnr, *sn, *snr, *wqkv, *qkv, *attn, *woc, *w13c, *w2c, *w13a, *c13;
    float *h1, *u13, *u2;
    float *logits, *zmax, *zsum, *wgt, *expout;
    int *cnt, *off, *tok, *sel, *pos;
    cudaGetSymbolAddress((void**)&xnr, g_xnr);
    cudaGetSymbolAddress((void**)&sn, g_sn);
    cudaGetSymbolAddress((void**)&snr, g_snr);
    cudaGetSymbolAddress((void**)&wqkv, g_wqkv);
    cudaGetSymbolAddress((void**)&qkv, g_qkv);
    cudaGetSymbolAddress((void**)&attn, g_attn);
    cudaGetSymbolAddress((void**)&woc, g_woc);
    cudaGetSymbolAddress((void**)&w13c, g_w13c);
    cudaGetSymbolAddress((void**)&w2c, g_w2c);
    cudaGetSymbolAddress((void**)&w13a, g_w13a);
    cudaGetSymbolAddress((void**)&c13, g_c13);
    cudaGetSymbolAddress((void**)&h1, g_h1);
    cudaGetSymbolAddress((void**)&u13, g_u13);
    cudaGetSymbolAddress((void**)&u2, g_u2);
    cudaGetSymbolAddress((void**)&expout, g_expout);
    cudaGetSymbolAddress((void**)&logits, g_logits);
    cudaGetSymbolAddress((void**)&zmax, g_zmax);
    cudaGetSymbolAddress((void**)&zsum, g_zsum);
    cudaGetSymbolAddress((void**)&cnt, g_cnt);
    cudaGetSymbolAddress((void**)&off, g_off);
    cudaGetSymbolAddress((void**)&tok, g_tok);
    cudaGetSymbolAddress((void**)&sel, g_sel);
    cudaGetSymbolAddress((void**)&pos, g_pos);
    cudaGetSymbolAddress((void**)&wgt, g_wgt);

    cudaFuncSetAttribute(attn_mma, cudaFuncAttributeMaxDynamicSharedMemorySize, ATTN_SMEM);
    cudaFuncSetAttribute(gemm_mma, cudaFuncAttributeMaxDynamicSharedMemorySize, GMS);

    reset_kernel<<<1, 32>>>(cnt);
    concat_w_kernel<<<(NQKV_*D_/4 + 255)/256, 256>>>(wq, wk, wv, wqkv);
    concat_a_kernel<<<((E_*2*R_*D_/4) + 255)/256, 256>>>(w1_a, w3_a, w13a);
    cvt_kernel<<<((D_*D_/4) + 255)/256, 256>>>(wo, woc, (size_t)D_*D_/4);
    cvt_kernel<<<((F_*D_/4) + 255)/256, 256>>>(w1, w13c, (size_t)F_*D_/4);
    cvt_kernel<<<((F_*D_/4) + 255)/256, 256>>>(w3, w13c + (size_t)F_*D_, (size_t)F_*D_/4);
    cvt_kernel<<<((D_*F_/4) + 255)/256, 256>>>(w2, w2c, (size_t)D_*F_/4);

    rmsnorm_kernel<<<T_, 256>>>(data, anw, xnr, xnr);

    // Fused QKV projection; rope on cols < 3072
    gemm_mma<<<dim3(NQKV_/128, T_/128, 1), 128, GMS>>>(xnr, wqkv, qkv, T_, NQKV_, D_,
        nullptr, nullptr, nullptr, ropec, ropes, 3072);

    attn_mma<<<dim3(S_/64, H_, B_), 256, ATTN_SMEM>>>(qkv, mask, attn);

    // out = data + attn @ wo^T
    gemm_mma<<<dim3(D_/128, T_/128, 1), 128, GMS>>>(attn, woc, out, T_, D_, D_,
        data, nullptr, nullptr, nullptr, nullptr, 0);

    rmsnorm_kernel<<<T_, 256>>>(out, fnw, sn, snr);

    router_logits_kernel<<<T_, 256>>>(sn, gate_w, logits);
    col_softmax_stats<<<B_*E_, 256>>>(logits, zmax, zsum);
    top2_kernel<<<T_/256, 256>>>(logits, zmax, zsum, cnt, tok, sel, pos, wgt);
    offsets_kernel<<<1, 32>>>(cnt, off);

    // merged dense c1|c3: one GEMM, N=11264
    gemm_mma<<<dim3(2*F_/128, T_/128, 1), 128, GMS>>>(snr, w13c, c13, T_, 2*F_, D_,
        nullptr, nullptr, nullptr, nullptr, nullptr, 0);

    // ---- expert-batched LoRA path (z = expert) ----
    gemm_small<<<dim3(1, T_/64, E_), 256>>>(sn, w13a, u13, 2*R_, D_,
        tok, 1, 1.f, 0, cnt, off, (size_t)(2*R_)*D_);
    lora_h_kernel<<<dim3(F_/64, T_/64, E_), 256>>>(u13, w1_b, w3_b, c13, h1,
        tok, cnt, off);
    gemm_small<<<dim3(1, T_/64, E_), 256>>>(h1, w2_a, u2, R_, F_,
        tok, 0, 1.f, 0, cnt, off, (size_t)R_*F_);
    gemm_mma<<<dim3(D_/128, T_/128, E_), 128, GMS>>>(h1, w2c, expout, T_, D_, F_,
        nullptr, cnt, off, nullptr, nullptr, 0);
    lora_o_kernel<<<dim3(D_/64, T_/64, E_), 256>>>(u2, w2_b, expout, cnt, off);

    // out[t] += w0*expout[slot0] + w1*expout[slot1]
    gather_kernel<<<T_, 256>>>(expout, off, sel, pos, wgt, out);
}